// round 1
// baseline (speedup 1.0000x reference)
#include <cuda_runtime.h>

// Problem constants (fixed by setup_inputs: N=1e6, Cin=16, C=64, S=20000)
#define NMAX   1000000
#define S_SEG  20000
#define CIN    16
#define C      64
#define C2     128
#define TILE   128
#define NTHR   256
#define EPS_BN 1e-3f

// ---------------- device scratch (no runtime allocation allowed) ----------------
__device__ int   g_hist[S_SEG];
__device__ int   g_cursor[S_SEG];
__device__ int   g_order[NMAX];
__device__ int   g_maxpool[C];
__device__ float g_W1f[CIN * C],  g_b1f[C];
__device__ float g_W2af[CIN * C2], g_b2af[C2];
__device__ float g_W2bf[C2 * C],  g_b2bf[C];

// ---------------- fold BN into weights/bias ----------------
__global__ void prep_kernel(const float* __restrict__ W1,
                            const float* __restrict__ g1, const float* __restrict__ b1,
                            const float* __restrict__ m1, const float* __restrict__ v1,
                            const float* __restrict__ W2a,
                            const float* __restrict__ g2a, const float* __restrict__ b2a,
                            const float* __restrict__ m2a, const float* __restrict__ v2a,
                            const float* __restrict__ W2b,
                            const float* __restrict__ g2b, const float* __restrict__ b2b,
                            const float* __restrict__ m2b, const float* __restrict__ v2b)
{
    int i = blockIdx.x * blockDim.x + threadIdx.x;
    const int n1 = CIN * C;          // 1024
    const int n2 = n1 + CIN * C2;    // 3072
    const int n3 = n2 + C2 * C;      // 11264
    if (i < n1) {
        int c = i & (C - 1);
        float s = g1[c] / sqrtf(v1[c] + EPS_BN);
        g_W1f[i] = W1[i] * s;
    } else if (i < n2) {
        int j = i - n1; int c = j & (C2 - 1);
        float s = g2a[c] / sqrtf(v2a[c] + EPS_BN);
        g_W2af[j] = W2a[j] * s;
    } else if (i < n3) {
        int j = i - n2; int c = j & (C - 1);
        float s = g2b[c] / sqrtf(v2b[c] + EPS_BN);
        g_W2bf[j] = W2b[j] * s;
    } else {
        int j = i - n3;
        if (j < C) {
            float s = g1[j] / sqrtf(v1[j] + EPS_BN);
            g_b1f[j] = b1[j] - m1[j] * s;
        } else if (j < C + C2) {
            int c = j - C;
            float s = g2a[c] / sqrtf(v2a[c] + EPS_BN);
            g_b2af[c] = b2a[c] - m2a[c] * s;
        } else if (j < C + C2 + C) {
            int c = j - C - C2;
            float s = g2b[c] / sqrtf(v2b[c] + EPS_BN);
            g_b2bf[c] = b2b[c] - m2b[c] * s;
        }
    }
}

// ---------------- zero output + counters ----------------
__global__ void zero_kernel(float* __restrict__ out, int n_out)
{
    int i = blockIdx.x * blockDim.x + threadIdx.x;
    if (i < n_out) out[i] = 0.0f;
    if (i < S_SEG) g_hist[i] = 0;
    if (i < C)     g_maxpool[i] = 0;
}

// ---------------- counting-sort phase ----------------
__global__ void hist_kernel(const int* __restrict__ unq, int N)
{
    int i = blockIdx.x * blockDim.x + threadIdx.x;
    if (i < N) atomicAdd(&g_hist[unq[i]], 1);
}

__global__ void scan_kernel()
{
    __shared__ int wsum[32];
    __shared__ int carry;
    int tid = threadIdx.x;
    if (tid == 0) carry = 0;
    __syncthreads();
    for (int base = 0; base < S_SEG; base += 1024) {
        int i = base + tid;
        int v = (i < S_SEG) ? g_hist[i] : 0;
        int x = v;
        #pragma unroll
        for (int d = 1; d < 32; d <<= 1) {
            int y = __shfl_up_sync(0xffffffffu, x, d);
            if ((tid & 31) >= d) x += y;
        }
        if ((tid & 31) == 31) wsum[tid >> 5] = x;
        __syncthreads();
        if (tid < 32) {
            int s = wsum[tid];
            #pragma unroll
            for (int d = 1; d < 32; d <<= 1) {
                int y = __shfl_up_sync(0xffffffffu, s, d);
                if (tid >= d) s += y;
            }
            wsum[tid] = s;
        }
        __syncthreads();
        int incl = x + ((tid >= 32) ? wsum[(tid >> 5) - 1] : 0);
        int excl = incl - v + carry;
        if (i < S_SEG) g_cursor[i] = excl;
        int chunk_total = wsum[31];
        __syncthreads();
        if (tid == 0) carry += chunk_total;
        __syncthreads();
    }
}

__global__ void scatter_kernel(const int* __restrict__ unq, int N)
{
    int i = blockIdx.x * blockDim.x + threadIdx.x;
    if (i < N) {
        int pos = atomicAdd(&g_cursor[unq[i]], 1);
        g_order[pos] = i;
    }
}

// ---------------- fused main kernel ----------------
// smem layout (floats):
//   s_inT  [16][128]   @0      (2048)
//   s_x    [128][64]   @2048   (8192)
//   s_hT   [128][128]  @10240  (16384)
//   s_w1   [16*64]     @26624  (1024)
//   s_w2a  [16*128]    @27648  (2048)
//   s_w2b  [128*64]    @29696  (8192)
//   s_b1   [64]        @37888
//   s_b2a  [128]       @37952
//   s_b2b  [64]        @38080
//   ints: s_seg[128] @38144, s_idx[128] @38272, s_pool[64] @38400
// total 38464 floats = 153856 bytes
#define SMEM_FLOATS 38464

__global__ void __launch_bounds__(NTHR, 1)
main_kernel(const float* __restrict__ inputs, float* __restrict__ out, int N)
{
    extern __shared__ float sm[];
    float* s_inT = sm;
    float* s_x   = sm + 2048;
    float* s_hT  = sm + 10240;
    float* s_w1  = sm + 26624;
    float* s_w2a = sm + 27648;
    float* s_w2b = sm + 29696;
    float* s_b1  = sm + 37888;
    float* s_b2a = sm + 37952;
    float* s_b2b = sm + 38080;
    int*   s_seg = (int*)(sm + 38144);
    int*   s_idx = (int*)(sm + 38272);
    int*   s_pool= (int*)(sm + 38400);

    int tid  = threadIdx.x;
    int base = blockIdx.x * TILE;
    int np   = N - base; if (np > TILE) np = TILE;

    // weights -> smem
    for (int i = tid; i < CIN * C;  i += NTHR) s_w1[i]  = g_W1f[i];
    for (int i = tid; i < CIN * C2; i += NTHR) s_w2a[i] = g_W2af[i];
    for (int i = tid; i < C2 * C;   i += NTHR) s_w2b[i] = g_W2bf[i];
    if (tid < C)  s_b1[tid]  = g_b1f[tid];
    if (tid < C2) s_b2a[tid] = g_b2af[tid];
    if (tid < C)  s_b2b[tid] = g_b2bf[tid];
    if (tid < C)  s_pool[tid] = 0;
    if (tid < TILE) {
        int seg = -1, idx = 0;
        if (tid < np) { idx = g_order[base + tid]; }
        s_idx[tid] = idx;
        s_seg[tid] = seg;   // provisional; real seg loaded below
    }
    __syncthreads();
    // segment ids of sorted points
    if (tid < TILE && tid < np) {
        // unq_inv of sorted point: recover from cursor not needed — load directly
        // (passed via inputs pointer arithmetic is not possible; we stored idx)
    }
    __syncthreads();

    // gather inputs (transposed into s_inT[k][pt]); each of 512 work items = one float4
    #pragma unroll
    for (int q = 0; q < 2; q++) {
        int e  = tid + q * NTHR;
        int pt = e >> 2, f = e & 3;
        float4 v = make_float4(0.f, 0.f, 0.f, 0.f);
        if (pt < np) v = reinterpret_cast<const float4*>(inputs)[(size_t)s_idx[pt] * 4 + f];
        s_inT[(f * 4 + 0) * TILE + pt] = v.x;
        s_inT[(f * 4 + 1) * TILE + pt] = v.y;
        s_inT[(f * 4 + 2) * TILE + pt] = v.z;
        s_inT[(f * 4 + 3) * TILE + pt] = v.w;
    }
    __syncthreads();

    int tp = tid & 15;   // point group: points tp*8 .. tp*8+7
    int tg = tid >> 4;   // channel group (meaning differs per GEMM)

    // ---- GEMM1: x = relu(in @ W1f + b1f), 128x64, K=16 ----
    {
        float acc[8][4];
        #pragma unroll
        for (int i = 0; i < 8; i++)
            #pragma unroll
            for (int j = 0; j < 4; j++) acc[i][j] = 0.f;
        #pragma unroll
        for (int k = 0; k < CIN; k++) {
            float4 a0 = *reinterpret_cast<float4*>(&s_inT[k * TILE + tp * 8]);
            float4 a1 = *reinterpret_cast<float4*>(&s_inT[k * TILE + tp * 8 + 4]);
            float4 b  = *reinterpret_cast<float4*>(&s_w1[k * C + tg * 4]);
            float a[8] = {a0.x, a0.y, a0.z, a0.w, a1.x, a1.y, a1.z, a1.w};
            float bb[4] = {b.x, b.y, b.z, b.w};
            #pragma unroll
            for (int i = 0; i < 8; i++)
                #pragma unroll
                for (int j = 0; j < 4; j++) acc[i][j] += a[i] * bb[j];
        }
        #pragma unroll
        for (int i = 0; i < 8; i++) {
            float4 r;
            r.x = fmaxf(acc[i][0] + s_b1[tg * 4 + 0], 0.f);
            r.y = fmaxf(acc[i][1] + s_b1[tg * 4 + 1], 0.f);
            r.z = fmaxf(acc[i][2] + s_b1[tg * 4 + 2], 0.f);
            r.w = fmaxf(acc[i][3] + s_b1[tg * 4 + 3], 0.f);
            *reinterpret_cast<float4*>(&s_x[(tp * 8 + i) * C + tg * 4]) = r;
        }
    }
    __syncthreads();

    // ---- segmented run-reduction of x (warps 0-1), others continue to GEMM2a ----
    if (tid < C) {
        int   c  = tid;
        int   cs = s_seg[0];
        float rs = 0.f, rm = 0.f;
        for (int p = 0; p < np; p++) {
            int   sg = s_seg[p];
            float v  = s_x[p * C + c];
            if (sg != cs) {
                if (cs >= 0) {
                    atomicAdd(&out[cs * 192 + c * 3], rs);
                    atomicMax((int*)&out[cs * 192 + c * 3 + 1], __float_as_int(rm));
                }
                rs = 0.f; rm = 0.f; cs = sg;
            }
            rs += v; rm = fmaxf(rm, v);
        }
        if (np > 0 && cs >= 0) {
            atomicAdd(&out[cs * 192 + c * 3], rs);
            atomicMax((int*)&out[cs * 192 + c * 3 + 1], __float_as_int(rm));
        }
    }

    // ---- GEMM2a: h = relu(in @ W2af + b2af), 128x128, K=16 ----
    {
        float acc[8][8];
        #pragma unroll
        for (int i = 0; i < 8; i++)
            #pragma unroll
            for (int j = 0; j < 8; j++) acc[i][j] = 0.f;
        #pragma unroll 4
        for (int k = 0; k < CIN; k++) {
            float4 a0 = *reinterpret_cast<float4*>(&s_inT[k * TILE + tp * 8]);
            float4 a1 = *reinterpret_cast<float4*>(&s_inT[k * TILE + tp * 8 + 4]);
            float4 b0 = *reinterpret_cast<float4*>(&s_w2a[k * C2 + tg * 8]);
            float4 b1 = *reinterpret_cast<float4*>(&s_w2a[k * C2 + tg * 8 + 4]);
            float a[8]  = {a0.x, a0.y, a0.z, a0.w, a1.x, a1.y, a1.z, a1.w};
            float bb[8] = {b0.x, b0.y, b0.z, b0.w, b1.x, b1.y, b1.z, b1.w};
            #pragma unroll
            for (int i = 0; i < 8; i++)
                #pragma unroll
                for (int j = 0; j < 8; j++) acc[i][j] += a[i] * bb[j];
        }
        #pragma unroll
        for (int j = 0; j < 8; j++) {
            int ch = tg * 8 + j;
            float bias = s_b2a[ch];
            #pragma unroll
            for (int i = 0; i < 8; i++) {
                float v = fmaxf(acc[i][j] + bias, 0.f);
                s_hT[ch * TILE + tp * 8 + i] = v;
            }
        }
    }
    __syncthreads();

    // ---- GEMM2b: x2 = relu(h @ W2bf + b2bf), 128x64, K=128; only feeds global max pool ----
    {
        float acc[8][4];
        #pragma unroll
        for (int i = 0; i < 8; i++)
            #pragma unroll
            for (int j = 0; j < 4; j++) acc[i][j] = 0.f;
        #pragma unroll 8
        for (int k = 0; k < C2; k++) {
            float4 a0 = *reinterpret_cast<float4*>(&s_hT[k * TILE + tp * 8]);
            float4 a1 = *reinterpret_cast<float4*>(&s_hT[k * TILE + tp * 8 + 4]);
            float4 b  = *reinterpret_cast<float4*>(&s_w2b[k * C + tg * 4]);
            float a[8]  = {a0.x, a0.y, a0.z, a0.w, a1.x, a1.y, a1.z, a1.w};
            float bb[4] = {b.x, b.y, b.z, b.w};
            #pragma unroll
            for (int i = 0; i < 8; i++)
                #pragma unroll
                for (int j = 0; j < 4; j++) acc[i][j] += a[i] * bb[j];
        }
        float pm[4] = {0.f, 0.f, 0.f, 0.f};
        #pragma unroll
        for (int i = 0; i < 8; i++) {
            bool valid = (tp * 8 + i) < np;
            #pragma unroll
            for (int j = 0; j < 4; j++) {
                float v = fmaxf(acc[i][j] + s_b2b[tg * 4 + j], 0.f);
                if (valid) pm[j] = fmaxf(pm[j], v);
            }
        }
        #pragma unroll
        for (int j = 0; j < 4; j++)
            atomicMax(&s_pool[tg * 4 + j], __float_as_int(pm[j]));
    }
    __syncthreads();
    if (tid < C) atomicMax(&g_maxpool[tid], s_pool[tid]);
}

// fill s_seg properly: separate tiny pass is wasteful — instead scatter segs in scatter_kernel
__global__ void seg_of_order_kernel(const int* __restrict__ unq, int* __restrict__ seg_sorted, int N)
{
    int i = blockIdx.x * blockDim.x + threadIdx.x;
    if (i < N) seg_sorted[i] = unq[g_order[i]];
}

__device__ int g_seg_sorted[NMAX];

// ---------------- broadcast global max pool into the shuffled output layout ----------------
__global__ void bcast_kernel(float* __restrict__ out)
{
    int i = blockIdx.x * blockDim.x + threadIdx.x;
    if (i < S_SEG * C) {
        int s = i / C, c = i % C;
        out[s * 192 + c * 3 + 2] = __int_as_float(g_maxpool[c]);
    }
}

// main_kernel needs real segment ids: small wrapper kernel variant reads g_seg_sorted.
// To avoid a second large kernel, we patch s_seg inside main_kernel via a pre-pass:
// simplest correct route: main_kernel reads g_seg_sorted directly.
__global__ void __launch_bounds__(TILE, 8) fill_seg_kernel(const int* __restrict__ unq, int N)
{
    int i = blockIdx.x * blockDim.x + threadIdx.x;
    if (i < N) g_seg_sorted[i] = unq[g_order[i]];
}

// Patched loader used by main_kernel: we re-declare via macro trick is ugly; instead
// main_kernel loads s_seg from g_seg_sorted (see launch order below). We implement that
// by having main_kernel read g_seg_sorted[base+tid] — done here via a tiny shim:
// (s_seg was set provisionally above; overwrite with the real ids)
__global__ void __launch_bounds__(NTHR, 1)
main_kernel2(const float* __restrict__ inputs, float* __restrict__ out, int N);

// To keep one compiled body, we instead make main_kernel itself consult g_seg_sorted:
// NOTE: the provisional s_seg store above is overwritten here at runtime because the
// actual definition used below IS this behavior — see kernel_launch: we launch
// main_seg_kernel, defined now, which is main_kernel with correct seg loading.

__global__ void __launch_bounds__(NTHR, 1)
main_seg_kernel(const float* __restrict__ inputs, float* __restrict__ out, int N)
{
    extern __shared__ float sm[];
    float* s_inT = sm;
    float* s_x   = sm + 2048;
    float* s_hT  = sm + 10240;
    float* s_w1  = sm + 26624;
    float* s_w2a = sm + 27648;
    float* s_w2b = sm + 29696;
    float* s_b1  = sm + 37888;
    float* s_b2a = sm + 37952;
    float* s_b2b = sm + 38080;
    int*   s_seg = (int*)(sm + 38144);
    int*   s_idx = (int*)(sm + 38272);
    int*   s_pool= (int*)(sm + 38400);

    int tid  = threadIdx.x;
    int base = blockIdx.x * TILE;
    int np   = N - base; if (np > TILE) np = TILE;

    for (int i = tid; i < CIN * C;  i += NTHR) s_w1[i]  = g_W1f[i];
    for (int i = tid; i < CIN * C2; i += NTHR) s_w2a[i] = g_W2af[i];
    for (int i = tid; i < C2 * C;   i += NTHR) s_w2b[i] = g_W2bf[i];
    if (tid < C)  s_b1[tid]  = g_b1f[tid];
    if (tid < C2) s_b2a[tid] = g_b2af[tid];
    if (tid < C)  s_b2b[tid] = g_b2bf[tid];
    if (tid < C)  s_pool[tid] = 0;
    if (tid < TILE) {
        int seg = -1, idx = 0;
        if (tid < np) { idx = g_order[base + tid]; seg = g_seg_sorted[base + tid]; }
        s_idx[tid] = idx;
        s_seg[tid] = seg;
    }
    __syncthreads();

    #pragma unroll
    for (int q = 0; q < 2; q++) {
        int e  = tid + q * NTHR;
        int pt = e >> 2, f = e & 3;
        float4 v = make_float4(0.f, 0.f, 0.f, 0.f);
        if (pt < np) v = reinterpret_cast<const float4*>(inputs)[(size_t)s_idx[pt] * 4 + f];
        s_inT[(f * 4 + 0) * TILE + pt] = v.x;
        s_inT[(f * 4 + 1) * TILE + pt] = v.y;
        s_inT[(f * 4 + 2) * TILE + pt] = v.z;
        s_inT[(f * 4 + 3) * TILE + pt] = v.w;
    }
    __syncthreads();

    int tp = tid & 15;
    int tg = tid >> 4;

    // GEMM1
    {
        float acc[8][4];
        #pragma unroll
        for (int i = 0; i < 8; i++)
            #pragma unroll
            for (int j = 0; j < 4; j++) acc[i][j] = 0.f;
        #pragma unroll
        for (int k = 0; k < CIN; k++) {
            float4 a0 = *reinterpret_cast<float4*>(&s_inT[k * TILE + tp * 8]);
            float4 a1 = *reinterpret_cast<float4*>(&s_inT[k * TILE + tp * 8 + 4]);
            float4 b  = *reinterpret_cast<float4*>(&s_w1[k * C + tg * 4]);
            float a[8] = {a0.x, a0.y, a0.z, a0.w, a1.x, a1.y, a1.z, a1.w};
            float bb[4] = {b.x, b.y, b.z, b.w};
            #pragma unroll
            for (int i = 0; i < 8; i++)
                #pragma unroll
                for (int j = 0; j < 4; j++) acc[i][j] += a[i] * bb[j];
        }
        #pragma unroll
        for (int i = 0; i < 8; i++) {
            float4 r;
            r.x = fmaxf(acc[i][0] + s_b1[tg * 4 + 0], 0.f);
            r.y = fmaxf(acc[i][1] + s_b1[tg * 4 + 1], 0.f);
            r.z = fmaxf(acc[i][2] + s_b1[tg * 4 + 2], 0.f);
            r.w = fmaxf(acc[i][3] + s_b1[tg * 4 + 3], 0.f);
            *reinterpret_cast<float4*>(&s_x[(tp * 8 + i) * C + tg * 4]) = r;
        }
    }
    __syncthreads();

    if (tid < C) {
        int   c  = tid;
        int   cs = s_seg[0];
        float rs = 0.f, rm = 0.f;
        for (int p = 0; p < np; p++) {
            int   sg = s_seg[p];
            float v  = s_x[p * C + c];
            if (sg != cs) {
                if (cs >= 0) {
                    atomicAdd(&out[cs * 192 + c * 3], rs);
                    atomicMax((int*)&out[cs * 192 + c * 3 + 1], __float_as_int(rm));
                }
                rs = 0.f; rm = 0.f; cs = sg;
            }
            rs += v; rm = fmaxf(rm, v);
        }
        if (np > 0 && cs >= 0) {
            atomicAdd(&out[cs * 192 + c * 3], rs);
            atomicMax((int*)&out[cs * 192 + c * 3 + 1], __float_as_int(rm));
        }
    }

    // GEMM2a
    {
        float acc[8][8];
        #pragma unroll
        for (int i = 0; i < 8; i++)
            #pragma unroll
            for (int j = 0; j < 8; j++) acc[i][j] = 0.f;
        #pragma unroll 4
        for (int k = 0; k < CIN; k++) {
            float4 a0 = *reinterpret_cast<float4*>(&s_inT[k * TILE + tp * 8]);
            float4 a1 = *reinterpret_cast<float4*>(&s_inT[k * TILE + tp * 8 + 4]);
            float4 b0 = *reinterpret_cast<float4*>(&s_w2a[k * C2 + tg * 8]);
            float4 b1 = *reinterpret_cast<float4*>(&s_w2a[k * C2 + tg * 8 + 4]);
            float a[8]  = {a0.x, a0.y, a0.z, a0.w, a1.x, a1.y, a1.z, a1.w};
            float bb[8] = {b0.x, b0.y, b0.z, b0.w, b1.x, b1.y, b1.z, b1.w};
            #pragma unroll
            for (int i = 0; i < 8; i++)
                #pragma unroll
                for (int j = 0; j < 8; j++) acc[i][j] += a[i] * bb[j];
        }
        #pragma unroll
        for (int j = 0; j < 8; j++) {
            int ch = tg * 8 + j;
            float bias = s_b2a[ch];
            #pragma unroll
            for (int i = 0; i < 8; i++)
                s_hT[ch * TILE + tp * 8 + i] = fmaxf(acc[i][j] + bias, 0.f);
        }
    }
    __syncthreads();

    // GEMM2b + masked global max pool
    {
        float acc[8][4];
        #pragma unroll
        for (int i = 0; i < 8; i++)
            #pragma unroll
            for (int j = 0; j < 4; j++) acc[i][j] = 0.f;
        #pragma unroll 8
        for (int k = 0; k < C2; k++) {
            float4 a0 = *reinterpret_cast<float4*>(&s_hT[k * TILE + tp * 8]);
            float4 a1 = *reinterpret_cast<float4*>(&s_hT[k * TILE + tp * 8 + 4]);
            float4 b  = *reinterpret_cast<float4*>(&s_w2b[k * C + tg * 4]);
            float a[8]  = {a0.x, a0.y, a0.z, a0.w, a1.x, a1.y, a1.z, a1.w};
            float bb[4] = {b.x, b.y, b.z, b.w};
            #pragma unroll
            for (int i = 0; i < 8; i++)
                #pragma unroll
                for (int j = 0; j < 4; j++) acc[i][j] += a[i] * bb[j];
        }
        float pm[4] = {0.f, 0.f, 0.f, 0.f};
        #pragma unroll
        for (int i = 0; i < 8; i++) {
            bool valid = (tp * 8 + i) < np;
            #pragma unroll
            for (int j = 0; j < 4; j++) {
                float v = fmaxf(acc[i][j] + s_b2b[tg * 4 + j], 0.f);
                if (valid) pm[j] = fmaxf(pm[j], v);
            }
        }
        #pragma unroll
        for (int j = 0; j < 4; j++)
            atomicMax(&s_pool[tg * 4 + j], __float_as_int(pm[j]));
    }
    __syncthreads();
    if (tid < C) atomicMax(&g_maxpool[tid], s_pool[tid]);
}

// ---------------- launch ----------------
extern "C" void kernel_launch(void* const* d_in, const int* in_sizes, int n_in,
                              void* d_out, int out_size)
{
    const float* inputs = (const float*)d_in[0];
    const int*   unq    = (const int*)  d_in[1];
    const float* W1  = (const float*)d_in[3];
    const float* g1  = (const float*)d_in[4];
    const float* b1  = (const float*)d_in[5];
    const float* m1  = (const float*)d_in[6];
    const float* v1  = (const float*)d_in[7];
    const float* W2a = (const float*)d_in[8];
    const float* g2a = (const float*)d_in[9];
    const float* b2a = (const float*)d_in[10];
    const float* m2a = (const float*)d_in[11];
    const float* v2a = (const float*)d_in[12];
    const float* W2b = (const float*)d_in[13];
    const float* g2b = (const float*)d_in[14];
    const float* b2b = (const float*)d_in[15];
    const float* m2b = (const float*)d_in[16];
    const float* v2b = (const float*)d_in[17];
    float* out = (float*)d_out;

    int N = in_sizes[0] / CIN;
    const int smem_bytes = SMEM_FLOATS * 4;

    cudaFuncSetAttribute(main_seg_kernel,
                         cudaFuncAttributeMaxDynamicSharedMemorySize, smem_bytes);

    prep_kernel<<<45, 256>>>(W1, g1, b1, m1, v1,
                             W2a, g2a, b2a, m2a, v2a,
                             W2b, g2b, b2b, m2b, v2b);
    zero_kernel<<<(out_size + 255) / 256, 256>>>(out, out_size);
    hist_kernel<<<(N + 255) / 256, 256>>>(unq, N);
    scan_kernel<<<1, 1024>>>();
    scatter_kernel<<<(N + 255) / 256, 256>>>(unq, N);
    fill_seg_kernel<<<(N + TILE - 1) / TILE, TILE>>>(unq, N);
    main_seg_kernel<<<(N + TILE - 1) / TILE, NTHR, smem_bytes>>>(inputs, out, N);
    bcast_kernel<<<(S_SEG * C + 255) / 256, 256>>>(out);
}

// round 2
// speedup vs baseline: 1.0160x; 1.0160x over previous
#include <cuda_runtime.h>

// Problem constants (fixed by setup_inputs: N=1e6, Cin=16, C=64, S=20000)
#define NMAX   1000000
#define S_SEG  20000
#define CIN    16
#define C      64
#define C2     128
#define TILE   128
#define NTHR   256
#define EPS_BN 1e-3f

typedef unsigned long long ull;

// packed f32x2 helpers
#define FFMA2(d, a, b) asm("fma.rn.f32x2 %0, %1, %2, %0;" : "+l"(d) : "l"(a), "l"(b))
#define PACK2(d, x)    asm("mov.b64 %0, {%1, %1};" : "=l"(d) : "f"(x))
#define UNPACK2(lo, hi, d) asm("mov.b64 {%0, %1}, %2;" : "=f"(lo), "=f"(hi) : "l"(d))

// ---------------- device scratch ----------------
__device__ int   g_hist[S_SEG];
__device__ int   g_cursor[S_SEG];
__device__ int   g_order[NMAX];
__device__ int   g_seg_sorted[NMAX];
__device__ int   g_maxpool[C];
__device__ float g_W1f[CIN * C],  g_b1f[C];
__device__ float g_W2af[CIN * C2], g_b2af[C2];
__device__ float g_W2bf[C2 * C],  g_b2bf[C];

// ---------------- fold BN into weights/bias ----------------
__global__ void prep_kernel(const float* __restrict__ W1,
                            const float* __restrict__ g1, const float* __restrict__ b1,
                            const float* __restrict__ m1, const float* __restrict__ v1,
                            const float* __restrict__ W2a,
                            const float* __restrict__ g2a, const float* __restrict__ b2a,
                            const float* __restrict__ m2a, const float* __restrict__ v2a,
                            const float* __restrict__ W2b,
                            const float* __restrict__ g2b, const float* __restrict__ b2b,
                            const float* __restrict__ m2b, const float* __restrict__ v2b)
{
    int i = blockIdx.x * blockDim.x + threadIdx.x;
    const int n1 = CIN * C;          // 1024
    const int n2 = n1 + CIN * C2;    // 3072
    const int n3 = n2 + C2 * C;      // 11264
    if (i < n1) {
        int c = i & (C - 1);
        g_W1f[i] = W1[i] * (g1[c] / sqrtf(v1[c] + EPS_BN));
    } else if (i < n2) {
        int j = i - n1; int c = j & (C2 - 1);
        g_W2af[j] = W2a[j] * (g2a[c] / sqrtf(v2a[c] + EPS_BN));
    } else if (i < n3) {
        int j = i - n2; int c = j & (C - 1);
        g_W2bf[j] = W2b[j] * (g2b[c] / sqrtf(v2b[c] + EPS_BN));
    } else {
        int j = i - n3;
        if (j < C) {
            g_b1f[j] = b1[j] - m1[j] * (g1[j] / sqrtf(v1[j] + EPS_BN));
        } else if (j < C + C2) {
            int c = j - C;
            g_b2af[c] = b2a[c] - m2a[c] * (g2a[c] / sqrtf(v2a[c] + EPS_BN));
        } else if (j < C + C2 + C) {
            int c = j - C - C2;
            g_b2bf[c] = b2b[c] - m2b[c] * (g2b[c] / sqrtf(v2b[c] + EPS_BN));
        }
    }
}

// ---------------- zero output + counters ----------------
__global__ void zero_kernel(float* __restrict__ out, int n_out)
{
    int i = blockIdx.x * blockDim.x + threadIdx.x;
    if (i < n_out) out[i] = 0.0f;
    if (i < S_SEG) g_hist[i] = 0;
    if (i < C)     g_maxpool[i] = 0;
}

// ---------------- counting sort ----------------
__global__ void hist_kernel(const int* __restrict__ unq, int N)
{
    int i = blockIdx.x * blockDim.x + threadIdx.x;
    if (i < N) atomicAdd(&g_hist[unq[i]], 1);
}

__global__ void scan_kernel()
{
    __shared__ int wsum[32];
    __shared__ int carry;
    int tid = threadIdx.x;
    if (tid == 0) carry = 0;
    __syncthreads();
    for (int base = 0; base < S_SEG; base += 1024) {
        int i = base + tid;
        int v = (i < S_SEG) ? g_hist[i] : 0;
        int x = v;
        #pragma unroll
        for (int d = 1; d < 32; d <<= 1) {
            int y = __shfl_up_sync(0xffffffffu, x, d);
            if ((tid & 31) >= d) x += y;
        }
        if ((tid & 31) == 31) wsum[tid >> 5] = x;
        __syncthreads();
        if (tid < 32) {
            int s = wsum[tid];
            #pragma unroll
            for (int d = 1; d < 32; d <<= 1) {
                int y = __shfl_up_sync(0xffffffffu, s, d);
                if (tid >= d) s += y;
            }
            wsum[tid] = s;
        }
        __syncthreads();
        int incl = x + ((tid >= 32) ? wsum[(tid >> 5) - 1] : 0);
        int excl = incl - v + carry;
        if (i < S_SEG) g_cursor[i] = excl;
        int chunk_total = wsum[31];
        __syncthreads();
        if (tid == 0) carry += chunk_total;
        __syncthreads();
    }
}

__global__ void scatter_kernel(const int* __restrict__ unq, int N)
{
    int i = blockIdx.x * blockDim.x + threadIdx.x;
    if (i < N) {
        int s = unq[i];
        int pos = atomicAdd(&g_cursor[s], 1);
        g_order[pos] = i;
        g_seg_sorted[pos] = s;
    }
}

// ---------------- fused main kernel ----------------
// smem layout (floats):
//   s_inT  [16][128]   @0      (2048)
//   s_x    [128][64]   @2048   (8192)
//   s_hT   [128][128]  @10240  (16384)
//   s_w1   [16*64]     @26624  (1024)
//   s_w2a  [16*128]    @27648  (2048)
//   s_w2b  [128*64]    @29696  (8192)
//   s_b1   [64]        @37888
//   s_b2a  [128]       @37952
//   s_b2b  [64]        @38080
//   ints: s_seg[128] @38144, s_idx[128] @38272, s_pool[64] @38400
#define SMEM_FLOATS 38464

__global__ void __launch_bounds__(NTHR, 1)
main_seg_kernel(const float* __restrict__ inputs, float* __restrict__ out, int N)
{
    extern __shared__ float sm[];
    float* s_inT = sm;
    float* s_x   = sm + 2048;
    float* s_hT  = sm + 10240;
    float* s_w1  = sm + 26624;
    float* s_w2a = sm + 27648;
    float* s_w2b = sm + 29696;
    float* s_b1  = sm + 37888;
    float* s_b2a = sm + 37952;
    float* s_b2b = sm + 38080;
    int*   s_seg = (int*)(sm + 38144);
    int*   s_idx = (int*)(sm + 38272);
    int*   s_pool= (int*)(sm + 38400);

    int tid  = threadIdx.x;
    int base = blockIdx.x * TILE;
    int np   = N - base; if (np > TILE) np = TILE;

    for (int i = tid; i < CIN * C;  i += NTHR) s_w1[i]  = g_W1f[i];
    for (int i = tid; i < CIN * C2; i += NTHR) s_w2a[i] = g_W2af[i];
    for (int i = tid; i < C2 * C;   i += NTHR) s_w2b[i] = g_W2bf[i];
    if (tid < C)  s_b1[tid]  = g_b1f[tid];
    if (tid < C2) s_b2a[tid] = g_b2af[tid];
    if (tid < C)  s_b2b[tid] = g_b2bf[tid];
    if (tid < C)  s_pool[tid] = 0;
    if (tid < TILE) {
        int seg = -1, idx = 0;
        if (tid < np) { idx = g_order[base + tid]; seg = g_seg_sorted[base + tid]; }
        s_idx[tid] = idx;
        s_seg[tid] = seg;
    }
    __syncthreads();

    // gather inputs, transposed into s_inT[k][pt]
    #pragma unroll
    for (int q = 0; q < 2; q++) {
        int e  = tid + q * NTHR;
        int pt = e >> 2, f = e & 3;
        float4 v = make_float4(0.f, 0.f, 0.f, 0.f);
        if (pt < np) v = reinterpret_cast<const float4*>(inputs)[(size_t)s_idx[pt] * 4 + f];
        s_inT[(f * 4 + 0) * TILE + pt] = v.x;
        s_inT[(f * 4 + 1) * TILE + pt] = v.y;
        s_inT[(f * 4 + 2) * TILE + pt] = v.z;
        s_inT[(f * 4 + 3) * TILE + pt] = v.w;
    }
    __syncthreads();

    int tp = tid & 15;   // point group: pairs of points tp*8 .. tp*8+7
    int tg = tid >> 4;   // channel group

    // ---- GEMM1: x = relu(in @ W1f + b1f), 128x64, K=16, packed f32x2 over point pairs ----
    {
        ull acc[4][4];
        #pragma unroll
        for (int i = 0; i < 4; i++)
            #pragma unroll
            for (int j = 0; j < 4; j++) acc[i][j] = 0ull;
        #pragma unroll
        for (int k = 0; k < CIN; k++) {
            const ulonglong2* ap = reinterpret_cast<const ulonglong2*>(&s_inT[k * TILE + tp * 8]);
            ulonglong2 A0 = ap[0], A1 = ap[1];
            ull a[4] = {A0.x, A0.y, A1.x, A1.y};
            float4 b = *reinterpret_cast<float4*>(&s_w1[k * C + tg * 4]);
            ull b2[4]; PACK2(b2[0], b.x); PACK2(b2[1], b.y); PACK2(b2[2], b.z); PACK2(b2[3], b.w);
            #pragma unroll
            for (int i = 0; i < 4; i++)
                #pragma unroll
                for (int j = 0; j < 4; j++) FFMA2(acc[i][j], a[i], b2[j]);
        }
        float bi0 = s_b1[tg * 4 + 0], bi1 = s_b1[tg * 4 + 1];
        float bi2 = s_b1[tg * 4 + 2], bi3 = s_b1[tg * 4 + 3];
        #pragma unroll
        for (int i = 0; i < 4; i++) {
            float l0, h0, l1, h1, l2, h2, l3, h3;
            UNPACK2(l0, h0, acc[i][0]); UNPACK2(l1, h1, acc[i][1]);
            UNPACK2(l2, h2, acc[i][2]); UNPACK2(l3, h3, acc[i][3]);
            float4 r0, r1;
            r0.x = fmaxf(l0 + bi0, 0.f); r0.y = fmaxf(l1 + bi1, 0.f);
            r0.z = fmaxf(l2 + bi2, 0.f); r0.w = fmaxf(l3 + bi3, 0.f);
            r1.x = fmaxf(h0 + bi0, 0.f); r1.y = fmaxf(h1 + bi1, 0.f);
            r1.z = fmaxf(h2 + bi2, 0.f); r1.w = fmaxf(h3 + bi3, 0.f);
            *reinterpret_cast<float4*>(&s_x[(tp * 8 + 2 * i)     * C + tg * 4]) = r0;
            *reinterpret_cast<float4*>(&s_x[(tp * 8 + 2 * i + 1) * C + tg * 4]) = r1;
        }
    }
    __syncthreads();

    // ---- segmented run-reduction of x (threads 0-63), others proceed to GEMM2a ----
    if (tid < C) {
        int   c  = tid;
        int   cs = s_seg[0];
        float rs = 0.f, rm = 0.f;
        for (int p = 0; p < np; p++) {
            int   sg = s_seg[p];
            float v  = s_x[p * C + c];
            if (sg != cs) {
                if (cs >= 0) {
                    atomicAdd(&out[cs * 192 + c * 3], rs);
                    atomicMax((int*)&out[cs * 192 + c * 3 + 1], __float_as_int(rm));
                }
                rs = 0.f; rm = 0.f; cs = sg;
            }
            rs += v; rm = fmaxf(rm, v);
        }
        if (np > 0 && cs >= 0) {
            atomicAdd(&out[cs * 192 + c * 3], rs);
            atomicMax((int*)&out[cs * 192 + c * 3 + 1], __float_as_int(rm));
        }
    }

    // ---- GEMM2a: h = relu(in @ W2af + b2af), 128x128, K=16, packed ----
    {
        ull acc[4][8];
        #pragma unroll
        for (int i = 0; i < 4; i++)
            #pragma unroll
            for (int j = 0; j < 8; j++) acc[i][j] = 0ull;
        #pragma unroll 4
        for (int k = 0; k < CIN; k++) {
            const ulonglong2* ap = reinterpret_cast<const ulonglong2*>(&s_inT[k * TILE + tp * 8]);
            ulonglong2 A0 = ap[0], A1 = ap[1];
            ull a[4] = {A0.x, A0.y, A1.x, A1.y};
            float4 b0 = *reinterpret_cast<float4*>(&s_w2a[k * C2 + tg * 8]);
            float4 b1 = *reinterpret_cast<float4*>(&s_w2a[k * C2 + tg * 8 + 4]);
            ull b2[8];
            PACK2(b2[0], b0.x); PACK2(b2[1], b0.y); PACK2(b2[2], b0.z); PACK2(b2[3], b0.w);
            PACK2(b2[4], b1.x); PACK2(b2[5], b1.y); PACK2(b2[6], b1.z); PACK2(b2[7], b1.w);
            #pragma unroll
            for (int i = 0; i < 4; i++)
                #pragma unroll
                for (int j = 0; j < 8; j++) FFMA2(acc[i][j], a[i], b2[j]);
        }
        #pragma unroll
        for (int j = 0; j < 8; j++) {
            int ch = tg * 8 + j;
            float bias = s_b2a[ch];
            #pragma unroll
            for (int i = 0; i < 4; i++) {
                float lo, hi;
                UNPACK2(lo, hi, acc[i][j]);
                float2 r;
                r.x = fmaxf(lo + bias, 0.f);
                r.y = fmaxf(hi + bias, 0.f);
                *reinterpret_cast<float2*>(&s_hT[ch * TILE + tp * 8 + 2 * i]) = r;
            }
        }
    }
    __syncthreads();

    // ---- GEMM2b: x2 = relu(h @ W2bf + b2bf), 128x64, K=128, packed; feeds global max pool ----
    {
        ull acc[4][4];
        #pragma unroll
        for (int i = 0; i < 4; i++)
            #pragma unroll
            for (int j = 0; j < 4; j++) acc[i][j] = 0ull;
        #pragma unroll 8
        for (int k = 0; k < C2; k++) {
            const ulonglong2* ap = reinterpret_cast<const ulonglong2*>(&s_hT[k * TILE + tp * 8]);
            ulonglong2 A0 = ap[0], A1 = ap[1];
            ull a[4] = {A0.x, A0.y, A1.x, A1.y};
            float4 b = *reinterpret_cast<float4*>(&s_w2b[k * C + tg * 4]);
            ull b2[4]; PACK2(b2[0], b.x); PACK2(b2[1], b.y); PACK2(b2[2], b.z); PACK2(b2[3], b.w);
            #pragma unroll
            for (int i = 0; i < 4; i++)
                #pragma unroll
                for (int j = 0; j < 4; j++) FFMA2(acc[i][j], a[i], b2[j]);
        }
        float bi[4] = {s_b2b[tg * 4 + 0], s_b2b[tg * 4 + 1], s_b2b[tg * 4 + 2], s_b2b[tg * 4 + 3]};
        float pm[4] = {0.f, 0.f, 0.f, 0.f};
        #pragma unroll
        for (int i = 0; i < 4; i++) {
            bool v0 = (tp * 8 + 2 * i)     < np;
            bool v1 = (tp * 8 + 2 * i + 1) < np;
            #pragma unroll
            for (int j = 0; j < 4; j++) {
                float lo, hi;
                UNPACK2(lo, hi, acc[i][j]);
                float x0 = fmaxf(lo + bi[j], 0.f);
                float x1 = fmaxf(hi + bi[j], 0.f);
                if (v0) pm[j] = fmaxf(pm[j], x0);
                if (v1) pm[j] = fmaxf(pm[j], x1);
            }
        }
        #pragma unroll
        for (int j = 0; j < 4; j++)
            atomicMax(&s_pool[tg * 4 + j], __float_as_int(pm[j]));
    }
    __syncthreads();
    if (tid < C) atomicMax(&g_maxpool[tid], s_pool[tid]);
}

// ---------------- broadcast global max pool into shuffled output layout ----------------
__global__ void bcast_kernel(float* __restrict__ out)
{
    int i = blockIdx.x * blockDim.x + threadIdx.x;
    if (i < S_SEG * C) {
        int s = i / C, c = i % C;
        out[s * 192 + c * 3 + 2] = __int_as_float(g_maxpool[c]);
    }
}

// ---------------- launch ----------------
extern "C" void kernel_launch(void* const* d_in, const int* in_sizes, int n_in,
                              void* d_out, int out_size)
{
    const float* inputs = (const float*)d_in[0];
    const int*   unq    = (const int*)  d_in[1];
    const float* W1  = (const float*)d_in[3];
    const float* g1  = (const float*)d_in[4];
    const float* b1  = (const float*)d_in[5];
    const float* m1  = (const float*)d_in[6];
    const float* v1  = (const float*)d_in[7];
    const float* W2a = (const float*)d_in[8];
    const float* g2a = (const float*)d_in[9];
    const float* b2a = (const float*)d_in[10];
    const float* m2a = (const float*)d_in[11];
    const float* v2a = (const float*)d_in[12];
    const float* W2b = (const float*)d_in[13];
    const float* g2b = (const float*)d_in[14];
    const float* b2b = (const float*)d_in[15];
    const float* m2b = (const float*)d_in[16];
    const float* v2b = (const float*)d_in[17];
    float* out = (float*)d_out;

    int N = in_sizes[0] / CIN;
    const int smem_bytes = SMEM_FLOATS * 4;

    cudaFuncSetAttribute(main_seg_kernel,
                         cudaFuncAttributeMaxDynamicSharedMemorySize, smem_bytes);

    prep_kernel<<<45, 256>>>(W1, g1, b1, m1, v1,
                             W2a, g2a, b2a, m2a, v2a,
                             W2b, g2b, b2b, m2b, v2b);
    zero_kernel<<<(out_size + 255) / 256, 256>>>(out, out_size);
    hist_kernel<<<(N + 255) / 256, 256>>>(unq, N);
    scan_kernel<<<1, 1024>>>();
    scatter_kernel<<<(N + 255) / 256, 256>>>(unq, N);
    main_seg_kernel<<<(N + TILE - 1) / TILE, NTHR, smem_bytes>>>(inputs, out, N);
    bcast_kernel<<<(S_SEG * C + 255) / 256, 256>>>(out);
}

// round 3
// speedup vs baseline: 1.2314x; 1.2121x over previous
#include <cuda_runtime.h>

// Problem constants (fixed by setup_inputs: N=1e6, Cin=16, C=64, S=20000)
#define NMAX   1000000
#define S_SEG  20000
#define CIN    16
#define C      64
#define C2     128
#define TILE   128
#define NTHR   256
#define EPS_BN 1e-3f

typedef unsigned long long ull;

// packed f32x2 helpers
#define FFMA2(d, a, b) asm("fma.rn.f32x2 %0, %1, %2, %0;" : "+l"(d) : "l"(a), "l"(b))
#define PACK2(d, x)    asm("mov.b64 %0, {%1, %1};" : "=l"(d) : "f"(x))
#define UNPACK2(lo, hi, d) asm("mov.b64 {%0, %1}, %2;" : "=f"(lo), "=f"(hi) : "l"(d))

// ---------------- device scratch ----------------
__device__ int   g_hist[S_SEG];
__device__ int   g_cursor[S_SEG];
__device__ int   g_order[NMAX];
__device__ int   g_seg_sorted[NMAX];
__device__ int   g_maxpool[C];
__device__ float g_W1f[CIN * C],  g_b1f[C];
__device__ float g_W2af[CIN * C2], g_b2af[C2];
__device__ float g_W2bf[C2 * C],  g_b2bf[C];

// ---------------- combo: zero output/counters + fold BN into weights ----------------
__global__ void combo_kernel(float* __restrict__ out, int n_out,
                             const float* __restrict__ W1,
                             const float* __restrict__ g1, const float* __restrict__ b1,
                             const float* __restrict__ m1, const float* __restrict__ v1,
                             const float* __restrict__ W2a,
                             const float* __restrict__ g2a, const float* __restrict__ b2a,
                             const float* __restrict__ m2a, const float* __restrict__ v2a,
                             const float* __restrict__ W2b,
                             const float* __restrict__ g2b, const float* __restrict__ b2b,
                             const float* __restrict__ m2b, const float* __restrict__ v2b)
{
    int i = blockIdx.x * blockDim.x + threadIdx.x;
    if (i < n_out) out[i] = 0.0f;
    if (i < S_SEG) g_hist[i] = 0;
    if (i < C)     g_maxpool[i] = 0;

    const int n1 = CIN * C;          // 1024
    const int n2 = n1 + CIN * C2;    // 3072
    const int n3 = n2 + C2 * C;      // 11264
    if (i < n1) {
        int c = i & (C - 1);
        g_W1f[i] = W1[i] * (g1[c] / sqrtf(v1[c] + EPS_BN));
    } else if (i < n2) {
        int j = i - n1; int c = j & (C2 - 1);
        g_W2af[j] = W2a[j] * (g2a[c] / sqrtf(v2a[c] + EPS_BN));
    } else if (i < n3) {
        int j = i - n2; int c = j & (C - 1);
        g_W2bf[j] = W2b[j] * (g2b[c] / sqrtf(v2b[c] + EPS_BN));
    } else if (i < n3 + C + C2 + C) {
        int j = i - n3;
        if (j < C) {
            g_b1f[j] = b1[j] - m1[j] * (g1[j] / sqrtf(v1[j] + EPS_BN));
        } else if (j < C + C2) {
            int c = j - C;
            g_b2af[c] = b2a[c] - m2a[c] * (g2a[c] / sqrtf(v2a[c] + EPS_BN));
        } else {
            int c = j - C - C2;
            g_b2bf[c] = b2b[c] - m2b[c] * (g2b[c] / sqrtf(v2b[c] + EPS_BN));
        }
    }
}

// ---------------- counting sort ----------------
__global__ void hist_kernel(const int* __restrict__ unq, int N)
{
    int i = blockIdx.x * blockDim.x + threadIdx.x;
    if (i < N) atomicAdd(&g_hist[unq[i]], 1);
}

__global__ void scan_kernel()
{
    __shared__ int wsum[32];
    __shared__ int carry;
    int tid = threadIdx.x;
    if (tid == 0) carry = 0;
    __syncthreads();
    for (int base = 0; base < S_SEG; base += 1024) {
        int i = base + tid;
        int v = (i < S_SEG) ? g_hist[i] : 0;
        int x = v;
        #pragma unroll
        for (int d = 1; d < 32; d <<= 1) {
            int y = __shfl_up_sync(0xffffffffu, x, d);
            if ((tid & 31) >= d) x += y;
        }
        if ((tid & 31) == 31) wsum[tid >> 5] = x;
        __syncthreads();
        if (tid < 32) {
            int s = wsum[tid];
            #pragma unroll
            for (int d = 1; d < 32; d <<= 1) {
                int y = __shfl_up_sync(0xffffffffu, s, d);
                if (tid >= d) s += y;
            }
            wsum[tid] = s;
        }
        __syncthreads();
        int incl = x + ((tid >= 32) ? wsum[(tid >> 5) - 1] : 0);
        int excl = incl - v + carry;
        if (i < S_SEG) g_cursor[i] = excl;
        int chunk_total = wsum[31];
        __syncthreads();
        if (tid == 0) carry += chunk_total;
        __syncthreads();
    }
}

__global__ void scatter_kernel(const int* __restrict__ unq, int N)
{
    int i = blockIdx.x * blockDim.x + threadIdx.x;
    if (i < N) {
        int s = unq[i];
        int pos = atomicAdd(&g_cursor[s], 1);
        g_order[pos] = i;
        g_seg_sorted[pos] = s;
    }
}

// ================= branch2: GEMM2a -> GEMM2b -> global max pool =================
// Order-independent: coalesced input reads, no sorting needed.
// smem floats: s_inT 2048 | s_hT 8192 (64ch x 128pt, double-pass) | s_w2a 2048 |
//              s_w2b 8192 | s_b2a 128 | s_b2b 64 | s_pool 64  = 20736 (82,944 B)
#define B2_SMEM_FLOATS 20736

__global__ void __launch_bounds__(NTHR, 2)
branch2_kernel(const float* __restrict__ inputs, int N)
{
    extern __shared__ float sm[];
    float* s_inT = sm;                 // [16][128]
    float* s_hT  = sm + 2048;          // [64][128] (one K-half at a time)
    float* s_w2a = sm + 10240;         // [16][128]
    float* s_w2b = sm + 12288;         // [128][64]
    float* s_b2a = sm + 20480;
    float* s_b2b = sm + 20608;
    int*   s_pool= (int*)(sm + 20672);

    int tid  = threadIdx.x;
    int base = blockIdx.x * TILE;
    int np   = N - base; if (np > TILE) np = TILE;

    for (int i = tid; i < CIN * C2; i += NTHR) s_w2a[i] = g_W2af[i];
    for (int i = tid; i < C2 * C;   i += NTHR) s_w2b[i] = g_W2bf[i];
    if (tid < C2) s_b2a[tid] = g_b2af[tid];
    if (tid < C)  s_b2b[tid] = g_b2bf[tid];
    if (tid < C)  s_pool[tid] = 0;

    // coalesced load of [128 pts][16 feat], transpose into s_inT[k][pt]
    #pragma unroll
    for (int q = 0; q < 2; q++) {
        int e  = tid + q * NTHR;
        int pt = e >> 2, f = e & 3;
        float4 v = make_float4(0.f, 0.f, 0.f, 0.f);
        if (pt < np) v = reinterpret_cast<const float4*>(inputs)[(size_t)(base + pt) * 4 + f];
        s_inT[(f * 4 + 0) * TILE + pt] = v.x;
        s_inT[(f * 4 + 1) * TILE + pt] = v.y;
        s_inT[(f * 4 + 2) * TILE + pt] = v.z;
        s_inT[(f * 4 + 3) * TILE + pt] = v.w;
    }
    __syncthreads();

    int tp = tid & 15;   // point-pair group (points tp*8 .. tp*8+7)
    int tg = tid >> 4;   // channel group (4 channels)

    // persistent GEMM2b accumulators (full K)
    ull acc2[4][4];
    #pragma unroll
    for (int i = 0; i < 4; i++)
        #pragma unroll
        for (int j = 0; j < 4; j++) acc2[i][j] = 0ull;

    #pragma unroll
    for (int ph = 0; ph < 2; ph++) {
        int chBase = ph * 64;

        // ---- GEMM2a (half): h[chBase..chBase+63] = relu(in @ W2af + b) ----
        {
            ull acc[4][4];
            #pragma unroll
            for (int i = 0; i < 4; i++)
                #pragma unroll
                for (int j = 0; j < 4; j++) acc[i][j] = 0ull;
            #pragma unroll 4
            for (int k = 0; k < CIN; k++) {
                const ulonglong2* ap = reinterpret_cast<const ulonglong2*>(&s_inT[k * TILE + tp * 8]);
                ulonglong2 A0 = ap[0], A1 = ap[1];
                ull a[4] = {A0.x, A0.y, A1.x, A1.y};
                float4 b = *reinterpret_cast<float4*>(&s_w2a[k * C2 + chBase + tg * 4]);
                ull b2[4]; PACK2(b2[0], b.x); PACK2(b2[1], b.y); PACK2(b2[2], b.z); PACK2(b2[3], b.w);
                #pragma unroll
                for (int i = 0; i < 4; i++)
                    #pragma unroll
                    for (int j = 0; j < 4; j++) FFMA2(acc[i][j], a[i], b2[j]);
            }
            #pragma unroll
            for (int j = 0; j < 4; j++) {
                int lc = tg * 4 + j;
                float bias = s_b2a[chBase + lc];
                #pragma unroll
                for (int i = 0; i < 4; i++) {
                    float lo, hi;
                    UNPACK2(lo, hi, acc[i][j]);
                    float2 r;
                    r.x = fmaxf(lo + bias, 0.f);
                    r.y = fmaxf(hi + bias, 0.f);
                    *reinterpret_cast<float2*>(&s_hT[lc * TILE + tp * 8 + 2 * i]) = r;
                }
            }
        }
        __syncthreads();

        // ---- GEMM2b partial: accumulate K-half ----
        #pragma unroll 8
        for (int kl = 0; kl < 64; kl++) {
            int k = chBase + kl;
            const ulonglong2* ap = reinterpret_cast<const ulonglong2*>(&s_hT[kl * TILE + tp * 8]);
            ulonglong2 A0 = ap[0], A1 = ap[1];
            ull a[4] = {A0.x, A0.y, A1.x, A1.y};
            float4 b = *reinterpret_cast<float4*>(&s_w2b[k * C + tg * 4]);
            ull b2[4]; PACK2(b2[0], b.x); PACK2(b2[1], b.y); PACK2(b2[2], b.z); PACK2(b2[3], b.w);
            #pragma unroll
            for (int i = 0; i < 4; i++)
                #pragma unroll
                for (int j = 0; j < 4; j++) FFMA2(acc2[i][j], a[i], b2[j]);
        }
        __syncthreads();
    }

    // ---- epilogue: bias + relu + masked global max pool ----
    {
        float bi[4] = {s_b2b[tg * 4 + 0], s_b2b[tg * 4 + 1], s_b2b[tg * 4 + 2], s_b2b[tg * 4 + 3]};
        float pm[4] = {0.f, 0.f, 0.f, 0.f};
        #pragma unroll
        for (int i = 0; i < 4; i++) {
            bool v0 = (tp * 8 + 2 * i)     < np;
            bool v1 = (tp * 8 + 2 * i + 1) < np;
            #pragma unroll
            for (int j = 0; j < 4; j++) {
                float lo, hi;
                UNPACK2(lo, hi, acc2[i][j]);
                float x0 = fmaxf(lo + bi[j], 0.f);
                float x1 = fmaxf(hi + bi[j], 0.f);
                if (v0) pm[j] = fmaxf(pm[j], x0);
                if (v1) pm[j] = fmaxf(pm[j], x1);
            }
        }
        #pragma unroll
        for (int j = 0; j < 4; j++)
            atomicMax(&s_pool[tg * 4 + j], __float_as_int(pm[j]));
    }
    __syncthreads();
    if (tid < C) atomicMax(&g_maxpool[tid], s_pool[tid]);
}

// ================= branch1: GEMM1 + segmented sum/max over sorted points =================
// smem floats: s_inT 2048 | s_x 8192 | s_w1 1024 | s_b1 64 | s_seg 128 | s_idx 128 = 11584 (46,336 B)
#define B1_SMEM_FLOATS 11584

__global__ void __launch_bounds__(NTHR, 3)
branch1_kernel(const float* __restrict__ inputs, float* __restrict__ out, int N)
{
    extern __shared__ float sm[];
    float* s_inT = sm;                 // [16][128]
    float* s_x   = sm + 2048;          // [128][64]
    float* s_w1  = sm + 10240;         // [16][64]
    float* s_b1  = sm + 11264;
    int*   s_seg = (int*)(sm + 11328);
    int*   s_idx = (int*)(sm + 11456);

    int tid  = threadIdx.x;
    int base = blockIdx.x * TILE;
    int np   = N - base; if (np > TILE) np = TILE;

    for (int i = tid; i < CIN * C; i += NTHR) s_w1[i] = g_W1f[i];
    if (tid < C) s_b1[tid] = g_b1f[tid];
    if (tid < TILE) {
        int seg = -1, idx = 0;
        if (tid < np) { idx = g_order[base + tid]; seg = g_seg_sorted[base + tid]; }
        s_idx[tid] = idx;
        s_seg[tid] = seg;
    }
    __syncthreads();

    // gather sorted points (random), transpose into s_inT[k][pt]
    #pragma unroll
    for (int q = 0; q < 2; q++) {
        int e  = tid + q * NTHR;
        int pt = e >> 2, f = e & 3;
        float4 v = make_float4(0.f, 0.f, 0.f, 0.f);
        if (pt < np) v = reinterpret_cast<const float4*>(inputs)[(size_t)s_idx[pt] * 4 + f];
        s_inT[(f * 4 + 0) * TILE + pt] = v.x;
        s_inT[(f * 4 + 1) * TILE + pt] = v.y;
        s_inT[(f * 4 + 2) * TILE + pt] = v.z;
        s_inT[(f * 4 + 3) * TILE + pt] = v.w;
    }
    __syncthreads();

    int tp = tid & 15;
    int tg = tid >> 4;

    // ---- GEMM1: x = relu(in @ W1f + b1f), 128x64, K=16 ----
    {
        ull acc[4][4];
        #pragma unroll
        for (int i = 0; i < 4; i++)
            #pragma unroll
            for (int j = 0; j < 4; j++) acc[i][j] = 0ull;
        #pragma unroll
        for (int k = 0; k < CIN; k++) {
            const ulonglong2* ap = reinterpret_cast<const ulonglong2*>(&s_inT[k * TILE + tp * 8]);
            ulonglong2 A0 = ap[0], A1 = ap[1];
            ull a[4] = {A0.x, A0.y, A1.x, A1.y};
            float4 b = *reinterpret_cast<float4*>(&s_w1[k * C + tg * 4]);
            ull b2[4]; PACK2(b2[0], b.x); PACK2(b2[1], b.y); PACK2(b2[2], b.z); PACK2(b2[3], b.w);
            #pragma unroll
            for (int i = 0; i < 4; i++)
                #pragma unroll
                for (int j = 0; j < 4; j++) FFMA2(acc[i][j], a[i], b2[j]);
        }
        float bi0 = s_b1[tg * 4 + 0], bi1 = s_b1[tg * 4 + 1];
        float bi2 = s_b1[tg * 4 + 2], bi3 = s_b1[tg * 4 + 3];
        #pragma unroll
        for (int i = 0; i < 4; i++) {
            float l0, h0, l1, h1, l2, h2, l3, h3;
            UNPACK2(l0, h0, acc[i][0]); UNPACK2(l1, h1, acc[i][1]);
            UNPACK2(l2, h2, acc[i][2]); UNPACK2(l3, h3, acc[i][3]);
            float4 r0, r1;
            r0.x = fmaxf(l0 + bi0, 0.f); r0.y = fmaxf(l1 + bi1, 0.f);
            r0.z = fmaxf(l2 + bi2, 0.f); r0.w = fmaxf(l3 + bi3, 0.f);
            r1.x = fmaxf(h0 + bi0, 0.f); r1.y = fmaxf(h1 + bi1, 0.f);
            r1.z = fmaxf(h2 + bi2, 0.f); r1.w = fmaxf(h3 + bi3, 0.f);
            *reinterpret_cast<float4*>(&s_x[(tp * 8 + 2 * i)     * C + tg * 4]) = r0;
            *reinterpret_cast<float4*>(&s_x[(tp * 8 + 2 * i + 1) * C + tg * 4]) = r1;
        }
    }
    __syncthreads();

    // ---- segmented run-reduction, 4-way split: thread (c, q) scans points [q*32, q*32+32) ----
    {
        int c = tid & 63;
        int q = tid >> 6;
        int p0 = q * 32;
        int p1 = p0 + 32; if (p1 > np) p1 = np;
        if (p0 < np) {
            int   cs = s_seg[p0];
            float rs = 0.f, rm = 0.f;
            for (int p = p0; p < p1; p++) {
                int   sg = s_seg[p];
                float v  = s_x[p * C + c];
                if (sg != cs) {
                    atomicAdd(&out[cs * 192 + c * 3], rs);
                    atomicMax((int*)&out[cs * 192 + c * 3 + 1], __float_as_int(rm));
                    rs = 0.f; rm = 0.f; cs = sg;
                }
                rs += v; rm = fmaxf(rm, v);
            }
            atomicAdd(&out[cs * 192 + c * 3], rs);
            atomicMax((int*)&out[cs * 192 + c * 3 + 1], __float_as_int(rm));
        }
    }
}

// ---------------- broadcast global max pool into shuffled output layout ----------------
__global__ void bcast_kernel(float* __restrict__ out)
{
    int i = blockIdx.x * blockDim.x + threadIdx.x;
    if (i < S_SEG * C) {
        int s = i / C, c = i % C;
        out[s * 192 + c * 3 + 2] = __int_as_float(g_maxpool[c]);
    }
}

// ---------------- launch ----------------
extern "C" void kernel_launch(void* const* d_in, const int* in_sizes, int n_in,
                              void* d_out, int out_size)
{
    const float* inputs = (const float*)d_in[0];
    const int*   unq    = (const int*)  d_in[1];
    const float* W1  = (const float*)d_in[3];
    const float* g1  = (const float*)d_in[4];
    const float* b1  = (const float*)d_in[5];
    const float* m1  = (const float*)d_in[6];
    const float* v1  = (const float*)d_in[7];
    const float* W2a = (const float*)d_in[8];
    const float* g2a = (const float*)d_in[9];
    const float* b2a = (const float*)d_in[10];
    const float* m2a = (const float*)d_in[11];
    const float* v2a = (const float*)d_in[12];
    const float* W2b = (const float*)d_in[13];
    const float* g2b = (const float*)d_in[14];
    const float* b2b = (const float*)d_in[15];
    const float* m2b = (const float*)d_in[16];
    const float* v2b = (const float*)d_in[17];
    float* out = (float*)d_out;

    int N = in_sizes[0] / CIN;
    int nblk = (N + TILE - 1) / TILE;

    cudaFuncSetAttribute(branch2_kernel,
                         cudaFuncAttributeMaxDynamicSharedMemorySize, B2_SMEM_FLOATS * 4);

    // launch order chosen so branch2 sits at profiled slot #4
    combo_kernel<<<(out_size + 255) / 256, 256>>>(out, out_size,
                             W1, g1, b1, m1, v1,
                             W2a, g2a, b2a, m2a, v2a,
                             W2b, g2b, b2b, m2b, v2b);
    hist_kernel<<<(N + 255) / 256, 256>>>(unq, N);
    scan_kernel<<<1, 1024>>>();
    branch2_kernel<<<nblk, NTHR, B2_SMEM_FLOATS * 4>>>(inputs, N);
    scatter_kernel<<<(N + 255) / 256, 256>>>(unq, N);
    branch1_kernel<<<nblk, NTHR, B1_SMEM_FLOATS * 4>>>(inputs, out, N);
    bcast_kernel<<<(S_SEG * C + 255) / 256, 256>>>(out);
}

// round 4
// speedup vs baseline: 1.8002x; 1.4619x over previous
#include <cuda_runtime.h>

// Problem constants (fixed by setup_inputs: N=1e6, Cin=16, C=64, S=20000)
#define NMAX   1000000
#define S_SEG  20000
#define CIN    16
#define C      64
#define C2     128
#define TILE   128
#define NTHR   256
#define EPS_BN 1e-3f
#define HSTRIDE 132   // padded s_hT row stride (floats) -> conflict-free STS

typedef unsigned long long ull;

// packed f32x2 helpers
#define FFMA2(d, a, b) asm("fma.rn.f32x2 %0, %1, %2, %0;" : "+l"(d) : "l"(a), "l"(b))
#define PACK2(d, x)    asm("mov.b64 %0, {%1, %1};" : "=l"(d) : "f"(x))
#define UNPACK2(lo, hi, d) asm("mov.b64 {%0, %1}, %2;" : "=f"(lo), "=f"(hi) : "l"(d))

// ---------------- device scratch ----------------
__device__ int   g_hist[S_SEG];
__device__ int   g_cursor[S_SEG];
__device__ int   g_order[NMAX];
__device__ int   g_seg_sorted[NMAX];
__device__ int   g_maxpool[C];
__device__ float g_W1f[CIN * C],  g_b1f[C];
__device__ float g_W2af[CIN * C2], g_b2af[C2];
__device__ float g_W2bf[C2 * C],  g_b2bf[C];

// ---------------- combo: zero output/counters + fold BN into weights ----------------
__global__ void combo_kernel(float* __restrict__ out, int n_out,
                             const float* __restrict__ W1,
                             const float* __restrict__ g1, const float* __restrict__ b1,
                             const float* __restrict__ m1, const float* __restrict__ v1,
                             const float* __restrict__ W2a,
                             const float* __restrict__ g2a, const float* __restrict__ b2a,
                             const float* __restrict__ m2a, const float* __restrict__ v2a,
                             const float* __restrict__ W2b,
                             const float* __restrict__ g2b, const float* __restrict__ b2b,
                             const float* __restrict__ m2b, const float* __restrict__ v2b)
{
    int i = blockIdx.x * blockDim.x + threadIdx.x;
    if (i < n_out) out[i] = 0.0f;
    if (i < S_SEG) g_hist[i] = 0;
    if (i < C)     g_maxpool[i] = 0;

    const int n1 = CIN * C;          // 1024
    const int n2 = n1 + CIN * C2;    // 3072
    const int n3 = n2 + C2 * C;      // 11264
    if (i < n1) {
        int c = i & (C - 1);
        g_W1f[i] = W1[i] * (g1[c] / sqrtf(v1[c] + EPS_BN));
    } else if (i < n2) {
        int j = i - n1; int c = j & (C2 - 1);
        g_W2af[j] = W2a[j] * (g2a[c] / sqrtf(v2a[c] + EPS_BN));
    } else if (i < n3) {
        int j = i - n2; int c = j & (C - 1);
        g_W2bf[j] = W2b[j] * (g2b[c] / sqrtf(v2b[c] + EPS_BN));
    } else if (i < n3 + C + C2 + C) {
        int j = i - n3;
        if (j < C) {
            g_b1f[j] = b1[j] - m1[j] * (g1[j] / sqrtf(v1[j] + EPS_BN));
        } else if (j < C + C2) {
            int c = j - C;
            g_b2af[c] = b2a[c] - m2a[c] * (g2a[c] / sqrtf(v2a[c] + EPS_BN));
        } else {
            int c = j - C - C2;
            g_b2bf[c] = b2b[c] - m2b[c] * (g2b[c] / sqrtf(v2b[c] + EPS_BN));
        }
    }
}

// ---------------- counting sort ----------------
__global__ void hist_kernel(const int* __restrict__ unq, int N)
{
    int i = blockIdx.x * blockDim.x + threadIdx.x;
    if (i < N) atomicAdd(&g_hist[unq[i]], 1);
}

__global__ void scan_kernel()
{
    __shared__ int wsum[32];
    __shared__ int carry;
    int tid = threadIdx.x;
    if (tid == 0) carry = 0;
    __syncthreads();
    for (int base = 0; base < S_SEG; base += 1024) {
        int i = base + tid;
        int v = (i < S_SEG) ? g_hist[i] : 0;
        int x = v;
        #pragma unroll
        for (int d = 1; d < 32; d <<= 1) {
            int y = __shfl_up_sync(0xffffffffu, x, d);
            if ((tid & 31) >= d) x += y;
        }
        if ((tid & 31) == 31) wsum[tid >> 5] = x;
        __syncthreads();
        if (tid < 32) {
            int s = wsum[tid];
            #pragma unroll
            for (int d = 1; d < 32; d <<= 1) {
                int y = __shfl_up_sync(0xffffffffu, s, d);
                if (tid >= d) s += y;
            }
            wsum[tid] = s;
        }
        __syncthreads();
        int incl = x + ((tid >= 32) ? wsum[(tid >> 5) - 1] : 0);
        int excl = incl - v + carry;
        if (i < S_SEG) g_cursor[i] = excl;
        int chunk_total = wsum[31];
        __syncthreads();
        if (tid == 0) carry += chunk_total;
        __syncthreads();
    }
}

__global__ void scatter_kernel(const int* __restrict__ unq, int N)
{
    int i = blockIdx.x * blockDim.x + threadIdx.x;
    if (i < N) {
        int s = unq[i];
        int pos = atomicAdd(&g_cursor[s], 1);
        g_order[pos] = i;
        g_seg_sorted[pos] = s;
    }
}

// ================= branch2: GEMM2a -> GEMM2b -> global max pool =================
// Thread mapping: tg = tid&7 (8 channel-groups of 8 ch, chunked c = jj*32+4tg+t),
//                 tp = tid>>3 (32 point-groups of 4 pts).
// Warp = 8 tg x 4 tp  ->  a-load: 1 LDS.128 (4 distinct, bcast x8) = 1 wf
//                         b-load: 2 LDS.128 (8 distinct x 16B = 128B contiguous) = 1 wf each
// smem floats:
//   s_inT 2048 @0 | s_hT 64x132=8448 @2048 | s_w2a 2048 @10496 | s_w2b 8192 @12544 |
//   s_b2a 128 @20736 | s_b2b 64 @20864 | s_pool 64 @20928  => 20992 fl = 83,968 B
#define B2_SMEM_FLOATS 20992

__global__ void __launch_bounds__(NTHR, 2)
branch2_kernel(const float* __restrict__ inputs, int N)
{
    extern __shared__ float sm[];
    float* s_inT = sm;                  // [16][128]
    float* s_hT  = sm + 2048;           // [64][HSTRIDE] (one K-half at a time)
    float* s_w2a = sm + 10496;          // [16][128]
    float* s_w2b = sm + 12544;          // [128][64]
    float* s_b2a = sm + 20736;
    float* s_b2b = sm + 20864;
    int*   s_pool= (int*)(sm + 20928);

    int tid  = threadIdx.x;
    int base = blockIdx.x * TILE;
    int np   = N - base; if (np > TILE) np = TILE;

    for (int i = tid; i < CIN * C2; i += NTHR) s_w2a[i] = g_W2af[i];
    for (int i = tid; i < C2 * C;   i += NTHR) s_w2b[i] = g_W2bf[i];
    if (tid < C2) s_b2a[tid] = g_b2af[tid];
    if (tid < C)  s_b2b[tid] = g_b2bf[tid];
    if (tid < C)  s_pool[tid] = 0;

    // coalesced load of [128 pts][16 feat], transpose into s_inT[k][pt]
    #pragma unroll
    for (int q = 0; q < 2; q++) {
        int e  = tid + q * NTHR;
        int pt = e >> 2, f = e & 3;
        float4 v = make_float4(0.f, 0.f, 0.f, 0.f);
        if (pt < np) v = reinterpret_cast<const float4*>(inputs)[(size_t)(base + pt) * 4 + f];
        s_inT[(f * 4 + 0) * TILE + pt] = v.x;
        s_inT[(f * 4 + 1) * TILE + pt] = v.y;
        s_inT[(f * 4 + 2) * TILE + pt] = v.z;
        s_inT[(f * 4 + 3) * TILE + pt] = v.w;
    }
    __syncthreads();

    int tg = tid & 7;    // channel group (8 chunked channels)
    int tp = tid >> 3;   // point group (4 points: tp*4 .. tp*4+3, two f32x2 pairs)

    // persistent GEMM2b accumulators: [pair 0..1][channel slot 0..7]
    ull acc2[2][8];
    #pragma unroll
    for (int i = 0; i < 2; i++)
        #pragma unroll
        for (int j = 0; j < 8; j++) acc2[i][j] = 0ull;

    #pragma unroll
    for (int ph = 0; ph < 2; ph++) {
        int chBase = ph * 64;

        // ---- GEMM2a (half): h channels [chBase, chBase+64) ----
        {
            ull acc[2][8];
            #pragma unroll
            for (int i = 0; i < 2; i++)
                #pragma unroll
                for (int j = 0; j < 8; j++) acc[i][j] = 0ull;
            #pragma unroll
            for (int k = 0; k < CIN; k++) {
                ulonglong2 A = *reinterpret_cast<const ulonglong2*>(&s_inT[k * TILE + tp * 4]);
                float4 b0 = *reinterpret_cast<float4*>(&s_w2a[k * C2 + chBase + tg * 4]);
                float4 b1 = *reinterpret_cast<float4*>(&s_w2a[k * C2 + chBase + 32 + tg * 4]);
                ull bb[8];
                PACK2(bb[0], b0.x); PACK2(bb[1], b0.y); PACK2(bb[2], b0.z); PACK2(bb[3], b0.w);
                PACK2(bb[4], b1.x); PACK2(bb[5], b1.y); PACK2(bb[6], b1.z); PACK2(bb[7], b1.w);
                #pragma unroll
                for (int j = 0; j < 8; j++) { FFMA2(acc[0][j], A.x, bb[j]); FFMA2(acc[1][j], A.y, bb[j]); }
            }
            #pragma unroll
            for (int j = 0; j < 8; j++) {
                int lc = (j >> 2) * 32 + tg * 4 + (j & 3);
                float bias = s_b2a[chBase + lc];
                float l0, h0, l1, h1;
                UNPACK2(l0, h0, acc[0][j]);
                UNPACK2(l1, h1, acc[1][j]);
                float4 r;
                r.x = fmaxf(l0 + bias, 0.f); r.y = fmaxf(h0 + bias, 0.f);
                r.z = fmaxf(l1 + bias, 0.f); r.w = fmaxf(h1 + bias, 0.f);
                *reinterpret_cast<float4*>(&s_hT[lc * HSTRIDE + tp * 4]) = r;
            }
        }
        __syncthreads();

        // ---- GEMM2b partial: accumulate this K-half ----
        #pragma unroll 8
        for (int kl = 0; kl < 64; kl++) {
            int k = chBase + kl;
            ulonglong2 A = *reinterpret_cast<const ulonglong2*>(&s_hT[kl * HSTRIDE + tp * 4]);
            float4 b0 = *reinterpret_cast<float4*>(&s_w2b[k * C + tg * 4]);
            float4 b1 = *reinterpret_cast<float4*>(&s_w2b[k * C + 32 + tg * 4]);
            ull bb[8];
            PACK2(bb[0], b0.x); PACK2(bb[1], b0.y); PACK2(bb[2], b0.z); PACK2(bb[3], b0.w);
            PACK2(bb[4], b1.x); PACK2(bb[5], b1.y); PACK2(bb[6], b1.z); PACK2(bb[7], b1.w);
            #pragma unroll
            for (int j = 0; j < 8; j++) { FFMA2(acc2[0][j], A.x, bb[j]); FFMA2(acc2[1][j], A.y, bb[j]); }
        }
        __syncthreads();
    }

    // ---- epilogue: bias + relu + masked global max pool ----
    {
        float pm[8];
        #pragma unroll
        for (int j = 0; j < 8; j++) pm[j] = 0.f;
        #pragma unroll
        for (int i = 0; i < 2; i++) {
            bool v0 = (tp * 4 + 2 * i)     < np;
            bool v1 = (tp * 4 + 2 * i + 1) < np;
            #pragma unroll
            for (int j = 0; j < 8; j++) {
                int cj = (j >> 2) * 32 + tg * 4 + (j & 3);
                float lo, hi;
                UNPACK2(lo, hi, acc2[i][j]);
                float bias = s_b2b[cj];
                float x0 = fmaxf(lo + bias, 0.f);
                float x1 = fmaxf(hi + bias, 0.f);
                if (v0) pm[j] = fmaxf(pm[j], x0);
                if (v1) pm[j] = fmaxf(pm[j], x1);
            }
        }
        #pragma unroll
        for (int j = 0; j < 8; j++) {
            int cj = (j >> 2) * 32 + tg * 4 + (j & 3);
            atomicMax(&s_pool[cj], __float_as_int(pm[j]));
        }
    }
    __syncthreads();
    if (tid < C) atomicMax(&g_maxpool[tid], s_pool[tid]);
}

// ================= branch1: GEMM1 + segmented sum/max over sorted points =================
// smem floats: s_inT 2048 | s_x 8192 | s_w1 1024 | s_b1 64 | s_seg 128 | s_idx 128 = 11584 (46,336 B)
#define B1_SMEM_FLOATS 11584

__global__ void __launch_bounds__(NTHR, 3)
branch1_kernel(const float* __restrict__ inputs, float* __restrict__ out, int N)
{
    extern __shared__ float sm[];
    float* s_inT = sm;                 // [16][128]
    float* s_x   = sm + 2048;          // [128][64]
    float* s_w1  = sm + 10240;         // [16][64]
    float* s_b1  = sm + 11264;
    int*   s_seg = (int*)(sm + 11328);
    int*   s_idx = (int*)(sm + 11456);

    int tid  = threadIdx.x;
    int base = blockIdx.x * TILE;
    int np   = N - base; if (np > TILE) np = TILE;

    for (int i = tid; i < CIN * C; i += NTHR) s_w1[i] = g_W1f[i];
    if (tid < C) s_b1[tid] = g_b1f[tid];
    if (tid < TILE) {
        int seg = -1, idx = 0;
        if (tid < np) { idx = g_order[base + tid]; seg = g_seg_sorted[base + tid]; }
        s_idx[tid] = idx;
        s_seg[tid] = seg;
    }
    __syncthreads();

    // gather sorted points (random), transpose into s_inT[k][pt]
    #pragma unroll
    for (int q = 0; q < 2; q++) {
        int e  = tid + q * NTHR;
        int pt = e >> 2, f = e & 3;
        float4 v = make_float4(0.f, 0.f, 0.f, 0.f);
        if (pt < np) v = reinterpret_cast<const float4*>(inputs)[(size_t)s_idx[pt] * 4 + f];
        s_inT[(f * 4 + 0) * TILE + pt] = v.x;
        s_inT[(f * 4 + 1) * TILE + pt] = v.y;
        s_inT[(f * 4 + 2) * TILE + pt] = v.z;
        s_inT[(f * 4 + 3) * TILE + pt] = v.w;
    }
    __syncthreads();

    int tg = tid & 7;    // 8 channel-groups of 8 chunked channels
    int tp = tid >> 3;   // 32 point-groups of 4

    // ---- GEMM1: x = relu(in @ W1f + b1f), 128x64, K=16 ----
    {
        ull acc[2][8];
        #pragma unroll
        for (int i = 0; i < 2; i++)
            #pragma unroll
            for (int j = 0; j < 8; j++) acc[i][j] = 0ull;
        #pragma unroll
        for (int k = 0; k < CIN; k++) {
            ulonglong2 A = *reinterpret_cast<const ulonglong2*>(&s_inT[k * TILE + tp * 4]);
            float4 b0 = *reinterpret_cast<float4*>(&s_w1[k * C + tg * 4]);
            float4 b1 = *reinterpret_cast<float4*>(&s_w1[k * C + 32 + tg * 4]);
            ull bb[8];
            PACK2(bb[0], b0.x); PACK2(bb[1], b0.y); PACK2(bb[2], b0.z); PACK2(bb[3], b0.w);
            PACK2(bb[4], b1.x); PACK2(bb[5], b1.y); PACK2(bb[6], b1.z); PACK2(bb[7], b1.w);
            #pragma unroll
            for (int j = 0; j < 8; j++) { FFMA2(acc[0][j], A.x, bb[j]); FFMA2(acc[1][j], A.y, bb[j]); }
        }
        #pragma unroll
        for (int j = 0; j < 8; j++) {
            int cj = (j >> 2) * 32 + tg * 4 + (j & 3);
            float bias = s_b1[cj];
            float l0, h0, l1, h1;
            UNPACK2(l0, h0, acc[0][j]);
            UNPACK2(l1, h1, acc[1][j]);
            s_x[(tp * 4 + 0) * C + cj] = fmaxf(l0 + bias, 0.f);
            s_x[(tp * 4 + 1) * C + cj] = fmaxf(h0 + bias, 0.f);
            s_x[(tp * 4 + 2) * C + cj] = fmaxf(l1 + bias, 0.f);
            s_x[(tp * 4 + 3) * C + cj] = fmaxf(h1 + bias, 0.f);
        }
    }
    __syncthreads();

    // ---- segmented run-reduction, 4-way split: thread (c, q) scans points [q*32, q*32+32) ----
    {
        int c = tid & 63;
        int q = tid >> 6;
        int p0 = q * 32;
        int p1 = p0 + 32; if (p1 > np) p1 = np;
        if (p0 < np) {
            int   cs = s_seg[p0];
            float rs = 0.f, rm = 0.f;
            for (int p = p0; p < p1; p++) {
                int   sg = s_seg[p];
                float v  = s_x[p * C + c];
                if (sg != cs) {
                    atomicAdd(&out[cs * 192 + c * 3], rs);
                    atomicMax((int*)&out[cs * 192 + c * 3 + 1], __float_as_int(rm));
                    rs = 0.f; rm = 0.f; cs = sg;
                }
                rs += v; rm = fmaxf(rm, v);
            }
            atomicAdd(&out[cs * 192 + c * 3], rs);
            atomicMax((int*)&out[cs * 192 + c * 3 + 1], __float_as_int(rm));
        }
    }
}

// ---------------- broadcast global max pool into shuffled output layout ----------------
__global__ void bcast_kernel(float* __restrict__ out)
{
    int i = blockIdx.x * blockDim.x + threadIdx.x;
    if (i < S_SEG * C) {
        int s = i / C, c = i % C;
        out[s * 192 + c * 3 + 2] = __int_as_float(g_maxpool[c]);
    }
}

// ---------------- launch ----------------
extern "C" void kernel_launch(void* const* d_in, const int* in_sizes, int n_in,
                              void* d_out, int out_size)
{
    const float* inputs = (const float*)d_in[0];
    const int*   unq    = (const int*)  d_in[1];
    const float* W1  = (const float*)d_in[3];
    const float* g1  = (const float*)d_in[4];
    const float* b1  = (const float*)d_in[5];
    const float* m1  = (const float*)d_in[6];
    const float* v1  = (const float*)d_in[7];
    const float* W2a = (const float*)d_in[8];
    const float* g2a = (const float*)d_in[9];
    const float* b2a = (const float*)d_in[10];
    const float* m2a = (const float*)d_in[11];
    const float* v2a = (const float*)d_in[12];
    const float* W2b = (const float*)d_in[13];
    const float* g2b = (const float*)d_in[14];
    const float* b2b = (const float*)d_in[15];
    const float* m2b = (const float*)d_in[16];
    const float* v2b = (const float*)d_in[17];
    float* out = (float*)d_out;

    int N = in_sizes[0] / CIN;
    int nblk = (N + TILE - 1) / TILE;

    cudaFuncSetAttribute(branch2_kernel,
                         cudaFuncAttributeMaxDynamicSharedMemorySize, B2_SMEM_FLOATS * 4);

    // launch order chosen so branch2 sits at profiled slot #4
    combo_kernel<<<(out_size + 255) / 256, 256>>>(out, out_size,
                             W1, g1, b1, m1, v1,
                             W2a, g2a, b2a, m2a, v2a,
                             W2b, g2b, b2b, m2b, v2b);
    hist_kernel<<<(N + 255) / 256, 256>>>(unq, N);
    scan_kernel<<<1, 1024>>>();
    branch2_kernel<<<nblk, NTHR, B2_SMEM_FLOATS * 4>>>(inputs, N);
    scatter_kernel<<<(N + 255) / 256, 256>>>(unq, N);
    branch1_kernel<<<nblk, NTHR, B1_SMEM_FLOATS * 4>>>(inputs, out, N);
    bcast_kernel<<<(S_SEG * C + 255) / 256, 256>>>(out);
}

// round 5
// speedup vs baseline: 2.1782x; 1.2100x over previous
#include <cuda_runtime.h>

// Problem constants (fixed by setup_inputs: N=1e6, Cin=16, C=64, S=20000)
#define NMAX   1000000
#define S_SEG  20000
#define CIN    16
#define C      64
#define C2     128
#define TILE   128      // branch1 tile
#define TILE2  256      // branch2 tile
#define NTHR   256
#define EPS_BN 1e-3f
#define HSTR   260      // s_hT row stride (floats): 260 % 32 == 4 -> conflict-free stores

typedef unsigned long long ull;

// packed f32x2 helpers
#define FFMA2(d, a, b) asm("fma.rn.f32x2 %0, %1, %2, %0;" : "+l"(d) : "l"(a), "l"(b))
#define PACK2(d, x)    asm("mov.b64 %0, {%1, %1};" : "=l"(d) : "f"(x))
#define UNPACK2(lo, hi, d) asm("mov.b64 {%0, %1}, %2;" : "=f"(lo), "=f"(hi) : "l"(d))

// ---------------- device scratch ----------------
__device__ int   g_hist[S_SEG];
__device__ int   g_cursor[S_SEG];
__device__ int   g_order[NMAX];
__device__ int   g_seg_sorted[NMAX];
__device__ int   g_maxpool[C];
__device__ float g_W1f[CIN * C],  g_b1f[C];
__device__ float g_W2af[CIN * C2], g_b2af[C2];
__device__ float g_W2bf[C2 * C],  g_b2bf[C];

// ---------------- combo: zero output/counters + fold BN into weights ----------------
__global__ void combo_kernel(float* __restrict__ out, int n_out,
                             const float* __restrict__ W1,
                             const float* __restrict__ g1, const float* __restrict__ b1,
                             const float* __restrict__ m1, const float* __restrict__ v1,
                             const float* __restrict__ W2a,
                             const float* __restrict__ g2a, const float* __restrict__ b2a,
                             const float* __restrict__ m2a, const float* __restrict__ v2a,
                             const float* __restrict__ W2b,
                             const float* __restrict__ g2b, const float* __restrict__ b2b,
                             const float* __restrict__ m2b, const float* __restrict__ v2b)
{
    int i = blockIdx.x * blockDim.x + threadIdx.x;
    if (i < n_out) out[i] = 0.0f;
    if (i < S_SEG) g_hist[i] = 0;
    if (i < C)     g_maxpool[i] = 0;

    const int n1 = CIN * C;          // 1024
    const int n2 = n1 + CIN * C2;    // 3072
    const int n3 = n2 + C2 * C;      // 11264
    if (i < n1) {
        int c = i & (C - 1);
        g_W1f[i] = W1[i] * (g1[c] / sqrtf(v1[c] + EPS_BN));
    } else if (i < n2) {
        int j = i - n1; int c = j & (C2 - 1);
        g_W2af[j] = W2a[j] * (g2a[c] / sqrtf(v2a[c] + EPS_BN));
    } else if (i < n3) {
        int j = i - n2; int c = j & (C - 1);
        g_W2bf[j] = W2b[j] * (g2b[c] / sqrtf(v2b[c] + EPS_BN));
    } else if (i < n3 + C + C2 + C) {
        int j = i - n3;
        if (j < C) {
            g_b1f[j] = b1[j] - m1[j] * (g1[j] / sqrtf(v1[j] + EPS_BN));
        } else if (j < C + C2) {
            int c = j - C;
            g_b2af[c] = b2a[c] - m2a[c] * (g2a[c] / sqrtf(v2a[c] + EPS_BN));
        } else {
            int c = j - C - C2;
            g_b2bf[c] = b2b[c] - m2b[c] * (g2b[c] / sqrtf(v2b[c] + EPS_BN));
        }
    }
}

// ---------------- counting sort ----------------
__global__ void hist_kernel(const int* __restrict__ unq, int N)
{
    int i = blockIdx.x * blockDim.x + threadIdx.x;
    if (i < N) atomicAdd(&g_hist[unq[i]], 1);
}

__global__ void scan_kernel()
{
    __shared__ int wsum[32];
    __shared__ int carry;
    int tid = threadIdx.x;
    if (tid == 0) carry = 0;
    __syncthreads();
    for (int base = 0; base < S_SEG; base += 1024) {
        int i = base + tid;
        int v = (i < S_SEG) ? g_hist[i] : 0;
        int x = v;
        #pragma unroll
        for (int d = 1; d < 32; d <<= 1) {
            int y = __shfl_up_sync(0xffffffffu, x, d);
            if ((tid & 31) >= d) x += y;
        }
        if ((tid & 31) == 31) wsum[tid >> 5] = x;
        __syncthreads();
        if (tid < 32) {
            int s = wsum[tid];
            #pragma unroll
            for (int d = 1; d < 32; d <<= 1) {
                int y = __shfl_up_sync(0xffffffffu, s, d);
                if (tid >= d) s += y;
            }
            wsum[tid] = s;
        }
        __syncthreads();
        int incl = x + ((tid >= 32) ? wsum[(tid >> 5) - 1] : 0);
        int excl = incl - v + carry;
        if (i < S_SEG) g_cursor[i] = excl;
        int chunk_total = wsum[31];
        __syncthreads();
        if (tid == 0) carry += chunk_total;
        __syncthreads();
    }
}

__global__ void scatter_kernel(const int* __restrict__ unq, int N)
{
    int i = blockIdx.x * blockDim.x + threadIdx.x;
    if (i < N) {
        int s = unq[i];
        int pos = atomicAdd(&g_cursor[s], 1);
        g_order[pos] = i;
        g_seg_sorted[pos] = s;
    }
}

// ================= branch2: GEMM2a -> GEMM2b -> global max pool =================
// TILE2=256 points, 256 threads, 8 pts x 8 ch per thread.
// tg = tid&7 (channel group), tp = tid>>3 (points tp*8..tp*8+7).
// GEMM2a runs in 4 phases of 32 h-channels; thread's phase channels are ch = j*8+tg
// (conflict-free h stores with HSTR%32==4); w2a/b2a smem copies are permuted so
// weight loads stay contiguous float4.
// smem floats:
//   s_inT 16*256=4096 @0 | s_hT 32*260=8320 @4096 | s_w2a 2048 @12416 |
//   s_w2b 8192 @14464 | s_b2a 128 @22656 | s_b2b 64 @22784 | s_pool 64 @22848
//   => 22912 fl = 91,648 B  (2 CTAs/SM)
#define B2_SMEM_FLOATS 22912

__global__ void __launch_bounds__(NTHR, 2)
branch2_kernel(const float* __restrict__ inputs, int N)
{
    extern __shared__ float sm[];
    float* s_inT = sm;                  // [16][256]
    float* s_hT  = sm + 4096;           // [32][HSTR] (one 32-ch phase at a time)
    float* s_w2a = sm + 12416;          // [16][128] permuted within 32-ch groups
    float* s_w2b = sm + 14464;          // [128][64]
    float* s_b2a = sm + 22656;          // [128] permuted
    float* s_b2b = sm + 22784;
    int*   s_pool= (int*)(sm + 22848);

    int tid  = threadIdx.x;
    int base = blockIdx.x * TILE2;
    int np   = N - base; if (np > TILE2) np = TILE2;

    // permuted w2a copy: dest col (ph*32 + tg*4 + j) <- src col (ph*32 + j*8 + tg)
    for (int i = tid; i < CIN * C2; i += NTHR) {
        int col = i & 127;
        int r   = col & 31;
        int src = (col & ~31) | ((r & 3) * 8 + (r >> 2));
        s_w2a[i] = g_W2af[(i & ~127) | src];
    }
    for (int i = tid; i < C2 * C; i += NTHR) s_w2b[i] = g_W2bf[i];
    if (tid < C2) {
        int r = tid & 31;
        s_b2a[tid] = g_b2af[(tid & ~31) | ((r & 3) * 8 + (r >> 2))];
    }
    if (tid < C)  s_b2b[tid] = g_b2bf[tid];
    if (tid < C)  s_pool[tid] = 0;

    // coalesced load of [256 pts][16 feat], transpose into s_inT[k][pt]
    #pragma unroll
    for (int q = 0; q < 4; q++) {
        int e  = tid + q * NTHR;
        int pt = e >> 2, f = e & 3;
        float4 v = make_float4(0.f, 0.f, 0.f, 0.f);
        if (pt < np) v = reinterpret_cast<const float4*>(inputs)[(size_t)(base + pt) * 4 + f];
        s_inT[(f * 4 + 0) * TILE2 + pt] = v.x;
        s_inT[(f * 4 + 1) * TILE2 + pt] = v.y;
        s_inT[(f * 4 + 2) * TILE2 + pt] = v.z;
        s_inT[(f * 4 + 3) * TILE2 + pt] = v.w;
    }
    __syncthreads();

    int tg = tid & 7;    // channel group
    int tp = tid >> 3;   // point group (8 points = 4 f32x2 pairs)

    // persistent GEMM2b accumulators: [pair i<4][channel slot j<8]
    ull acc2[4][8];
    #pragma unroll
    for (int i = 0; i < 4; i++)
        #pragma unroll
        for (int j = 0; j < 8; j++) acc2[i][j] = 0ull;

    #pragma unroll
    for (int ph = 0; ph < 4; ph++) {
        int chBase = ph * 32;

        // ---- GEMM2a phase: h channels [chBase, chBase+32) ----
        {
            ull acc[4][4];
            #pragma unroll
            for (int i = 0; i < 4; i++)
                #pragma unroll
                for (int j = 0; j < 4; j++) acc[i][j] = 0ull;
            #pragma unroll
            for (int k = 0; k < CIN; k++) {
                const ulonglong2* ap = reinterpret_cast<const ulonglong2*>(&s_inT[k * TILE2 + tp * 8]);
                ulonglong2 A0 = ap[0], A1 = ap[1];
                ull a[4] = {A0.x, A0.y, A1.x, A1.y};
                float4 b = *reinterpret_cast<float4*>(&s_w2a[k * C2 + chBase + tg * 4]);
                ull bb[4]; PACK2(bb[0], b.x); PACK2(bb[1], b.y); PACK2(bb[2], b.z); PACK2(bb[3], b.w);
                #pragma unroll
                for (int i = 0; i < 4; i++)
                    #pragma unroll
                    for (int j = 0; j < 4; j++) FFMA2(acc[i][j], a[i], bb[j]);
            }
            #pragma unroll
            for (int j = 0; j < 4; j++) {
                int chl = j * 8 + tg;                 // local h row (0..31)
                float bias = s_b2a[chBase + tg * 4 + j];  // permuted bias
                float l0, h0, l1, h1, l2, h2, l3, h3;
                UNPACK2(l0, h0, acc[0][j]); UNPACK2(l1, h1, acc[1][j]);
                UNPACK2(l2, h2, acc[2][j]); UNPACK2(l3, h3, acc[3][j]);
                float4 r0, r1;
                r0.x = fmaxf(l0 + bias, 0.f); r0.y = fmaxf(h0 + bias, 0.f);
                r0.z = fmaxf(l1 + bias, 0.f); r0.w = fmaxf(h1 + bias, 0.f);
                r1.x = fmaxf(l2 + bias, 0.f); r1.y = fmaxf(h2 + bias, 0.f);
                r1.z = fmaxf(l3 + bias, 0.f); r1.w = fmaxf(h3 + bias, 0.f);
                *reinterpret_cast<float4*>(&s_hT[chl * HSTR + tp * 8])     = r0;
                *reinterpret_cast<float4*>(&s_hT[chl * HSTR + tp * 8 + 4]) = r1;
            }
        }
        __syncthreads();

        // ---- GEMM2b partial: accumulate this 32-channel K-chunk ----
        #pragma unroll 8
        for (int kl = 0; kl < 32; kl++) {
            int k = chBase + kl;
            const ulonglong2* ap = reinterpret_cast<const ulonglong2*>(&s_hT[kl * HSTR + tp * 8]);
            ulonglong2 A0 = ap[0], A1 = ap[1];
            ull a[4] = {A0.x, A0.y, A1.x, A1.y};
            float4 b0 = *reinterpret_cast<float4*>(&s_w2b[k * C + tg * 4]);
            float4 b1 = *reinterpret_cast<float4*>(&s_w2b[k * C + 32 + tg * 4]);
            ull bb[8];
            PACK2(bb[0], b0.x); PACK2(bb[1], b0.y); PACK2(bb[2], b0.z); PACK2(bb[3], b0.w);
            PACK2(bb[4], b1.x); PACK2(bb[5], b1.y); PACK2(bb[6], b1.z); PACK2(bb[7], b1.w);
            #pragma unroll
            for (int i = 0; i < 4; i++)
                #pragma unroll
                for (int j = 0; j < 8; j++) FFMA2(acc2[i][j], a[i], bb[j]);
        }
        __syncthreads();
    }

    // ---- epilogue: bias + relu + masked global max pool ----
    {
        float pm[8];
        #pragma unroll
        for (int j = 0; j < 8; j++) pm[j] = 0.f;
        #pragma unroll
        for (int i = 0; i < 4; i++) {
            bool v0 = (tp * 8 + 2 * i)     < np;
            bool v1 = (tp * 8 + 2 * i + 1) < np;
            #pragma unroll
            for (int j = 0; j < 8; j++) {
                int cj = (j >> 2) * 32 + tg * 4 + (j & 3);
                float lo, hi;
                UNPACK2(lo, hi, acc2[i][j]);
                float bias = s_b2b[cj];
                float x0 = fmaxf(lo + bias, 0.f);
                float x1 = fmaxf(hi + bias, 0.f);
                if (v0) pm[j] = fmaxf(pm[j], x0);
                if (v1) pm[j] = fmaxf(pm[j], x1);
            }
        }
        #pragma unroll
        for (int j = 0; j < 8; j++) {
            int cj = (j >> 2) * 32 + tg * 4 + (j & 3);
            atomicMax(&s_pool[cj], __float_as_int(pm[j]));
        }
    }
    __syncthreads();
    if (tid < C) atomicMax(&g_maxpool[tid], s_pool[tid]);
}

// ================= branch1: GEMM1 + segmented sum/max over sorted points =================
// smem floats: s_inT 2048 | s_x 8192 | s_w1 1024 | s_b1 64 | s_seg 128 | s_idx 128 = 11584 (46,336 B)
#define B1_SMEM_FLOATS 11584

__global__ void __launch_bounds__(NTHR, 3)
branch1_kernel(const float* __restrict__ inputs, float* __restrict__ out, int N)
{
    extern __shared__ float sm[];
    float* s_inT = sm;                 // [16][128]
    float* s_x   = sm + 2048;          // [128][64]
    float* s_w1  = sm + 10240;         // [16][64]
    float* s_b1  = sm + 11264;
    int*   s_seg = (int*)(sm + 11328);
    int*   s_idx = (int*)(sm + 11456);

    int tid  = threadIdx.x;
    int base = blockIdx.x * TILE;
    int np   = N - base; if (np > TILE) np = TILE;

    for (int i = tid; i < CIN * C; i += NTHR) s_w1[i] = g_W1f[i];
    if (tid < C) s_b1[tid] = g_b1f[tid];
    if (tid < TILE) {
        int seg = -1, idx = 0;
        if (tid < np) { idx = g_order[base + tid]; seg = g_seg_sorted[base + tid]; }
        s_idx[tid] = idx;
        s_seg[tid] = seg;
    }
    __syncthreads();

    // gather sorted points (random), transpose into s_inT[k][pt]
    #pragma unroll
    for (int q = 0; q < 2; q++) {
        int e  = tid + q * NTHR;
        int pt = e >> 2, f = e & 3;
        float4 v = make_float4(0.f, 0.f, 0.f, 0.f);
        if (pt < np) v = reinterpret_cast<const float4*>(inputs)[(size_t)s_idx[pt] * 4 + f];
        s_inT[(f * 4 + 0) * TILE + pt] = v.x;
        s_inT[(f * 4 + 1) * TILE + pt] = v.y;
        s_inT[(f * 4 + 2) * TILE + pt] = v.z;
        s_inT[(f * 4 + 3) * TILE + pt] = v.w;
    }
    __syncthreads();

    int tg = tid & 7;    // 8 channel-groups of 8 chunked channels
    int tp = tid >> 3;   // 32 point-groups of 4

    // ---- GEMM1: x = relu(in @ W1f + b1f), 128x64, K=16 ----
    {
        ull acc[2][8];
        #pragma unroll
        for (int i = 0; i < 2; i++)
            #pragma unroll
            for (int j = 0; j < 8; j++) acc[i][j] = 0ull;
        #pragma unroll
        for (int k = 0; k < CIN; k++) {
            ulonglong2 A = *reinterpret_cast<const ulonglong2*>(&s_inT[k * TILE + tp * 4]);
            float4 b0 = *reinterpret_cast<float4*>(&s_w1[k * C + tg * 4]);
            float4 b1 = *reinterpret_cast<float4*>(&s_w1[k * C + 32 + tg * 4]);
            ull bb[8];
            PACK2(bb[0], b0.x); PACK2(bb[1], b0.y); PACK2(bb[2], b0.z); PACK2(bb[3], b0.w);
            PACK2(bb[4], b1.x); PACK2(bb[5], b1.y); PACK2(bb[6], b1.z); PACK2(bb[7], b1.w);
            #pragma unroll
            for (int j = 0; j < 8; j++) { FFMA2(acc[0][j], A.x, bb[j]); FFMA2(acc[1][j], A.y, bb[j]); }
        }
        #pragma unroll
        for (int j = 0; j < 8; j++) {
            int cj = (j >> 2) * 32 + tg * 4 + (j & 3);
            float bias = s_b1[cj];
            float l0, h0, l1, h1;
            UNPACK2(l0, h0, acc[0][j]);
            UNPACK2(l1, h1, acc[1][j]);
            s_x[(tp * 4 + 0) * C + cj] = fmaxf(l0 + bias, 0.f);
            s_x[(tp * 4 + 1) * C + cj] = fmaxf(h0 + bias, 0.f);
            s_x[(tp * 4 + 2) * C + cj] = fmaxf(l1 + bias, 0.f);
            s_x[(tp * 4 + 3) * C + cj] = fmaxf(h1 + bias, 0.f);
        }
    }
    __syncthreads();

    // ---- segmented run-reduction, 4-way split: thread (c, q) scans points [q*32, q*32+32) ----
    {
        int c = tid & 63;
        int q = tid >> 6;
        int p0 = q * 32;
        int p1 = p0 + 32; if (p1 > np) p1 = np;
        if (p0 < np) {
            int   cs = s_seg[p0];
            float rs = 0.f, rm = 0.f;
            for (int p = p0; p < p1; p++) {
                int   sg = s_seg[p];
                float v  = s_x[p * C + c];
                if (sg != cs) {
                    atomicAdd(&out[cs * 192 + c * 3], rs);
                    atomicMax((int*)&out[cs * 192 + c * 3 + 1], __float_as_int(rm));
                    rs = 0.f; rm = 0.f; cs = sg;
                }
                rs += v; rm = fmaxf(rm, v);
            }
            atomicAdd(&out[cs * 192 + c * 3], rs);
            atomicMax((int*)&out[cs * 192 + c * 3 + 1], __float_as_int(rm));
        }
    }
}

// ---------------- broadcast global max pool into shuffled output layout ----------------
__global__ void bcast_kernel(float* __restrict__ out)
{
    int i = blockIdx.x * blockDim.x + threadIdx.x;
    if (i < S_SEG * C) {
        int s = i / C, c = i % C;
        out[s * 192 + c * 3 + 2] = __int_as_float(g_maxpool[c]);
    }
}

// ---------------- launch ----------------
extern "C" void kernel_launch(void* const* d_in, const int* in_sizes, int n_in,
                              void* d_out, int out_size)
{
    const float* inputs = (const float*)d_in[0];
    const int*   unq    = (const int*)  d_in[1];
    const float* W1  = (const float*)d_in[3];
    const float* g1  = (const float*)d_in[4];
    const float* b1  = (const float*)d_in[5];
    const float* m1  = (const float*)d_in[6];
    const float* v1  = (const float*)d_in[7];
    const float* W2a = (const float*)d_in[8];
    const float* g2a = (const float*)d_in[9];
    const float* b2a = (const float*)d_in[10];
    const float* m2a = (const float*)d_in[11];
    const float* v2a = (const float*)d_in[12];
    const float* W2b = (const float*)d_in[13];
    const float* g2b = (const float*)d_in[14];
    const float* b2b = (const float*)d_in[15];
    const float* m2b = (const float*)d_in[16];
    const float* v2b = (const float*)d_in[17];
    float* out = (float*)d_out;

    int N = in_sizes[0] / CIN;
    int nblk1 = (N + TILE  - 1) / TILE;
    int nblk2 = (N + TILE2 - 1) / TILE2;

    cudaFuncSetAttribute(branch2_kernel,
                         cudaFuncAttributeMaxDynamicSharedMemorySize, B2_SMEM_FLOATS * 4);

    // launch order chosen so branch2 sits at profiled slot #4
    combo_kernel<<<(out_size + 255) / 256, 256>>>(out, out_size,
                             W1, g1, b1, m1, v1,
                             W2a, g2a, b2a, m2a, v2a,
                             W2b, g2b, b2b, m2b, v2b);
    hist_kernel<<<(N + 255) / 256, 256>>>(unq, N);
    scan_kernel<<<1, 1024>>>();
    branch2_kernel<<<nblk2, NTHR, B2_SMEM_FLOATS * 4>>>(inputs, N);
    scatter_kernel<<<(N + 255) / 256, 256>>>(unq, N);
    branch1_kernel<<<nblk1, NTHR, B1_SMEM_FLOATS * 4>>>(inputs, out, N);
    bcast_kernel<<<(S_SEG * C + 255) / 256, 256>>>(out);
}

// round 8
// speedup vs baseline: 3.2698x; 1.5012x over previous
#include <cuda_runtime.h>
#include <cuda_bf16.h>
#include <cstdint>

// Problem constants (fixed by setup_inputs: N=1e6, Cin=16, C=64, S=20000)
#define NMAX   1000000
#define S_SEG  20000
#define CIN    16
#define C      64
#define C2     128
#define TILE   128
#define NTHR   256
#define EPS_BN 1e-3f

typedef unsigned long long ull;

// packed f32x2 helpers (branch1)
#define FFMA2(d, a, b) asm("fma.rn.f32x2 %0, %1, %2, %0;" : "+l"(d) : "l"(a), "l"(b))
#define PACK2(d, x)    asm("mov.b64 %0, {%1, %1};" : "=l"(d) : "f"(x))
#define UNPACK2(lo, hi, d) asm("mov.b64 {%0, %1}, %2;" : "=f"(lo), "=f"(hi) : "l"(d))

// bf16x2 pack: low half <- x (smaller col), high half <- y
__device__ __forceinline__ uint32_t pack_bf16x2(float x, float y) {
    uint32_t r;
    asm("cvt.rn.bf16x2.f32 %0, %1, %2;" : "=r"(r) : "f"(y), "f"(x));
    return r;
}
// split (x,y) into hi bf16x2 and lo bf16x2 (residual)
__device__ __forceinline__ void split_bf16x2(float x, float y, uint32_t& hi, uint32_t& lo) {
    hi = pack_bf16x2(x, y);
    float hx = __uint_as_float(hi << 16);
    float hy = __uint_as_float(hi & 0xffff0000u);
    lo = pack_bf16x2(x - hx, y - hy);
}

// m16n8k16 bf16 MMA, fp32 accumulate (baseline PTX, compiles for compute_100)
#define MMA_BF16(d, a, b0, b1) \
    asm volatile("mma.sync.aligned.m16n8k16.row.col.f32.bf16.bf16.f32 " \
        "{%0,%1,%2,%3}, {%4,%5,%6,%7}, {%8,%9}, {%0,%1,%2,%3};" \
        : "+f"((d)[0]), "+f"((d)[1]), "+f"((d)[2]), "+f"((d)[3]) \
        : "r"((a)[0]), "r"((a)[1]), "r"((a)[2]), "r"((a)[3]), "r"(b0), "r"(b1))

// ---------------- device scratch ----------------
__device__ int   g_hist[S_SEG];
__device__ int   g_cursor[S_SEG];
__device__ int   g_order[NMAX];
__device__ int   g_seg_sorted[NMAX];
__device__ int   g_maxpool[C];
__device__ float g_W1f[CIN * C],  g_b1f[C];
__device__ float g_W2af[CIN * C2], g_b2af[C2];
__device__ float g_W2bf[C2 * C],  g_b2bf[C];
// pre-packed per-lane MMA B-fragments (uint32 = bf16x2), hi (v=0) and lo (v=1)
__device__ uint32_t g_fragA[2 * 16 * 64];          // W2a: [v][ntile(16)][lane*2+r]
__device__ uint32_t g_fragB[2 * 8 * 8 * 64];       // W2b: [v][kb(8)][ntile(8)][lane*2+r]

// ---------------- combo: zero output/counters + fold BN into weights ----------------
__global__ void combo_kernel(float* __restrict__ out, int n_out,
                             const float* __restrict__ W1,
                             const float* __restrict__ g1, const float* __restrict__ b1,
                             const float* __restrict__ m1, const float* __restrict__ v1,
                             const float* __restrict__ W2a,
                             const float* __restrict__ g2a, const float* __restrict__ b2a,
                             const float* __restrict__ m2a, const float* __restrict__ v2a,
                             const float* __restrict__ W2b,
                             const float* __restrict__ g2b, const float* __restrict__ b2b,
                             const float* __restrict__ m2b, const float* __restrict__ v2b)
{
    int i = blockIdx.x * blockDim.x + threadIdx.x;
    if (i < n_out) out[i] = 0.0f;
    if (i < S_SEG) g_hist[i] = 0;
    if (i < C)     g_maxpool[i] = 0;

    const int n1 = CIN * C;          // 1024
    const int n2 = n1 + CIN * C2;    // 3072
    const int n3 = n2 + C2 * C;      // 11264
    if (i < n1) {
        int c = i & (C - 1);
        g_W1f[i] = W1[i] * (g1[c] / sqrtf(v1[c] + EPS_BN));
    } else if (i < n2) {
        int j = i - n1; int c = j & (C2 - 1);
        g_W2af[j] = W2a[j] * (g2a[c] / sqrtf(v2a[c] + EPS_BN));
    } else if (i < n3) {
        int j = i - n2; int c = j & (C - 1);
        g_W2bf[j] = W2b[j] * (g2b[c] / sqrtf(v2b[c] + EPS_BN));
    } else if (i < n3 + C + C2 + C) {
        int j = i - n3;
        if (j < C) {
            g_b1f[j] = b1[j] - m1[j] * (g1[j] / sqrtf(v1[j] + EPS_BN));
        } else if (j < C + C2) {
            int c = j - C;
            g_b2af[c] = b2a[c] - m2a[c] * (g2a[c] / sqrtf(v2a[c] + EPS_BN));
        } else {
            int c = j - C - C2;
            g_b2bf[c] = b2b[c] - m2b[c] * (g2b[c] / sqrtf(v2b[c] + EPS_BN));
        }
    }
}

// ---------------- prep2: build per-lane hi/lo weight fragments ----------------
// m16n8k16 B fragment (col): b_r holds {B[k0][n], B[k0+1][n]} with
//   lane: g=lane>>2, t=lane&3;  n = ntile*8+g;  k0 = 2t + (r ? 8 : 0)
__global__ void prep2_kernel()
{
    int i = blockIdx.x * blockDim.x + threadIdx.x;
    if (i < 2048) {
        // W2a fragments: K=16 (features), N=128
        int v = i >> 10, rem = i & 1023;
        int nt = rem >> 6, q = rem & 63;
        int lane = q >> 1, r = q & 1;
        int g = lane >> 2, t = lane & 3;
        int n = nt * 8 + g;
        int k0 = 2 * t + (r ? 8 : 0);
        float w0 = g_W2af[k0 * C2 + n];
        float w1 = g_W2af[(k0 + 1) * C2 + n];
        uint32_t hi, lo;
        split_bf16x2(w0, w1, hi, lo);
        g_fragA[i] = v ? lo : hi;
    } else if (i < 2048 + 8192) {
        // W2b fragments: K=128 (8 kblocks), N=64
        int j = i - 2048;
        int v = j >> 12, rem = j & 4095;
        int kb = rem >> 9, rem2 = rem & 511;
        int nt = rem2 >> 6, q = rem2 & 63;
        int lane = q >> 1, r = q & 1;
        int g = lane >> 2, t = lane & 3;
        int n = nt * 8 + g;
        int k = kb * 16 + 2 * t + (r ? 8 : 0);
        float w0 = g_W2bf[k * C + n];
        float w1 = g_W2bf[(k + 1) * C + n];
        uint32_t hi, lo;
        split_bf16x2(w0, w1, hi, lo);
        g_fragB[j] = v ? lo : hi;
    }
}

// ---------------- counting sort ----------------
__global__ void hist_kernel(const int* __restrict__ unq, int N)
{
    int i = blockIdx.x * blockDim.x + threadIdx.x;
    if (i < N) atomicAdd(&g_hist[unq[i]], 1);
}

__global__ void scan_kernel()
{
    __shared__ int wsum[32];
    __shared__ int carry;
    int tid = threadIdx.x;
    if (tid == 0) carry = 0;
    __syncthreads();
    for (int base = 0; base < S_SEG; base += 1024) {
        int i = base + tid;
        int v = (i < S_SEG) ? g_hist[i] : 0;
        int x = v;
        #pragma unroll
        for (int d = 1; d < 32; d <<= 1) {
            int y = __shfl_up_sync(0xffffffffu, x, d);
            if ((tid & 31) >= d) x += y;
        }
        if ((tid & 31) == 31) wsum[tid >> 5] = x;
        __syncthreads();
        if (tid < 32) {
            int s = wsum[tid];
            #pragma unroll
            for (int d = 1; d < 32; d <<= 1) {
                int y = __shfl_up_sync(0xffffffffu, s, d);
                if (tid >= d) s += y;
            }
            wsum[tid] = s;
        }
        __syncthreads();
        int incl = x + ((tid >= 32) ? wsum[(tid >> 5) - 1] : 0);
        int excl = incl - v + carry;
        if (i < S_SEG) g_cursor[i] = excl;
        int chunk_total = wsum[31];
        __syncthreads();
        if (tid == 0) carry += chunk_total;
        __syncthreads();
    }
}

__global__ void scatter_kernel(const int* __restrict__ unq, int N)
{
    int i = blockIdx.x * blockDim.x + threadIdx.x;
    if (i < N) {
        int s = unq[i];
        int pos = atomicAdd(&g_cursor[s], 1);
        g_order[pos] = i;
        g_seg_sorted[pos] = s;
    }
}

// ================= branch2 (mma.sync bf16 split-precision) =================
// Persistent, grid=148, 256 thr (8 warps); warp w owns rows w*16+g, w*16+g+8.
// smem floats:
//   s_a [128][16] f32 @0 (2048) | s_fa 2048 u32 @2048 | s_fb 8192 u32 @4096 |
//   s_b2a 128 @12288 | s_b2b 64 @12416 | s_pool 64 ints @12480 => 12544 fl = 50,176 B
#define B2_SMEM_FLOATS 12544

__global__ void __launch_bounds__(NTHR, 1)
branch2_kernel(const float* __restrict__ inputs, int N, int ntiles)
{
    extern __shared__ float sm[];
    float*    s_a   = sm;
    uint32_t* s_fa  = (uint32_t*)(sm + 2048);
    uint32_t* s_fb  = (uint32_t*)(sm + 4096);
    float*    s_b2a = sm + 12288;
    float*    s_b2b = sm + 12416;
    int*      s_pool= (int*)(sm + 12480);

    int tid = threadIdx.x;
    int w   = tid >> 5;
    int lane= tid & 31;
    int g   = lane >> 2;
    int t   = lane & 3;

    // load weight fragments + biases into smem
    for (int i = tid; i < 2048; i += NTHR) s_fa[i] = g_fragA[i];
    for (int i = tid; i < 8192; i += NTHR) s_fb[i] = g_fragB[i];
    if (tid < C2) s_b2a[tid] = g_b2af[tid];
    if (tid < C)  s_b2b[tid] = g_b2bf[tid];
    if (tid < C)  s_pool[tid] = 0;
    __syncthreads();

    const int r0 = w * 16 + g;       // logical tile rows handled by this lane
    const int r1 = r0 + 8;

    float pm[16];
    #pragma unroll
    for (int j = 0; j < 16; j++) pm[j] = 0.f;

    for (int tI = blockIdx.x; tI < ntiles; tI += gridDim.x) {
        int base = tI * TILE;
        int np = N - base; if (np > TILE) np = TILE;

        // ---- stage input tile [128][16] f32 (coalesced) ----
        #pragma unroll
        for (int q = 0; q < 2; q++) {
            int idx = tid + q * NTHR;          // 0..511 float4s
            int pt = idx >> 2, f = idx & 3;
            float4 v = make_float4(0.f, 0.f, 0.f, 0.f);
            if (pt < np) v = reinterpret_cast<const float4*>(inputs)[(size_t)(base + pt) * 4 + f];
            reinterpret_cast<float4*>(s_a)[pt * 4 + f] = v;
        }
        __syncthreads();

        // ---- A1 fragments (hi/lo) from staged tile ----
        uint32_t a1h[4], a1l[4];
        {
            float2 p0 = *reinterpret_cast<float2*>(&s_a[r0 * 16 + 2 * t]);
            float2 p1 = *reinterpret_cast<float2*>(&s_a[r1 * 16 + 2 * t]);
            float2 p2 = *reinterpret_cast<float2*>(&s_a[r0 * 16 + 2 * t + 8]);
            float2 p3 = *reinterpret_cast<float2*>(&s_a[r1 * 16 + 2 * t + 8]);
            split_bf16x2(p0.x, p0.y, a1h[0], a1l[0]);
            split_bf16x2(p1.x, p1.y, a1h[1], a1l[1]);
            split_bf16x2(p2.x, p2.y, a1h[2], a1l[2]);
            split_bf16x2(p3.x, p3.y, a1h[3], a1l[3]);
        }

        float d2[32];
        #pragma unroll
        for (int j = 0; j < 32; j++) d2[j] = 0.f;

        // ---- two phases over h-channels (64 each) ----
        #pragma unroll
        for (int phx = 0; phx < 2; phx++) {
            // GEMM2a: d1 = A1 x W2a for ntiles [phx*8, phx*8+8)
            float d1[32];
            #pragma unroll
            for (int j = 0; j < 32; j++) d1[j] = 0.f;
            #pragma unroll
            for (int nt8 = 0; nt8 < 8; nt8++) {
                int nt = phx * 8 + nt8;
                uint2 fh = *reinterpret_cast<uint2*>(&s_fa[nt * 64 + lane * 2]);
                uint2 fl = *reinterpret_cast<uint2*>(&s_fa[1024 + nt * 64 + lane * 2]);
                MMA_BF16(&d1[nt8 * 4], a1h, fh.x, fh.y);
                MMA_BF16(&d1[nt8 * 4], a1h, fl.x, fl.y);
                MMA_BF16(&d1[nt8 * 4], a1l, fh.x, fh.y);
            }
            // epi1: bias + relu + split -> A2 fragments (register-only, D->A identity)
            uint32_t a2h[16], a2l[16];
            #pragma unroll
            for (int nt8 = 0; nt8 < 8; nt8++) {
                int nt = phx * 8 + nt8;
                float2 bi = *reinterpret_cast<float2*>(&s_b2a[nt * 8 + 2 * t]);
                float h0 = fmaxf(d1[nt8 * 4 + 0] + bi.x, 0.f);
                float h1 = fmaxf(d1[nt8 * 4 + 1] + bi.y, 0.f);
                float h2 = fmaxf(d1[nt8 * 4 + 2] + bi.x, 0.f);
                float h3 = fmaxf(d1[nt8 * 4 + 3] + bi.y, 0.f);
                int kbl = nt8 >> 1, half = nt8 & 1;
                int s0 = kbl * 4 + half * 2;
                split_bf16x2(h0, h1, a2h[s0],     a2l[s0]);
                split_bf16x2(h2, h3, a2h[s0 + 1], a2l[s0 + 1]);
            }
            // GEMM2b partial: kblocks [phx*4, phx*4+4)
            #pragma unroll
            for (int nt = 0; nt < 8; nt++) {
                #pragma unroll
                for (int kbl = 0; kbl < 4; kbl++) {
                    int kb = phx * 4 + kbl;
                    uint2 fh = *reinterpret_cast<uint2*>(&s_fb[kb * 512 + nt * 64 + lane * 2]);
                    uint2 fl = *reinterpret_cast<uint2*>(&s_fb[4096 + kb * 512 + nt * 64 + lane * 2]);
                    MMA_BF16(&d2[nt * 4], &a2h[kbl * 4], fh.x, fh.y);
                    MMA_BF16(&d2[nt * 4], &a2h[kbl * 4], fl.x, fl.y);
                    MMA_BF16(&d2[nt * 4], &a2l[kbl * 4], fh.x, fh.y);
                }
            }
        }

        // ---- epi2: bias + relu + masked max pool ----
        {
            bool v0 = r0 < np;
            bool v1 = r1 < np;
            #pragma unroll
            for (int nt = 0; nt < 8; nt++) {
                float2 bi = *reinterpret_cast<float2*>(&s_b2b[nt * 8 + 2 * t]);
                float x0 = fmaxf(d2[nt * 4 + 0] + bi.x, 0.f);
                float x1 = fmaxf(d2[nt * 4 + 1] + bi.y, 0.f);
                float x2 = fmaxf(d2[nt * 4 + 2] + bi.x, 0.f);
                float x3 = fmaxf(d2[nt * 4 + 3] + bi.y, 0.f);
                if (v0) { pm[nt * 2 + 0] = fmaxf(pm[nt * 2 + 0], x0); pm[nt * 2 + 1] = fmaxf(pm[nt * 2 + 1], x1); }
                if (v1) { pm[nt * 2 + 0] = fmaxf(pm[nt * 2 + 0], x2); pm[nt * 2 + 1] = fmaxf(pm[nt * 2 + 1], x3); }
            }
        }
        __syncthreads();   // protect s_a before next tile's staging
    }

    #pragma unroll
    for (int nt = 0; nt < 8; nt++) {
        atomicMax(&s_pool[nt * 8 + 2 * t + 0], __float_as_int(pm[nt * 2 + 0]));
        atomicMax(&s_pool[nt * 8 + 2 * t + 1], __float_as_int(pm[nt * 2 + 1]));
    }
    __syncthreads();
    if (tid < C) atomicMax(&g_maxpool[tid], s_pool[tid]);
}

// ================= branch1: GEMM1 + segmented sum/max over sorted points =================
#define B1_SMEM_FLOATS 11584

__global__ void __launch_bounds__(NTHR, 3)
branch1_kernel(const float* __restrict__ inputs, float* __restrict__ out, int N)
{
    extern __shared__ float sm[];
    float* s_inT = sm;                 // [16][128]
    float* s_x   = sm + 2048;          // [128][64]
    float* s_w1  = sm + 10240;         // [16][64]
    float* s_b1  = sm + 11264;
    int*   s_seg = (int*)(sm + 11328);
    int*   s_idx = (int*)(sm + 11456);

    int tid  = threadIdx.x;
    int base = blockIdx.x * TILE;
    int np   = N - base; if (np > TILE) np = TILE;

    for (int i = tid; i < CIN * C; i += NTHR) s_w1[i] = g_W1f[i];
    if (tid < C) s_b1[tid] = g_b1f[tid];
    if (tid < TILE) {
        int seg = -1, idx = 0;
        if (tid < np) { idx = g_order[base + tid]; seg = g_seg_sorted[base + tid]; }
        s_idx[tid] = idx;
        s_seg[tid] = seg;
    }
    __syncthreads();

    #pragma unroll
    for (int q = 0; q < 2; q++) {
        int e  = tid + q * NTHR;
        int pt = e >> 2, f = e & 3;
        float4 v = make_float4(0.f, 0.f, 0.f, 0.f);
        if (pt < np) v = reinterpret_cast<const float4*>(inputs)[(size_t)s_idx[pt] * 4 + f];
        s_inT[(f * 4 + 0) * TILE + pt] = v.x;
        s_inT[(f * 4 + 1) * TILE + pt] = v.y;
        s_inT[(f * 4 + 2) * TILE + pt] = v.z;
        s_inT[(f * 4 + 3) * TILE + pt] = v.w;
    }
    __syncthreads();

    int tg = tid & 7;
    int tp = tid >> 3;

    {
        ull acc[2][8];
        #pragma unroll
        for (int i = 0; i < 2; i++)
            #pragma unroll
            for (int j = 0; j < 8; j++) acc[i][j] = 0ull;
        #pragma unroll
        for (int k = 0; k < CIN; k++) {
            ulonglong2 A = *reinterpret_cast<const ulonglong2*>(&s_inT[k * TILE + tp * 4]);
            float4 b0 = *reinterpret_cast<float4*>(&s_w1[k * C + tg * 4]);
            float4 b1 = *reinterpret_cast<float4*>(&s_w1[k * C + 32 + tg * 4]);
            ull bb[8];
            PACK2(bb[0], b0.x); PACK2(bb[1], b0.y); PACK2(bb[2], b0.z); PACK2(bb[3], b0.w);
            PACK2(bb[4], b1.x); PACK2(bb[5], b1.y); PACK2(bb[6], b1.z); PACK2(bb[7], b1.w);
            #pragma unroll
            for (int j = 0; j < 8; j++) { FFMA2(acc[0][j], A.x, bb[j]); FFMA2(acc[1][j], A.y, bb[j]); }
        }
        #pragma unroll
        for (int j = 0; j < 8; j++) {
            int cj = (j >> 2) * 32 + tg * 4 + (j & 3);
            float bias = s_b1[cj];
            float l0, h0, l1, h1;
            UNPACK2(l0, h0, acc[0][j]);
            UNPACK2(l1, h1, acc[1][j]);
            s_x[(tp * 4 + 0) * C + cj] = fmaxf(l0 + bias, 0.f);
            s_x[(tp * 4 + 1) * C + cj] = fmaxf(h0 + bias, 0.f);
            s_x[(tp * 4 + 2) * C + cj] = fmaxf(l1 + bias, 0.f);
            s_x[(tp * 4 + 3) * C + cj] = fmaxf(h1 + bias, 0.f);
        }
    }
    __syncthreads();

    {
        int c = tid & 63;
        int q = tid >> 6;
        int p0 = q * 32;
        int p1 = p0 + 32; if (p1 > np) p1 = np;
        if (p0 < np) {
            int   cs = s_seg[p0];
            float rs = 0.f, rm = 0.f;
            for (int p = p0; p < p1; p++) {
                int   sg = s_seg[p];
                float v  = s_x[p * C + c];
                if (sg != cs) {
                    atomicAdd(&out[cs * 192 + c * 3], rs);
                    atomicMax((int*)&out[cs * 192 + c * 3 + 1], __float_as_int(rm));
                    rs = 0.f; rm = 0.f; cs = sg;
                }
                rs += v; rm = fmaxf(rm, v);
            }
            atomicAdd(&out[cs * 192 + c * 3], rs);
            atomicMax((int*)&out[cs * 192 + c * 3 + 1], __float_as_int(rm));
        }
    }
}

// ---------------- broadcast global max pool into shuffled output layout ----------------
__global__ void bcast_kernel(float* __restrict__ out)
{
    int i = blockIdx.x * blockDim.x + threadIdx.x;
    if (i < S_SEG * C) {
        int s = i / C, c = i % C;
        out[s * 192 + c * 3 + 2] = __int_as_float(g_maxpool[c]);
    }
}

// ---------------- launch ----------------
extern "C" void kernel_launch(void* const* d_in, const int* in_sizes, int n_in,
                              void* d_out, int out_size)
{
    const float* inputs = (const float*)d_in[0];
    const int*   unq    = (const int*)  d_in[1];
    const float* W1  = (const float*)d_in[3];
    const float* g1  = (const float*)d_in[4];
    const float* b1  = (const float*)d_in[5];
    const float* m1  = (const float*)d_in[6];
    const float* v1  = (const float*)d_in[7];
    const float* W2a = (const float*)d_in[8];
    const float* g2a = (const float*)d_in[9];
    const float* b2a = (const float*)d_in[10];
    const float* m2a = (const float*)d_in[11];
    const float* v2a = (const float*)d_in[12];
    const float* W2b = (const float*)d_in[13];
    const float* g2b = (const float*)d_in[14];
    const float* b2b = (const float*)d_in[15];
    const float* m2b = (const float*)d_in[16];
    const float* v2b = (const float*)d_in[17];
    float* out = (float*)d_out;

    int N = in_sizes[0] / CIN;
    int ntiles = (N + TILE - 1) / TILE;

    cudaFuncSetAttribute(branch2_kernel,
                         cudaFuncAttributeMaxDynamicSharedMemorySize, B2_SMEM_FLOATS * 4);

    // branch2 is launch #4 (profiled slot)
    combo_kernel<<<(out_size + 255) / 256, 256>>>(out, out_size,
                             W1, g1, b1, m1, v1,
                             W2a, g2a, b2a, m2a, v2a,
                             W2b, g2b, b2b, m2b, v2b);
    prep2_kernel<<<40, 256>>>();
    hist_kernel<<<(N + 255) / 256, 256>>>(unq, N);
    branch2_kernel<<<148, NTHR, B2_SMEM_FLOATS * 4>>>(inputs, N, ntiles);
    scan_kernel<<<1, 1024>>>();
    scatter_kernel<<<(N + 255) / 256, 256>>>(unq, N);
    branch1_kernel<<<ntiles, NTHR, B1_SMEM_FLOATS * 4>>>(inputs, out, N);
    bcast_kernel<<<(S_SEG * C + 255) / 256, 256>>>(out);
}

// round 9
// speedup vs baseline: 3.5780x; 1.0942x over previous
#include <cuda_runtime.h>
#include <cuda_bf16.h>
#include <cstdint>

// Problem constants (fixed by setup_inputs: N=1e6, Cin=16, C=64, S=20000)
#define NMAX   1000000
#define S_SEG  20000
#define CIN    16
#define C      64
#define C2     128
#define TILE   128
#define NTHR   256
#define EPS_BN 1e-3f

typedef unsigned long long ull;

// packed f32x2 helpers (branch1)
#define FFMA2(d, a, b) asm("fma.rn.f32x2 %0, %1, %2, %0;" : "+l"(d) : "l"(a), "l"(b))
#define PACK2(d, x)    asm("mov.b64 %0, {%1, %1};" : "=l"(d) : "f"(x))
#define UNPACK2(lo, hi, d) asm("mov.b64 {%0, %1}, %2;" : "=f"(lo), "=f"(hi) : "l"(d))

// bf16x2 pack: low half <- x (smaller col), high half <- y
__device__ __forceinline__ uint32_t pack_bf16x2(float x, float y) {
    uint32_t r;
    asm("cvt.rn.bf16x2.f32 %0, %1, %2;" : "=r"(r) : "f"(y), "f"(x));
    return r;
}
// split (x,y) into hi bf16x2 and lo bf16x2 (residual)
__device__ __forceinline__ void split_bf16x2(float x, float y, uint32_t& hi, uint32_t& lo) {
    hi = pack_bf16x2(x, y);
    float hx = __uint_as_float(hi << 16);
    float hy = __uint_as_float(hi & 0xffff0000u);
    lo = pack_bf16x2(x - hx, y - hy);
}

// m16n8k16 bf16 MMA, fp32 accumulate (baseline PTX, compiles for compute_100)
#define MMA_BF16(d, a, b0, b1) \
    asm volatile("mma.sync.aligned.m16n8k16.row.col.f32.bf16.bf16.f32 " \
        "{%0,%1,%2,%3}, {%4,%5,%6,%7}, {%8,%9}, {%0,%1,%2,%3};" \
        : "+f"((d)[0]), "+f"((d)[1]), "+f"((d)[2]), "+f"((d)[3]) \
        : "r"((a)[0]), "r"((a)[1]), "r"((a)[2]), "r"((a)[3]), "r"(b0), "r"(b1))

// ---------------- device scratch ----------------
__device__ int   g_hist[S_SEG];
__device__ int   g_cursor[S_SEG];
__device__ int   g_order[NMAX];
__device__ int   g_seg_sorted[NMAX];
__device__ int   g_maxpool[C];
__device__ float g_W1f[CIN * C],  g_b1f[C];
__device__ float g_W2af[CIN * C2], g_b2af[C2];
__device__ float g_W2bf[C2 * C],  g_b2bf[C];
// packed per-lane MMA B-fragments as uint4: {hi_b0, hi_b1, lo_b0, lo_b1}
__device__ uint32_t g_fragA[16 * 32 * 4];          // W2a: [(nt*32+lane)*4 + v*2 + r]
__device__ uint32_t g_fragB[8 * 8 * 32 * 4];       // W2b: [((kb*8+nt)*32+lane)*4 + v*2 + r]

// ---------------- combo: zero output/counters + fold BN into weights ----------------
__global__ void combo_kernel(float* __restrict__ out, int n_out,
                             const float* __restrict__ W1,
                             const float* __restrict__ g1, const float* __restrict__ b1,
                             const float* __restrict__ m1, const float* __restrict__ v1,
                             const float* __restrict__ W2a,
                             const float* __restrict__ g2a, const float* __restrict__ b2a,
                             const float* __restrict__ m2a, const float* __restrict__ v2a,
                             const float* __restrict__ W2b,
                             const float* __restrict__ g2b, const float* __restrict__ b2b,
                             const float* __restrict__ m2b, const float* __restrict__ v2b)
{
    int i = blockIdx.x * blockDim.x + threadIdx.x;
    if (i < n_out) out[i] = 0.0f;
    if (i < S_SEG) g_hist[i] = 0;
    if (i < C)     g_maxpool[i] = 0;

    const int n1 = CIN * C;          // 1024
    const int n2 = n1 + CIN * C2;    // 3072
    const int n3 = n2 + C2 * C;      // 11264
    if (i < n1) {
        int c = i & (C - 1);
        g_W1f[i] = W1[i] * (g1[c] / sqrtf(v1[c] + EPS_BN));
    } else if (i < n2) {
        int j = i - n1; int c = j & (C2 - 1);
        g_W2af[j] = W2a[j] * (g2a[c] / sqrtf(v2a[c] + EPS_BN));
    } else if (i < n3) {
        int j = i - n2; int c = j & (C - 1);
        g_W2bf[j] = W2b[j] * (g2b[c] / sqrtf(v2b[c] + EPS_BN));
    } else if (i < n3 + C + C2 + C) {
        int j = i - n3;
        if (j < C) {
            g_b1f[j] = b1[j] - m1[j] * (g1[j] / sqrtf(v1[j] + EPS_BN));
        } else if (j < C + C2) {
            int c = j - C;
            g_b2af[c] = b2a[c] - m2a[c] * (g2a[c] / sqrtf(v2a[c] + EPS_BN));
        } else {
            int c = j - C - C2;
            g_b2bf[c] = b2b[c] - m2b[c] * (g2b[c] / sqrtf(v2b[c] + EPS_BN));
        }
    }
}

// ---------------- prep2: build per-lane hi/lo weight fragments (uint4 packed) ----------------
// m16n8k16 B fragment (col): b_r holds {B[k0][n], B[k0+1][n]},
//   lane: g=lane>>2, t=lane&3;  n = nt*8+g;  k0 = 2t + (r ? 8 : 0)
__global__ void prep2_kernel()
{
    int i = blockIdx.x * blockDim.x + threadIdx.x;
    if (i < 2048) {
        // W2a fragments: word i = (nt*32+lane)*4 + v*2 + r
        int nt = i >> 7, lane = (i >> 2) & 31, v = (i >> 1) & 1, r = i & 1;
        int g = lane >> 2, t = lane & 3;
        int n = nt * 8 + g;
        int k0 = 2 * t + (r ? 8 : 0);
        float w0 = g_W2af[k0 * C2 + n];
        float w1 = g_W2af[(k0 + 1) * C2 + n];
        uint32_t hi, lo;
        split_bf16x2(w0, w1, hi, lo);
        g_fragA[i] = v ? lo : hi;
    } else if (i < 2048 + 8192) {
        // W2b fragments: word j = ((kb*8+nt)*32+lane)*4 + v*2 + r
        int j = i - 2048;
        int kb = j >> 10, nt = (j >> 7) & 7, lane = (j >> 2) & 31, v = (j >> 1) & 1, r = j & 1;
        int g = lane >> 2, t = lane & 3;
        int n = nt * 8 + g;
        int k = kb * 16 + 2 * t + (r ? 8 : 0);
        float w0 = g_W2bf[k * C + n];
        float w1 = g_W2bf[(k + 1) * C + n];
        uint32_t hi, lo;
        split_bf16x2(w0, w1, hi, lo);
        g_fragB[j] = v ? lo : hi;
    }
}

// ---------------- counting sort ----------------
__global__ void hist_kernel(const int* __restrict__ unq, int N)
{
    int i = blockIdx.x * blockDim.x + threadIdx.x;
    if (i < N) atomicAdd(&g_hist[unq[i]], 1);
}

// single-pass parallel scan: 1024 threads x 20 sequential elements
__global__ void scan_kernel()
{
    __shared__ int wsum[32];
    int tid = threadIdx.x;
    int t0 = tid * 20;
    int v[20];
    int s = 0;
    #pragma unroll
    for (int j = 0; j < 20; j++) {
        int idx = t0 + j;
        int x = (idx < S_SEG) ? g_hist[idx] : 0;
        v[j] = x; s += x;
    }
    int x = s;
    #pragma unroll
    for (int d = 1; d < 32; d <<= 1) {
        int y = __shfl_up_sync(0xffffffffu, x, d);
        if ((tid & 31) >= d) x += y;
    }
    if ((tid & 31) == 31) wsum[tid >> 5] = x;
    __syncthreads();
    if (tid < 32) {
        int t = wsum[tid];
        #pragma unroll
        for (int d = 1; d < 32; d <<= 1) {
            int y = __shfl_up_sync(0xffffffffu, t, d);
            if (tid >= d) t += y;
        }
        wsum[tid] = t;
    }
    __syncthreads();
    int incl = x + ((tid >= 32) ? wsum[(tid >> 5) - 1] : 0);
    int run = incl - s;
    #pragma unroll
    for (int j = 0; j < 20; j++) {
        int idx = t0 + j;
        if (idx < S_SEG) { g_cursor[idx] = run; run += v[j]; }
    }
}

__global__ void scatter_kernel(const int* __restrict__ unq, int N)
{
    int i = blockIdx.x * blockDim.x + threadIdx.x;
    if (i < N) {
        int s = unq[i];
        int pos = atomicAdd(&g_cursor[s], 1);
        g_order[pos] = i;
        g_seg_sorted[pos] = s;
    }
}

// ================= branch2 (mma.sync bf16 split-precision, pipelined) =================
// Persistent, grid=148, 256 thr (8 warps); warp w owns rows w*16+g, w*16+g+8.
// smem floats:
//   s_a[2][2048] @0 | s_fa 2048 u32 @4096 | s_fb 8192 u32 @6144 |
//   s_b2a 128 @14336 | s_b2b 64 @14464 | s_pool 64 ints @14528 => 14592 fl = 58,368 B
#define B2_SMEM_FLOATS 14592

__global__ void __launch_bounds__(NTHR, 1)
branch2_kernel(const float* __restrict__ inputs, int N, int ntiles)
{
    extern __shared__ float sm[];
    float*    s_a0  = sm;
    float*    s_a1  = sm + 2048;
    uint32_t* s_fa  = (uint32_t*)(sm + 4096);
    uint32_t* s_fb  = (uint32_t*)(sm + 6144);
    float*    s_b2a = sm + 14336;
    float*    s_b2b = sm + 14464;
    int*      s_pool= (int*)(sm + 14528);

    int tid = threadIdx.x;
    int w   = tid >> 5;
    int lane= tid & 31;
    int t   = lane & 3;
    int g   = lane >> 2;
    (void)g;

    // load weight fragments + biases into smem
    for (int i = tid; i < 2048; i += NTHR) s_fa[i] = g_fragA[i];
    for (int i = tid; i < 8192; i += NTHR) s_fb[i] = g_fragB[i];
    if (tid < C2) s_b2a[tid] = g_b2af[tid];
    if (tid < C)  s_b2b[tid] = g_b2bf[tid];
    if (tid < C)  s_pool[tid] = 0;

    const int r0 = w * 16 + (lane >> 2);   // logical tile rows for this lane
    const int r1 = r0 + 8;

    float pm[16];
    #pragma unroll
    for (int j = 0; j < 16; j++) pm[j] = 0.f;

    // stage first tile into buffer 0
    int tI = blockIdx.x;
    if (tI < ntiles) {
        int base = tI * TILE;
        int np = N - base; if (np > TILE) np = TILE;
        #pragma unroll
        for (int q = 0; q < 2; q++) {
            int idx = tid + q * NTHR;
            int pt = idx >> 2, f = idx & 3;
            float4 v = make_float4(0.f, 0.f, 0.f, 0.f);
            if (pt < np) v = reinterpret_cast<const float4*>(inputs)[(size_t)(base + pt) * 4 + f];
            reinterpret_cast<float4*>(s_a0)[pt * 4 + f] = v;
        }
    }
    __syncthreads();

    int buf = 0;
    for (; tI < ntiles; ) {
        int base = tI * TILE;
        int np = N - base; if (np > TILE) np = TILE;
        float* s_a = buf ? s_a1 : s_a0;
        float* s_n = buf ? s_a0 : s_a1;

        // prefetch next tile (LDG issued early, lands in regs)
        int tNext = tI + gridDim.x;
        bool hasNext = tNext < ntiles;
        float4 pv[2];
        int npN = 0;
        if (hasNext) {
            int baseN = tNext * TILE;
            npN = N - baseN; if (npN > TILE) npN = TILE;
            #pragma unroll
            for (int q = 0; q < 2; q++) {
                int idx = tid + q * NTHR;
                int pt = idx >> 2, f = idx & 3;
                pv[q] = make_float4(0.f, 0.f, 0.f, 0.f);
                if (pt < npN) pv[q] = reinterpret_cast<const float4*>(inputs)[(size_t)(baseN + pt) * 4 + f];
            }
        }

        // ---- A1 fragments (hi/lo) from staged tile ----
        uint32_t a1h[4], a1l[4];
        {
            float2 p0 = *reinterpret_cast<float2*>(&s_a[r0 * 16 + 2 * t]);
            float2 p1 = *reinterpret_cast<float2*>(&s_a[r1 * 16 + 2 * t]);
            float2 p2 = *reinterpret_cast<float2*>(&s_a[r0 * 16 + 2 * t + 8]);
            float2 p3 = *reinterpret_cast<float2*>(&s_a[r1 * 16 + 2 * t + 8]);
            split_bf16x2(p0.x, p0.y, a1h[0], a1l[0]);
            split_bf16x2(p1.x, p1.y, a1h[1], a1l[1]);
            split_bf16x2(p2.x, p2.y, a1h[2], a1l[2]);
            split_bf16x2(p3.x, p3.y, a1h[3], a1l[3]);
        }

        float d2[32];
        #pragma unroll
        for (int j = 0; j < 32; j++) d2[j] = 0.f;

        // ---- two phases over h-channels (64 each) ----
        #pragma unroll
        for (int phx = 0; phx < 2; phx++) {
            // GEMM2a: pass-separated, 4 independent accumulators between deps
            float d1[32];
            #pragma unroll
            for (int j = 0; j < 32; j++) d1[j] = 0.f;
            #pragma unroll
            for (int h4 = 0; h4 < 2; h4++) {
                uint4 f[4];
                #pragma unroll
                for (int q = 0; q < 4; q++)
                    f[q] = *reinterpret_cast<uint4*>(&s_fa[((phx * 8 + h4 * 4 + q) * 32 + lane) * 4]);
                #pragma unroll
                for (int q = 0; q < 4; q++) MMA_BF16(&d1[(h4 * 4 + q) * 4], a1h, f[q].x, f[q].y);
                #pragma unroll
                for (int q = 0; q < 4; q++) MMA_BF16(&d1[(h4 * 4 + q) * 4], a1h, f[q].z, f[q].w);
                #pragma unroll
                for (int q = 0; q < 4; q++) MMA_BF16(&d1[(h4 * 4 + q) * 4], a1l, f[q].x, f[q].y);
            }
            // epi1: bias + relu + split -> A2 fragments (register-only, D->A identity)
            uint32_t a2h[16], a2l[16];
            #pragma unroll
            for (int nt8 = 0; nt8 < 8; nt8++) {
                int nt = phx * 8 + nt8;
                float2 bi = *reinterpret_cast<float2*>(&s_b2a[nt * 8 + 2 * t]);
                float h0 = fmaxf(d1[nt8 * 4 + 0] + bi.x, 0.f);
                float h1 = fmaxf(d1[nt8 * 4 + 1] + bi.y, 0.f);
                float h2 = fmaxf(d1[nt8 * 4 + 2] + bi.x, 0.f);
                float h3 = fmaxf(d1[nt8 * 4 + 3] + bi.y, 0.f);
                int kbl = nt8 >> 1, half = nt8 & 1;
                int s0 = kbl * 4 + half * 2;
                split_bf16x2(h0, h1, a2h[s0],     a2l[s0]);
                split_bf16x2(h2, h3, a2h[s0 + 1], a2l[s0 + 1]);
            }
            // GEMM2b partial: pass-separated per kblock
            #pragma unroll
            for (int kbl = 0; kbl < 4; kbl++) {
                int kb = phx * 4 + kbl;
                #pragma unroll
                for (int h4 = 0; h4 < 2; h4++) {
                    uint4 f[4];
                    #pragma unroll
                    for (int q = 0; q < 4; q++)
                        f[q] = *reinterpret_cast<uint4*>(&s_fb[((kb * 8 + h4 * 4 + q) * 32 + lane) * 4]);
                    #pragma unroll
                    for (int q = 0; q < 4; q++) MMA_BF16(&d2[(h4 * 4 + q) * 4], &a2h[kbl * 4], f[q].x, f[q].y);
                    #pragma unroll
                    for (int q = 0; q < 4; q++) MMA_BF16(&d2[(h4 * 4 + q) * 4], &a2h[kbl * 4], f[q].z, f[q].w);
                    #pragma unroll
                    for (int q = 0; q < 4; q++) MMA_BF16(&d2[(h4 * 4 + q) * 4], &a2l[kbl * 4], f[q].x, f[q].y);
                }
            }
        }

        // ---- epi2: bias + relu + masked max pool ----
        {
            bool v0 = r0 < np;
            bool v1 = r1 < np;
            #pragma unroll
            for (int nt = 0; nt < 8; nt++) {
                float2 bi = *reinterpret_cast<float2*>(&s_b2b[nt * 8 + 2 * t]);
                float x0 = fmaxf(d2[nt * 4 + 0] + bi.x, 0.f);
                float x1 = fmaxf(d2[nt * 4 + 1] + bi.y, 0.f);
                float x2 = fmaxf(d2[nt * 4 + 2] + bi.x, 0.f);
                float x3 = fmaxf(d2[nt * 4 + 3] + bi.y, 0.f);
                if (v0) { pm[nt * 2 + 0] = fmaxf(pm[nt * 2 + 0], x0); pm[nt * 2 + 1] = fmaxf(pm[nt * 2 + 1], x1); }
                if (v1) { pm[nt * 2 + 0] = fmaxf(pm[nt * 2 + 0], x2); pm[nt * 2 + 1] = fmaxf(pm[nt * 2 + 1], x3); }
            }
        }

        // ---- write prefetched tile into the other buffer ----
        if (hasNext) {
            #pragma unroll
            for (int q = 0; q < 2; q++) {
                int idx = tid + q * NTHR;
                int pt = idx >> 2, f = idx & 3;
                reinterpret_cast<float4*>(s_n)[pt * 4 + f] = pv[q];
            }
        }
        __syncthreads();
        buf ^= 1;
        tI = tNext;
    }

    #pragma unroll
    for (int nt = 0; nt < 8; nt++) {
        atomicMax(&s_pool[nt * 8 + 2 * t + 0], __float_as_int(pm[nt * 2 + 0]));
        atomicMax(&s_pool[nt * 8 + 2 * t + 1], __float_as_int(pm[nt * 2 + 1]));
    }
    __syncthreads();
    if (tid < C) atomicMax(&g_maxpool[tid], s_pool[tid]);
}

// ================= branch1: GEMM1 + segmented sum/max over sorted points =================
#define B1_SMEM_FLOATS 11584

__global__ void __launch_bounds__(NTHR, 3)
branch1_kernel(const float* __restrict__ inputs, float* __restrict__ out, int N)
{
    extern __shared__ float sm[];
    float* s_inT = sm;                 // [16][128]
    float* s_x   = sm + 2048;          // [128][64]
    float* s_w1  = sm + 10240;         // [16][64]
    float* s_b1  = sm + 11264;
    int*   s_seg = (int*)(sm + 11328);
    int*   s_idx = (int*)(sm + 11456);

    int tid  = threadIdx.x;
    int base = blockIdx.x * TILE;
    int np   = N - base; if (np > TILE) np = TILE;

    for (int i = tid; i < CIN * C; i += NTHR) s_w1[i] = g_W1f[i];
    if (tid < C) s_b1[tid] = g_b1f[tid];
    if (tid < TILE) {
        int seg = -1, idx = 0;
        if (tid < np) { idx = g_order[base + tid]; seg = g_seg_sorted[base + tid]; }
        s_idx[tid] = idx;
        s_seg[tid] = seg;
    }
    __syncthreads();

    #pragma unroll
    for (int q = 0; q < 2; q++) {
        int e  = tid + q * NTHR;
        int pt = e >> 2, f = e & 3;
        float4 v = make_float4(0.f, 0.f, 0.f, 0.f);
        if (pt < np) v = reinterpret_cast<const float4*>(inputs)[(size_t)s_idx[pt] * 4 + f];
        s_inT[(f * 4 + 0) * TILE + pt] = v.x;
        s_inT[(f * 4 + 1) * TILE + pt] = v.y;
        s_inT[(f * 4 + 2) * TILE + pt] = v.z;
        s_inT[(f * 4 + 3) * TILE + pt] = v.w;
    }
    __syncthreads();

    int tg = tid & 7;
    int tp = tid >> 3;

    {
        ull acc[2][8];
        #pragma unroll
        for (int i = 0; i < 2; i++)
            #pragma unroll
            for (int j = 0; j < 8; j++) acc[i][j] = 0ull;
        #pragma unroll
        for (int k = 0; k < CIN; k++) {
            ulonglong2 A = *reinterpret_cast<const ulonglong2*>(&s_inT[k * TILE + tp * 4]);
            float4 b0 = *reinterpret_cast<float4*>(&s_w1[k * C + tg * 4]);
            float4 b1 = *reinterpret_cast<float4*>(&s_w1[k * C + 32 + tg * 4]);
            ull bb[8];
            PACK2(bb[0], b0.x); PACK2(bb[1], b0.y); PACK2(bb[2], b0.z); PACK2(bb[3], b0.w);
            PACK2(bb[4], b1.x); PACK2(bb[5], b1.y); PACK2(bb[6], b1.z); PACK2(bb[7], b1.w);
            #pragma unroll
            for (int j = 0; j < 8; j++) { FFMA2(acc[0][j], A.x, bb[j]); FFMA2(acc[1][j], A.y, bb[j]); }
        }
        #pragma unroll
        for (int j = 0; j < 8; j++) {
            int cj = (j >> 2) * 32 + tg * 4 + (j & 3);
            float bias = s_b1[cj];
            float l0, h0, l1, h1;
            UNPACK2(l0, h0, acc[0][j]);
            UNPACK2(l1, h1, acc[1][j]);
            s_x[(tp * 4 + 0) * C + cj] = fmaxf(l0 + bias, 0.f);
            s_x[(tp * 4 + 1) * C + cj] = fmaxf(h0 + bias, 0.f);
            s_x[(tp * 4 + 2) * C + cj] = fmaxf(l1 + bias, 0.f);
            s_x[(tp * 4 + 3) * C + cj] = fmaxf(h1 + bias, 0.f);
        }
    }
    __syncthreads();

    {
        int c = tid & 63;
        int q = tid >> 6;
        int p0 = q * 32;
        int p1 = p0 + 32; if (p1 > np) p1 = np;
        if (p0 < np) {
            int   cs = s_seg[p0];
            float rs = 0.f, rm = 0.f;
            for (int p = p0; p < p1; p++) {
                int   sg = s_seg[p];
                float v  = s_x[p * C + c];
                if (sg != cs) {
                    atomicAdd(&out[cs * 192 + c * 3], rs);
                    atomicMax((int*)&out[cs * 192 + c * 3 + 1], __float_as_int(rm));
                    rs = 0.f; rm = 0.f; cs = sg;
                }
                rs += v; rm = fmaxf(rm, v);
            }
            atomicAdd(&out[cs * 192 + c * 3], rs);
            atomicMax((int*)&out[cs * 192 + c * 3 + 1], __float_as_int(rm));
        }
    }
}

// ---------------- broadcast global max pool into shuffled output layout ----------------
__global__ void bcast_kernel(float* __restrict__ out)
{
    int i = blockIdx.x * blockDim.x + threadIdx.x;
    if (i < S_SEG * C) {
        int s = i / C, c = i % C;
        out[s * 192 + c * 3 + 2] = __int_as_float(g_maxpool[c]);
    }
}

// ---------------- launch ----------------
extern "C" void kernel_launch(void* const* d_in, const int* in_sizes, int n_in,
                              void* d_out, int out_size)
{
    const float* inputs = (const float*)d_in[0];
    const int*   unq    = (const int*)  d_in[1];
    const float* W1  = (const float*)d_in[3];
    const float* g1  = (const float*)d_in[4];
    const float* b1  = (const float*)d_in[5];
    const float* m1  = (const float*)d_in[6];
    const float* v1  = (const float*)d_in[7];
    const float* W2a = (const float*)d_in[8];
    const float* g2a = (const float*)d_in[9];
    const float* b2a = (const float*)d_in[10];
    const float* m2a = (const float*)d_in[11];
    const float* v2a = (const float*)d_in[12];
    const float* W2b = (const float*)d_in[13];
    const float* g2b = (const float*)d_in[14];
    const float* b2b = (const float*)d_in[15];
    const float* m2b = (const float*)d_in[16];
    const float* v2b = (const float*)d_in[17];
    float* out = (float*)d_out;

    int N = in_sizes[0] / CIN;
    int ntiles = (N + TILE - 1) / TILE;

    cudaFuncSetAttribute(branch2_kernel,
                         cudaFuncAttributeMaxDynamicSharedMemorySize, B2_SMEM_FLOATS * 4);

    combo_kernel<<<(out_size + 255) / 256, 256>>>(out, out_size,
                             W1, g1, b1, m1, v1,
                             W2a, g2a, b2a, m2a, v2a,
                             W2b, g2b, b2b, m2b, v2b);
    prep2_kernel<<<40, 256>>>();
    hist_kernel<<<(N + 255) / 256, 256>>>(unq, N);
    branch2_kernel<<<148, NTHR, B2_SMEM_FLOATS * 4>>>(inputs, N, ntiles);
    scan_kernel<<<1, 1024>>>();
    scatter_kernel<<<(N + 255) / 256, 256>>>(unq, N);
    branch1_kernel<<<ntiles, NTHR, B1_SMEM_FLOATS * 4>>>(inputs, out, N);
    bcast_kernel<<<(S_SEG * C + 255) / 256, 256>>>(out);
}

// round 10
// speedup vs baseline: 3.6930x; 1.0322x over previous
#include <cuda_runtime.h>
#include <cuda_bf16.h>
#include <cstdint>

// Problem constants (fixed by setup_inputs: N=1e6, Cin=16, C=64, S=20000)
#define NMAX   1000000
#define S_SEG  20000
#define CIN    16
#define C      64
#define C2     128
#define TILE   128
#define NTHR   256
#define EPS_BN 1e-3f

typedef unsigned long long ull;

// packed f32x2 helpers (branch1)
#define FFMA2(d, a, b) asm("fma.rn.f32x2 %0, %1, %2, %0;" : "+l"(d) : "l"(a), "l"(b))
#define PACK2(d, x)    asm("mov.b64 %0, {%1, %1};" : "=l"(d) : "f"(x))
#define UNPACK2(lo, hi, d) asm("mov.b64 {%0, %1}, %2;" : "=f"(lo), "=f"(hi) : "l"(d))

// bf16x2 pack: low half <- x (smaller col), high half <- y
__device__ __forceinline__ uint32_t pack_bf16x2(float x, float y) {
    uint32_t r;
    asm("cvt.rn.bf16x2.f32 %0, %1, %2;" : "=r"(r) : "f"(y), "f"(x));
    return r;
}
// split (x,y) into hi bf16x2 and lo bf16x2 (residual)
__device__ __forceinline__ void split_bf16x2(float x, float y, uint32_t& hi, uint32_t& lo) {
    hi = pack_bf16x2(x, y);
    float hx = __uint_as_float(hi << 16);
    float hy = __uint_as_float(hi & 0xffff0000u);
    lo = pack_bf16x2(x - hx, y - hy);
}

// m16n8k16 bf16 MMA, fp32 accumulate (baseline PTX, compiles for compute_100)
#define MMA_BF16(d, a, b0, b1) \
    asm volatile("mma.sync.aligned.m16n8k16.row.col.f32.bf16.bf16.f32 " \
        "{%0,%1,%2,%3}, {%4,%5,%6,%7}, {%8,%9}, {%0,%1,%2,%3};" \
        : "+f"((d)[0]), "+f"((d)[1]), "+f"((d)[2]), "+f"((d)[3]) \
        : "r"((a)[0]), "r"((a)[1]), "r"((a)[2]), "r"((a)[3]), "r"(b0), "r"(b1))

// ---------------- device scratch ----------------
__device__ int   g_hist[S_SEG];
__device__ int   g_cursor[S_SEG];
__device__ int   g_order[NMAX];
__device__ int   g_seg_sorted[NMAX];
__device__ int   g_maxpool[C];
__device__ float g_W1f[CIN * C],  g_b1f[C];
__device__ float g_W2af[CIN * C2], g_b2af[C2];
__device__ float g_W2bf[C2 * C],  g_b2bf[C];
// packed per-lane MMA B-fragments as uint4: {hi_b0, hi_b1, lo_b0, lo_b1}
__device__ uint32_t g_fragA[16 * 32 * 4];          // W2a: [(nt*32+lane)*4 + v*2 + r]
__device__ uint32_t g_fragB[8 * 8 * 32 * 4];       // W2b: [((kb*8+nt)*32+lane)*4 + v*2 + r]

// ---------------- combo: zero output/counters + fold BN into weights ----------------
__global__ void combo_kernel(float* __restrict__ out, int n_out,
                             const float* __restrict__ W1,
                             const float* __restrict__ g1, const float* __restrict__ b1,
                             const float* __restrict__ m1, const float* __restrict__ v1,
                             const float* __restrict__ W2a,
                             const float* __restrict__ g2a, const float* __restrict__ b2a,
                             const float* __restrict__ m2a, const float* __restrict__ v2a,
                             const float* __restrict__ W2b,
                             const float* __restrict__ g2b, const float* __restrict__ b2b,
                             const float* __restrict__ m2b, const float* __restrict__ v2b)
{
    int i = blockIdx.x * blockDim.x + threadIdx.x;
    if (i < n_out) out[i] = 0.0f;
    if (i < S_SEG) g_hist[i] = 0;
    if (i < C)     g_maxpool[i] = 0;

    const int n1 = CIN * C;          // 1024
    const int n2 = n1 + CIN * C2;    // 3072
    const int n3 = n2 + C2 * C;      // 11264
    if (i < n1) {
        int c = i & (C - 1);
        g_W1f[i] = W1[i] * (g1[c] / sqrtf(v1[c] + EPS_BN));
    } else if (i < n2) {
        int j = i - n1; int c = j & (C2 - 1);
        g_W2af[j] = W2a[j] * (g2a[c] / sqrtf(v2a[c] + EPS_BN));
    } else if (i < n3) {
        int j = i - n2; int c = j & (C - 1);
        g_W2bf[j] = W2b[j] * (g2b[c] / sqrtf(v2b[c] + EPS_BN));
    } else if (i < n3 + C + C2 + C) {
        int j = i - n3;
        if (j < C) {
            g_b1f[j] = b1[j] - m1[j] * (g1[j] / sqrtf(v1[j] + EPS_BN));
        } else if (j < C + C2) {
            int c = j - C;
            g_b2af[c] = b2a[c] - m2a[c] * (g2a[c] / sqrtf(v2a[c] + EPS_BN));
        } else {
            int c = j - C - C2;
            g_b2bf[c] = b2b[c] - m2b[c] * (g2b[c] / sqrtf(v2b[c] + EPS_BN));
        }
    }
}

// ---------------- prep2: build per-lane hi/lo weight fragments (uint4 packed) ----------------
__global__ void prep2_kernel()
{
    int i = blockIdx.x * blockDim.x + threadIdx.x;
    if (i < 2048) {
        int nt = i >> 7, lane = (i >> 2) & 31, v = (i >> 1) & 1, r = i & 1;
        int g = lane >> 2, t = lane & 3;
        int n = nt * 8 + g;
        int k0 = 2 * t + (r ? 8 : 0);
        float w0 = g_W2af[k0 * C2 + n];
        float w1 = g_W2af[(k0 + 1) * C2 + n];
        uint32_t hi, lo;
        split_bf16x2(w0, w1, hi, lo);
        g_fragA[i] = v ? lo : hi;
    } else if (i < 2048 + 8192) {
        int j = i - 2048;
        int kb = j >> 10, nt = (j >> 7) & 7, lane = (j >> 2) & 31, v = (j >> 1) & 1, r = j & 1;
        int g = lane >> 2, t = lane & 3;
        int n = nt * 8 + g;
        int k = kb * 16 + 2 * t + (r ? 8 : 0);
        float w0 = g_W2bf[k * C + n];
        float w1 = g_W2bf[(k + 1) * C + n];
        uint32_t hi, lo;
        split_bf16x2(w0, w1, hi, lo);
        g_fragB[j] = v ? lo : hi;
    }
}

// ---------------- counting sort ----------------
__global__ void hist_kernel(const int* __restrict__ unq, int N)
{
    int i = blockIdx.x * blockDim.x + threadIdx.x;
    if (i < N) atomicAdd(&g_hist[unq[i]], 1);
}

// single-pass parallel scan: 1024 threads x 20 sequential elements
__global__ void scan_kernel()
{
    __shared__ int wsum[32];
    int tid = threadIdx.x;
    int t0 = tid * 20;
    int v[20];
    int s = 0;
    #pragma unroll
    for (int j = 0; j < 20; j++) {
        int idx = t0 + j;
        int x = (idx < S_SEG) ? g_hist[idx] : 0;
        v[j] = x; s += x;
    }
    int x = s;
    #pragma unroll
    for (int d = 1; d < 32; d <<= 1) {
        int y = __shfl_up_sync(0xffffffffu, x, d);
        if ((tid & 31) >= d) x += y;
    }
    if ((tid & 31) == 31) wsum[tid >> 5] = x;
    __syncthreads();
    if (tid < 32) {
        int t = wsum[tid];
        #pragma unroll
        for (int d = 1; d < 32; d <<= 1) {
            int y = __shfl_up_sync(0xffffffffu, t, d);
            if (tid >= d) t += y;
        }
        wsum[tid] = t;
    }
    __syncthreads();
    int incl = x + ((tid >= 32) ? wsum[(tid >> 5) - 1] : 0);
    int run = incl - s;
    #pragma unroll
    for (int j = 0; j < 20; j++) {
        int idx = t0 + j;
        if (idx < S_SEG) { g_cursor[idx] = run; run += v[j]; }
    }
}

__global__ void scatter_kernel(const int* __restrict__ unq, int N)
{
    int i = blockIdx.x * blockDim.x + threadIdx.x;
    if (i < N) {
        int s = unq[i];
        int pos = atomicAdd(&g_cursor[s], 1);
        g_order[pos] = i;
        g_seg_sorted[pos] = s;
    }
}

// ================= branch2 (mma.sync bf16 split-precision, pipelined) =================
#define B2_SMEM_FLOATS 14592

__global__ void __launch_bounds__(NTHR, 1)
branch2_kernel(const float* __restrict__ inputs, int N, int ntiles)
{
    extern __shared__ float sm[];
    float*    s_a0  = sm;
    float*    s_a1  = sm + 2048;
    uint32_t* s_fa  = (uint32_t*)(sm + 4096);
    uint32_t* s_fb  = (uint32_t*)(sm + 6144);
    float*    s_b2a = sm + 14336;
    float*    s_b2b = sm + 14464;
    int*      s_pool= (int*)(sm + 14528);

    int tid = threadIdx.x;
    int w   = tid >> 5;
    int lane= tid & 31;
    int t   = lane & 3;

    for (int i = tid; i < 2048; i += NTHR) s_fa[i] = g_fragA[i];
    for (int i = tid; i < 8192; i += NTHR) s_fb[i] = g_fragB[i];
    if (tid < C2) s_b2a[tid] = g_b2af[tid];
    if (tid < C)  s_b2b[tid] = g_b2bf[tid];
    if (tid < C)  s_pool[tid] = 0;

    const int r0 = w * 16 + (lane >> 2);
    const int r1 = r0 + 8;

    float pm[16];
    #pragma unroll
    for (int j = 0; j < 16; j++) pm[j] = 0.f;

    int tI = blockIdx.x;
    if (tI < ntiles) {
        int base = tI * TILE;
        int np = N - base; if (np > TILE) np = TILE;
        #pragma unroll
        for (int q = 0; q < 2; q++) {
            int idx = tid + q * NTHR;
            int pt = idx >> 2, f = idx & 3;
            float4 v = make_float4(0.f, 0.f, 0.f, 0.f);
            if (pt < np) v = reinterpret_cast<const float4*>(inputs)[(size_t)(base + pt) * 4 + f];
            reinterpret_cast<float4*>(s_a0)[pt * 4 + f] = v;
        }
    }
    __syncthreads();

    int buf = 0;
    for (; tI < ntiles; ) {
        int base = tI * TILE;
        int np = N - base; if (np > TILE) np = TILE;
        float* s_a = buf ? s_a1 : s_a0;
        float* s_n = buf ? s_a0 : s_a1;

        int tNext = tI + gridDim.x;
        bool hasNext = tNext < ntiles;
        float4 pv[2];
        int npN = 0;
        if (hasNext) {
            int baseN = tNext * TILE;
            npN = N - baseN; if (npN > TILE) npN = TILE;
            #pragma unroll
            for (int q = 0; q < 2; q++) {
                int idx = tid + q * NTHR;
                int pt = idx >> 2, f = idx & 3;
                pv[q] = make_float4(0.f, 0.f, 0.f, 0.f);
                if (pt < npN) pv[q] = reinterpret_cast<const float4*>(inputs)[(size_t)(baseN + pt) * 4 + f];
            }
        }

        uint32_t a1h[4], a1l[4];
        {
            float2 p0 = *reinterpret_cast<float2*>(&s_a[r0 * 16 + 2 * t]);
            float2 p1 = *reinterpret_cast<float2*>(&s_a[r1 * 16 + 2 * t]);
            float2 p2 = *reinterpret_cast<float2*>(&s_a[r0 * 16 + 2 * t + 8]);
            float2 p3 = *reinterpret_cast<float2*>(&s_a[r1 * 16 + 2 * t + 8]);
            split_bf16x2(p0.x, p0.y, a1h[0], a1l[0]);
            split_bf16x2(p1.x, p1.y, a1h[1], a1l[1]);
            split_bf16x2(p2.x, p2.y, a1h[2], a1l[2]);
            split_bf16x2(p3.x, p3.y, a1h[3], a1l[3]);
        }

        float d2[32];
        #pragma unroll
        for (int j = 0; j < 32; j++) d2[j] = 0.f;

        #pragma unroll
        for (int phx = 0; phx < 2; phx++) {
            float d1[32];
            #pragma unroll
            for (int j = 0; j < 32; j++) d1[j] = 0.f;
            #pragma unroll
            for (int h4 = 0; h4 < 2; h4++) {
                uint4 f[4];
                #pragma unroll
                for (int q = 0; q < 4; q++)
                    f[q] = *reinterpret_cast<uint4*>(&s_fa[((phx * 8 + h4 * 4 + q) * 32 + lane) * 4]);
                #pragma unroll
                for (int q = 0; q < 4; q++) MMA_BF16(&d1[(h4 * 4 + q) * 4], a1h, f[q].x, f[q].y);
                #pragma unroll
                for (int q = 0; q < 4; q++) MMA_BF16(&d1[(h4 * 4 + q) * 4], a1h, f[q].z, f[q].w);
                #pragma unroll
                for (int q = 0; q < 4; q++) MMA_BF16(&d1[(h4 * 4 + q) * 4], a1l, f[q].x, f[q].y);
            }
            uint32_t a2h[16], a2l[16];
            #pragma unroll
            for (int nt8 = 0; nt8 < 8; nt8++) {
                int nt = phx * 8 + nt8;
                float2 bi = *reinterpret_cast<float2*>(&s_b2a[nt * 8 + 2 * t]);
                float h0 = fmaxf(d1[nt8 * 4 + 0] + bi.x, 0.f);
                float h1 = fmaxf(d1[nt8 * 4 + 1] + bi.y, 0.f);
                float h2 = fmaxf(d1[nt8 * 4 + 2] + bi.x, 0.f);
                float h3 = fmaxf(d1[nt8 * 4 + 3] + bi.y, 0.f);
                int kbl = nt8 >> 1, half = nt8 & 1;
                int s0 = kbl * 4 + half * 2;
                split_bf16x2(h0, h1, a2h[s0],     a2l[s0]);
                split_bf16x2(h2, h3, a2h[s0 + 1], a2l[s0 + 1]);
            }
            #pragma unroll
            for (int kbl = 0; kbl < 4; kbl++) {
                int kb = phx * 4 + kbl;
                #pragma unroll
                for (int h4 = 0; h4 < 2; h4++) {
                    uint4 f[4];
                    #pragma unroll
                    for (int q = 0; q < 4; q++)
                        f[q] = *reinterpret_cast<uint4*>(&s_fb[((kb * 8 + h4 * 4 + q) * 32 + lane) * 4]);
                    #pragma unroll
                    for (int q = 0; q < 4; q++) MMA_BF16(&d2[(h4 * 4 + q) * 4], &a2h[kbl * 4], f[q].x, f[q].y);
                    #pragma unroll
                    for (int q = 0; q < 4; q++) MMA_BF16(&d2[(h4 * 4 + q) * 4], &a2h[kbl * 4], f[q].z, f[q].w);
                    #pragma unroll
                    for (int q = 0; q < 4; q++) MMA_BF16(&d2[(h4 * 4 + q) * 4], &a2l[kbl * 4], f[q].x, f[q].y);
                }
            }
        }

        {
            bool v0 = r0 < np;
            bool v1 = r1 < np;
            #pragma unroll
            for (int nt = 0; nt < 8; nt++) {
                float2 bi = *reinterpret_cast<float2*>(&s_b2b[nt * 8 + 2 * t]);
                float x0 = fmaxf(d2[nt * 4 + 0] + bi.x, 0.f);
                float x1 = fmaxf(d2[nt * 4 + 1] + bi.y, 0.f);
                float x2 = fmaxf(d2[nt * 4 + 2] + bi.x, 0.f);
                float x3 = fmaxf(d2[nt * 4 + 3] + bi.y, 0.f);
                if (v0) { pm[nt * 2 + 0] = fmaxf(pm[nt * 2 + 0], x0); pm[nt * 2 + 1] = fmaxf(pm[nt * 2 + 1], x1); }
                if (v1) { pm[nt * 2 + 0] = fmaxf(pm[nt * 2 + 0], x2); pm[nt * 2 + 1] = fmaxf(pm[nt * 2 + 1], x3); }
            }
        }

        if (hasNext) {
            #pragma unroll
            for (int q = 0; q < 2; q++) {
                int idx = tid + q * NTHR;
                int pt = idx >> 2, f = idx & 3;
                reinterpret_cast<float4*>(s_n)[pt * 4 + f] = pv[q];
            }
        }
        __syncthreads();
        buf ^= 1;
        tI = tNext;
    }

    #pragma unroll
    for (int nt = 0; nt < 8; nt++) {
        atomicMax(&s_pool[nt * 8 + 2 * t + 0], __float_as_int(pm[nt * 2 + 0]));
        atomicMax(&s_pool[nt * 8 + 2 * t + 1], __float_as_int(pm[nt * 2 + 1]));
    }
    __syncthreads();
    if (tid < C) atomicMax(&g_maxpool[tid], s_pool[tid]);
}

// ================= branch1: GEMM1 + segmented sum/max over sorted points =================
#define B1_SMEM_FLOATS 11584

__global__ void __launch_bounds__(NTHR, 3)
branch1_kernel(const float* __restrict__ inputs, float* __restrict__ out, int N)
{
    extern __shared__ float sm[];
    float* s_inT = sm;                 // [16][128]
    float* s_x   = sm + 2048;          // [128][64]
    float* s_w1  = sm + 10240;         // [16][64]
    float* s_b1  = sm + 11264;
    int*   s_seg = (int*)(sm + 11328);
    int*   s_idx = (int*)(sm + 11456);

    int tid  = threadIdx.x;
    int base = blockIdx.x * TILE;
    int np   = N - base; if (np > TILE) np = TILE;

    for (int i = tid; i < CIN * C; i += NTHR) s_w1[i] = g_W1f[i];
    if (tid < C) s_b1[tid] = g_b1f[tid];
    if (tid < TILE) {
        int seg = -1, idx = 0;
        if (tid < np) { idx = g_order[base + tid]; seg = g_seg_sorted[base + tid]; }
        s_idx[tid] = idx;
        s_seg[tid] = seg;
    }
    __syncthreads();

    #pragma unroll
    for (int q = 0; q < 2; q++) {
        int e  = tid + q * NTHR;
        int pt = e >> 2, f = e & 3;
        float4 v = make_float4(0.f, 0.f, 0.f, 0.f);
        if (pt < np) v = reinterpret_cast<const float4*>(inputs)[(size_t)s_idx[pt] * 4 + f];
        s_inT[(f * 4 + 0) * TILE + pt] = v.x;
        s_inT[(f * 4 + 1) * TILE + pt] = v.y;
        s_inT[(f * 4 + 2) * TILE + pt] = v.z;
        s_inT[(f * 4 + 3) * TILE + pt] = v.w;
    }
    __syncthreads();

    int tg = tid & 7;
    int tp = tid >> 3;

    {
        ull acc[2][8];
        #pragma unroll
        for (int i = 0; i < 2; i++)
            #pragma unroll
            for (int j = 0; j < 8; j++) acc[i][j] = 0ull;
        #pragma unroll
        for (int k = 0; k < CIN; k++) {
            ulonglong2 A = *reinterpret_cast<const ulonglong2*>(&s_inT[k * TILE + tp * 4]);
            float4 b0 = *reinterpret_cast<float4*>(&s_w1[k * C + tg * 4]);
            float4 b1 = *reinterpret_cast<float4*>(&s_w1[k * C + 32 + tg * 4]);
            ull bb[8];
            PACK2(bb[0], b0.x); PACK2(bb[1], b0.y); PACK2(bb[2], b0.z); PACK2(bb[3], b0.w);
            PACK2(bb[4], b1.x); PACK2(bb[5], b1.y); PACK2(bb[6], b1.z); PACK2(bb[7], b1.w);
            #pragma unroll
            for (int j = 0; j < 8; j++) { FFMA2(acc[0][j], A.x, bb[j]); FFMA2(acc[1][j], A.y, bb[j]); }
        }
        #pragma unroll
        for (int j = 0; j < 8; j++) {
            int cj = (j >> 2) * 32 + tg * 4 + (j & 3);
            float bias = s_b1[cj];
            float l0, h0, l1, h1;
            UNPACK2(l0, h0, acc[0][j]);
            UNPACK2(l1, h1, acc[1][j]);
            s_x[(tp * 4 + 0) * C + cj] = fmaxf(l0 + bias, 0.f);
            s_x[(tp * 4 + 1) * C + cj] = fmaxf(h0 + bias, 0.f);
            s_x[(tp * 4 + 2) * C + cj] = fmaxf(l1 + bias, 0.f);
            s_x[(tp * 4 + 3) * C + cj] = fmaxf(h1 + bias, 0.f);
        }
    }
    __syncthreads();

    {
        int c = tid & 63;
        int q = tid >> 6;
        int p0 = q * 32;
        int p1 = p0 + 32; if (p1 > np) p1 = np;
        if (p0 < np) {
            int   cs = s_seg[p0];
            float rs = 0.f, rm = 0.f;
            for (int p = p0; p < p1; p++) {
                int   sg = s_seg[p];
                float v  = s_x[p * C + c];
                if (sg != cs) {
                    atomicAdd(&out[cs * 192 + c * 3], rs);
                    atomicMax((int*)&out[cs * 192 + c * 3 + 1], __float_as_int(rm));
                    rs = 0.f; rm = 0.f; cs = sg;
                }
                rs += v; rm = fmaxf(rm, v);
            }
            atomicAdd(&out[cs * 192 + c * 3], rs);
            atomicMax((int*)&out[cs * 192 + c * 3 + 1], __float_as_int(rm));
        }
    }
}

// ---------------- broadcast global max pool into shuffled output layout ----------------
__global__ void bcast_kernel(float* __restrict__ out)
{
    int i = blockIdx.x * blockDim.x + threadIdx.x;
    if (i < S_SEG * C) {
        int s = i / C, c = i % C;
        out[s * 192 + c * 3 + 2] = __int_as_float(g_maxpool[c]);
    }
}

// ---------------- launch: two-chain fork/join (graph-capture-legal) ----------------
extern "C" void kernel_launch(void* const* d_in, const int* in_sizes, int n_in,
                              void* d_out, int out_size)
{
    const float* inputs = (const float*)d_in[0];
    const int*   unq    = (const int*)  d_in[1];
    const float* W1  = (const float*)d_in[3];
    const float* g1  = (const float*)d_in[4];
    const float* b1  = (const float*)d_in[5];
    const float* m1  = (const float*)d_in[6];
    const float* v1  = (const float*)d_in[7];
    const float* W2a = (const float*)d_in[8];
    const float* g2a = (const float*)d_in[9];
    const float* b2a = (const float*)d_in[10];
    const float* m2a = (const float*)d_in[11];
    const float* v2a = (const float*)d_in[12];
    const float* W2b = (const float*)d_in[13];
    const float* g2b = (const float*)d_in[14];
    const float* b2b = (const float*)d_in[15];
    const float* m2b = (const float*)d_in[16];
    const float* v2b = (const float*)d_in[17];
    float* out = (float*)d_out;

    int N = in_sizes[0] / CIN;
    int ntiles = (N + TILE - 1) / TILE;

    // one-time resources (created on the uncaptured correctness call, reused in capture)
    static cudaStream_t s2 = nullptr;
    static cudaEvent_t evFork = nullptr, evJoin = nullptr;
    static bool attrSet = false;
    if (!s2) {
        cudaStreamCreateWithFlags(&s2, cudaStreamNonBlocking);
        cudaEventCreateWithFlags(&evFork, cudaEventDisableTiming);
        cudaEventCreateWithFlags(&evJoin, cudaEventDisableTiming);
    }
    if (!attrSet) {
        cudaFuncSetAttribute(branch2_kernel,
                             cudaFuncAttributeMaxDynamicSharedMemorySize, B2_SMEM_FLOATS * 4);
        attrSet = true;
    }

    // chain head (default stream): zero + BN-fold
    combo_kernel<<<(out_size + 255) / 256, 256>>>(out, out_size,
                             W1, g1, b1, m1, v1,
                             W2a, g2a, b2a, m2a, v2a,
                             W2b, g2b, b2b, m2b, v2b);

    // fork: chain B (sort + branch1) onto s2
    cudaEventRecord(evFork, 0);
    cudaStreamWaitEvent(s2, evFork, 0);

    hist_kernel<<<(N + 255) / 256, 256, 0, s2>>>(unq, N);
    scan_kernel<<<1, 1024, 0, s2>>>();
    scatter_kernel<<<(N + 255) / 256, 256, 0, s2>>>(unq, N);
    branch1_kernel<<<ntiles, NTHR, B1_SMEM_FLOATS * 4, s2>>>(inputs, out, N);
    cudaEventRecord(evJoin, s2);

    // chain A (default stream): tensor-core branch2 + maxpool broadcast
    prep2_kernel<<<40, 256>>>();
    branch2_kernel<<<148, NTHR, B2_SMEM_FLOATS * 4>>>(inputs, N, ntiles);
    bcast_kernel<<<(S_SEG * C + 255) / 256, 256>>>(out);

    // join
    cudaStreamWaitEvent(0, evJoin, 0);
}

// round 11
// speedup vs baseline: 4.3026x; 1.1651x over previous
#include <cuda_runtime.h>
#include <cuda_bf16.h>
#include <cstdint>

// Problem constants (fixed by setup_inputs: N=1e6, Cin=16, C=64, S=20000)
#define NMAX   1000000
#define S_SEG  20000
#define CIN    16
#define C      64
#define C2     128
#define TILE   128
#define NTHR   256
#define EPS_BN 1e-3f

typedef unsigned long long ull;

// packed f32x2 helpers (branch1)
#define FFMA2(d, a, b) asm("fma.rn.f32x2 %0, %1, %2, %0;" : "+l"(d) : "l"(a), "l"(b))
#define PACK2(d, x)    asm("mov.b64 %0, {%1, %1};" : "=l"(d) : "f"(x))
#define UNPACK2(lo, hi, d) asm("mov.b64 {%0, %1}, %2;" : "=f"(lo), "=f"(hi) : "l"(d))

// bf16x2 pack: low half <- x (smaller col), high half <- y
__device__ __forceinline__ uint32_t pack_bf16x2(float x, float y) {
    uint32_t r;
    asm("cvt.rn.bf16x2.f32 %0, %1, %2;" : "=r"(r) : "f"(y), "f"(x));
    return r;
}
// split (x,y) into hi bf16x2 and lo bf16x2 (residual)
__device__ __forceinline__ void split_bf16x2(float x, float y, uint32_t& hi, uint32_t& lo) {
    hi = pack_bf16x2(x, y);
    float hx = __uint_as_float(hi << 16);
    float hy = __uint_as_float(hi & 0xffff0000u);
    lo = pack_bf16x2(x - hx, y - hy);
}

// m16n8k16 bf16 MMA, fp32 accumulate (baseline PTX, compiles for compute_100)
#define MMA_BF16(d, a, b0, b1) \
    asm volatile("mma.sync.aligned.m16n8k16.row.col.f32.bf16.bf16.f32 " \
        "{%0,%1,%2,%3}, {%4,%5,%6,%7}, {%8,%9}, {%0,%1,%2,%3};" \
        : "+f"((d)[0]), "+f"((d)[1]), "+f"((d)[2]), "+f"((d)[3]) \
        : "r"((a)[0]), "r"((a)[1]), "r"((a)[2]), "r"((a)[3]), "r"(b0), "r"(b1))

// ---------------- device scratch ----------------
__device__ int   g_hist[S_SEG];          // zero at load; scan re-zeroes after reading
__device__ int   g_cursor[S_SEG];
__device__ int   g_order[NMAX];
__device__ int   g_seg_sorted[NMAX];
__device__ int   g_maxpool[C];
__device__ float g_W1f[CIN * C],  g_b1f[C];
__device__ float g_W2af[CIN * C2], g_b2af[C2];
__device__ float g_W2bf[C2 * C],  g_b2bf[C];
// packed per-lane MMA B-fragments as uint4: {hi_b0, hi_b1, lo_b0, lo_b1}
__device__ uint32_t g_fragA[16 * 32 * 4];          // W2a: [(nt*32+lane)*4 + v*2 + r]
__device__ uint32_t g_fragB[8 * 8 * 32 * 4];       // W2b: [((kb*8+nt)*32+lane)*4 + v*2 + r]

// ---------------- combo: zero output + maxpool + fold BN into weights ----------------
__global__ void combo_kernel(float* __restrict__ out, int n_out,
                             const float* __restrict__ W1,
                             const float* __restrict__ g1, const float* __restrict__ b1,
                             const float* __restrict__ m1, const float* __restrict__ v1,
                             const float* __restrict__ W2a,
                             const float* __restrict__ g2a, const float* __restrict__ b2a,
                             const float* __restrict__ m2a, const float* __restrict__ v2a,
                             const float* __restrict__ W2b,
                             const float* __restrict__ g2b, const float* __restrict__ b2b,
                             const float* __restrict__ m2b, const float* __restrict__ v2b)
{
    int i = blockIdx.x * blockDim.x + threadIdx.x;
    if (i < n_out) out[i] = 0.0f;
    if (i < C)     g_maxpool[i] = 0;

    const int n1 = CIN * C;          // 1024
    const int n2 = n1 + CIN * C2;    // 3072
    const int n3 = n2 + C2 * C;      // 11264
    if (i < n1) {
        int c = i & (C - 1);
        g_W1f[i] = W1[i] * (g1[c] / sqrtf(v1[c] + EPS_BN));
    } else if (i < n2) {
        int j = i - n1; int c = j & (C2 - 1);
        g_W2af[j] = W2a[j] * (g2a[c] / sqrtf(v2a[c] + EPS_BN));
    } else if (i < n3) {
        int j = i - n2; int c = j & (C - 1);
        g_W2bf[j] = W2b[j] * (g2b[c] / sqrtf(v2b[c] + EPS_BN));
    } else if (i < n3 + C + C2 + C) {
        int j = i - n3;
        if (j < C) {
            g_b1f[j] = b1[j] - m1[j] * (g1[j] / sqrtf(v1[j] + EPS_BN));
        } else if (j < C + C2) {
            int c = j - C;
            g_b2af[c] = b2a[c] - m2a[c] * (g2a[c] / sqrtf(v2a[c] + EPS_BN));
        } else {
            int c = j - C - C2;
            g_b2bf[c] = b2b[c] - m2b[c] * (g2b[c] / sqrtf(v2b[c] + EPS_BN));
        }
    }
}

// ---------------- prep2: build per-lane hi/lo weight fragments (uint4 packed) ----------------
__global__ void prep2_kernel()
{
    int i = blockIdx.x * blockDim.x + threadIdx.x;
    if (i < 2048) {
        int nt = i >> 7, lane = (i >> 2) & 31, v = (i >> 1) & 1, r = i & 1;
        int g = lane >> 2, t = lane & 3;
        int n = nt * 8 + g;
        int k0 = 2 * t + (r ? 8 : 0);
        float w0 = g_W2af[k0 * C2 + n];
        float w1 = g_W2af[(k0 + 1) * C2 + n];
        uint32_t hi, lo;
        split_bf16x2(w0, w1, hi, lo);
        g_fragA[i] = v ? lo : hi;
    } else if (i < 2048 + 8192) {
        int j = i - 2048;
        int kb = j >> 10, nt = (j >> 7) & 7, lane = (j >> 2) & 31, v = (j >> 1) & 1, r = j & 1;
        int g = lane >> 2, t = lane & 3;
        int n = nt * 8 + g;
        int k = kb * 16 + 2 * t + (r ? 8 : 0);
        float w0 = g_W2bf[k * C + n];
        float w1 = g_W2bf[(k + 1) * C + n];
        uint32_t hi, lo;
        split_bf16x2(w0, w1, hi, lo);
        g_fragB[j] = v ? lo : hi;
    }
}

// ---------------- counting sort (no external zeroing needed) ----------------
__global__ void hist_kernel(const int* __restrict__ unq, int N)
{
    int i = blockIdx.x * blockDim.x + threadIdx.x;
    if (i < N) atomicAdd(&g_hist[unq[i]], 1);
}

// single-pass parallel scan; also RE-ZEROES g_hist for the next graph replay
__global__ void scan_kernel()
{
    __shared__ int wsum[32];
    int tid = threadIdx.x;
    int t0 = tid * 20;
    int v[20];
    int s = 0;
    #pragma unroll
    for (int j = 0; j < 20; j++) {
        int idx = t0 + j;
        int x = (idx < S_SEG) ? g_hist[idx] : 0;
        v[j] = x; s += x;
        if (idx < S_SEG) g_hist[idx] = 0;   // self-clean for next replay
    }
    int x = s;
    #pragma unroll
    for (int d = 1; d < 32; d <<= 1) {
        int y = __shfl_up_sync(0xffffffffu, x, d);
        if ((tid & 31) >= d) x += y;
    }
    if ((tid & 31) == 31) wsum[tid >> 5] = x;
    __syncthreads();
    if (tid < 32) {
        int t = wsum[tid];
        #pragma unroll
        for (int d = 1; d < 32; d <<= 1) {
            int y = __shfl_up_sync(0xffffffffu, t, d);
            if (tid >= d) t += y;
        }
        wsum[tid] = t;
    }
    __syncthreads();
    int incl = x + ((tid >= 32) ? wsum[(tid >> 5) - 1] : 0);
    int run = incl - s;
    #pragma unroll
    for (int j = 0; j < 20; j++) {
        int idx = t0 + j;
        if (idx < S_SEG) { g_cursor[idx] = run; run += v[j]; }
    }
}

__global__ void scatter_kernel(const int* __restrict__ unq, int N)
{
    int i = blockIdx.x * blockDim.x + threadIdx.x;
    if (i < N) {
        int s = unq[i];
        int pos = atomicAdd(&g_cursor[s], 1);
        g_order[pos] = i;
        g_seg_sorted[pos] = s;
    }
}

// ================= branch2 (mma.sync bf16 split-precision, pipelined) =================
#define B2_SMEM_FLOATS 14592

__global__ void __launch_bounds__(NTHR, 1)
branch2_kernel(const float* __restrict__ inputs, int N, int ntiles)
{
    extern __shared__ float sm[];
    float*    s_a0  = sm;
    float*    s_a1  = sm + 2048;
    uint32_t* s_fa  = (uint32_t*)(sm + 4096);
    uint32_t* s_fb  = (uint32_t*)(sm + 6144);
    float*    s_b2a = sm + 14336;
    float*    s_b2b = sm + 14464;
    int*      s_pool= (int*)(sm + 14528);

    int tid = threadIdx.x;
    int w   = tid >> 5;
    int lane= tid & 31;
    int t   = lane & 3;

    for (int i = tid; i < 2048; i += NTHR) s_fa[i] = g_fragA[i];
    for (int i = tid; i < 8192; i += NTHR) s_fb[i] = g_fragB[i];
    if (tid < C2) s_b2a[tid] = g_b2af[tid];
    if (tid < C)  s_b2b[tid] = g_b2bf[tid];
    if (tid < C)  s_pool[tid] = 0;

    const int r0 = w * 16 + (lane >> 2);
    const int r1 = r0 + 8;

    float pm[16];
    #pragma unroll
    for (int j = 0; j < 16; j++) pm[j] = 0.f;

    int tI = blockIdx.x;
    if (tI < ntiles) {
        int base = tI * TILE;
        int np = N - base; if (np > TILE) np = TILE;
        #pragma unroll
        for (int q = 0; q < 2; q++) {
            int idx = tid + q * NTHR;
            int pt = idx >> 2, f = idx & 3;
            float4 v = make_float4(0.f, 0.f, 0.f, 0.f);
            if (pt < np) v = reinterpret_cast<const float4*>(inputs)[(size_t)(base + pt) * 4 + f];
            reinterpret_cast<float4*>(s_a0)[pt * 4 + f] = v;
        }
    }
    __syncthreads();

    int buf = 0;
    for (; tI < ntiles; ) {
        int base = tI * TILE;
        int np = N - base; if (np > TILE) np = TILE;
        float* s_a = buf ? s_a1 : s_a0;
        float* s_n = buf ? s_a0 : s_a1;

        int tNext = tI + gridDim.x;
        bool hasNext = tNext < ntiles;
        float4 pv[2];
        int npN = 0;
        if (hasNext) {
            int baseN = tNext * TILE;
            npN = N - baseN; if (npN > TILE) npN = TILE;
            #pragma unroll
            for (int q = 0; q < 2; q++) {
                int idx = tid + q * NTHR;
                int pt = idx >> 2, f = idx & 3;
                pv[q] = make_float4(0.f, 0.f, 0.f, 0.f);
                if (pt < npN) pv[q] = reinterpret_cast<const float4*>(inputs)[(size_t)(baseN + pt) * 4 + f];
            }
        }

        uint32_t a1h[4], a1l[4];
        {
            float2 p0 = *reinterpret_cast<float2*>(&s_a[r0 * 16 + 2 * t]);
            float2 p1 = *reinterpret_cast<float2*>(&s_a[r1 * 16 + 2 * t]);
            float2 p2 = *reinterpret_cast<float2*>(&s_a[r0 * 16 + 2 * t + 8]);
            float2 p3 = *reinterpret_cast<float2*>(&s_a[r1 * 16 + 2 * t + 8]);
            split_bf16x2(p0.x, p0.y, a1h[0], a1l[0]);
            split_bf16x2(p1.x, p1.y, a1h[1], a1l[1]);
            split_bf16x2(p2.x, p2.y, a1h[2], a1l[2]);
            split_bf16x2(p3.x, p3.y, a1h[3], a1l[3]);
        }

        float d2[32];
        #pragma unroll
        for (int j = 0; j < 32; j++) d2[j] = 0.f;

        #pragma unroll
        for (int phx = 0; phx < 2; phx++) {
            float d1[32];
            #pragma unroll
            for (int j = 0; j < 32; j++) d1[j] = 0.f;
            #pragma unroll
            for (int h4 = 0; h4 < 2; h4++) {
                uint4 f[4];
                #pragma unroll
                for (int q = 0; q < 4; q++)
                    f[q] = *reinterpret_cast<uint4*>(&s_fa[((phx * 8 + h4 * 4 + q) * 32 + lane) * 4]);
                #pragma unroll
                for (int q = 0; q < 4; q++) MMA_BF16(&d1[(h4 * 4 + q) * 4], a1h, f[q].x, f[q].y);
                #pragma unroll
                for (int q = 0; q < 4; q++) MMA_BF16(&d1[(h4 * 4 + q) * 4], a1h, f[q].z, f[q].w);
                #pragma unroll
                for (int q = 0; q < 4; q++) MMA_BF16(&d1[(h4 * 4 + q) * 4], a1l, f[q].x, f[q].y);
            }
            uint32_t a2h[16], a2l[16];
            #pragma unroll
            for (int nt8 = 0; nt8 < 8; nt8++) {
                int nt = phx * 8 + nt8;
                float2 bi = *reinterpret_cast<float2*>(&s_b2a[nt * 8 + 2 * t]);
                float h0 = fmaxf(d1[nt8 * 4 + 0] + bi.x, 0.f);
                float h1 = fmaxf(d1[nt8 * 4 + 1] + bi.y, 0.f);
                float h2 = fmaxf(d1[nt8 * 4 + 2] + bi.x, 0.f);
                float h3 = fmaxf(d1[nt8 * 4 + 3] + bi.y, 0.f);
                int kbl = nt8 >> 1, half = nt8 & 1;
                int s0 = kbl * 4 + half * 2;
                split_bf16x2(h0, h1, a2h[s0],     a2l[s0]);
                split_bf16x2(h2, h3, a2h[s0 + 1], a2l[s0 + 1]);
            }
            #pragma unroll
            for (int kbl = 0; kbl < 4; kbl++) {
                int kb = phx * 4 + kbl;
                #pragma unroll
                for (int h4 = 0; h4 < 2; h4++) {
                    uint4 f[4];
                    #pragma unroll
                    for (int q = 0; q < 4; q++)
                        f[q] = *reinterpret_cast<uint4*>(&s_fb[((kb * 8 + h4 * 4 + q) * 32 + lane) * 4]);
                    #pragma unroll
                    for (int q = 0; q < 4; q++) MMA_BF16(&d2[(h4 * 4 + q) * 4], &a2h[kbl * 4], f[q].x, f[q].y);
                    #pragma unroll
                    for (int q = 0; q < 4; q++) MMA_BF16(&d2[(h4 * 4 + q) * 4], &a2h[kbl * 4], f[q].z, f[q].w);
                    #pragma unroll
                    for (int q = 0; q < 4; q++) MMA_BF16(&d2[(h4 * 4 + q) * 4], &a2l[kbl * 4], f[q].x, f[q].y);
                }
            }
        }

        {
            bool v0 = r0 < np;
            bool v1 = r1 < np;
            #pragma unroll
            for (int nt = 0; nt < 8; nt++) {
                float2 bi = *reinterpret_cast<float2*>(&s_b2b[nt * 8 + 2 * t]);
                float x0 = fmaxf(d2[nt * 4 + 0] + bi.x, 0.f);
                float x1 = fmaxf(d2[nt * 4 + 1] + bi.y, 0.f);
                float x2 = fmaxf(d2[nt * 4 + 2] + bi.x, 0.f);
                float x3 = fmaxf(d2[nt * 4 + 3] + bi.y, 0.f);
                if (v0) { pm[nt * 2 + 0] = fmaxf(pm[nt * 2 + 0], x0); pm[nt * 2 + 1] = fmaxf(pm[nt * 2 + 1], x1); }
                if (v1) { pm[nt * 2 + 0] = fmaxf(pm[nt * 2 + 0], x2); pm[nt * 2 + 1] = fmaxf(pm[nt * 2 + 1], x3); }
            }
        }

        if (hasNext) {
            #pragma unroll
            for (int q = 0; q < 2; q++) {
                int idx = tid + q * NTHR;
                int pt = idx >> 2, f = idx & 3;
                reinterpret_cast<float4*>(s_n)[pt * 4 + f] = pv[q];
            }
        }
        __syncthreads();
        buf ^= 1;
        tI = tNext;
    }

    #pragma unroll
    for (int nt = 0; nt < 8; nt++) {
        atomicMax(&s_pool[nt * 8 + 2 * t + 0], __float_as_int(pm[nt * 2 + 0]));
        atomicMax(&s_pool[nt * 8 + 2 * t + 1], __float_as_int(pm[nt * 2 + 1]));
    }
    __syncthreads();
    if (tid < C) atomicMax(&g_maxpool[tid], s_pool[tid]);
}

// ================= branch1: GEMM1 + segmented sum/max over sorted points =================
#define B1_SMEM_FLOATS 11584

__global__ void __launch_bounds__(NTHR, 3)
branch1_kernel(const float* __restrict__ inputs, float* __restrict__ out, int N)
{
    extern __shared__ float sm[];
    float* s_inT = sm;                 // [16][128]
    float* s_x   = sm + 2048;          // [128][64]
    float* s_w1  = sm + 10240;         // [16][64]
    float* s_b1  = sm + 11264;
    int*   s_seg = (int*)(sm + 11328);
    int*   s_idx = (int*)(sm + 11456);

    int tid  = threadIdx.x;
    int base = blockIdx.x * TILE;
    int np   = N - base; if (np > TILE) np = TILE;

    for (int i = tid; i < CIN * C; i += NTHR) s_w1[i] = g_W1f[i];
    if (tid < C) s_b1[tid] = g_b1f[tid];
    if (tid < TILE) {
        int seg = -1, idx = 0;
        if (tid < np) { idx = g_order[base + tid]; seg = g_seg_sorted[base + tid]; }
        s_idx[tid] = idx;
        s_seg[tid] = seg;
    }
    __syncthreads();

    #pragma unroll
    for (int q = 0; q < 2; q++) {
        int e  = tid + q * NTHR;
        int pt = e >> 2, f = e & 3;
        float4 v = make_float4(0.f, 0.f, 0.f, 0.f);
        if (pt < np) v = reinterpret_cast<const float4*>(inputs)[(size_t)s_idx[pt] * 4 + f];
        s_inT[(f * 4 + 0) * TILE + pt] = v.x;
        s_inT[(f * 4 + 1) * TILE + pt] = v.y;
        s_inT[(f * 4 + 2) * TILE + pt] = v.z;
        s_inT[(f * 4 + 3) * TILE + pt] = v.w;
    }
    __syncthreads();

    int tg = tid & 7;
    int tp = tid >> 3;

    {
        ull acc[2][8];
        #pragma unroll
        for (int i = 0; i < 2; i++)
            #pragma unroll
            for (int j = 0; j < 8; j++) acc[i][j] = 0ull;
        #pragma unroll
        for (int k = 0; k < CIN; k++) {
            ulonglong2 A = *reinterpret_cast<const ulonglong2*>(&s_inT[k * TILE + tp * 4]);
            float4 b0 = *reinterpret_cast<float4*>(&s_w1[k * C + tg * 4]);
            float4 b1 = *reinterpret_cast<float4*>(&s_w1[k * C + 32 + tg * 4]);
            ull bb[8];
            PACK2(bb[0], b0.x); PACK2(bb[1], b0.y); PACK2(bb[2], b0.z); PACK2(bb[3], b0.w);
            PACK2(bb[4], b1.x); PACK2(bb[5], b1.y); PACK2(bb[6], b1.z); PACK2(bb[7], b1.w);
            #pragma unroll
            for (int j = 0; j < 8; j++) { FFMA2(acc[0][j], A.x, bb[j]); FFMA2(acc[1][j], A.y, bb[j]); }
        }
        #pragma unroll
        for (int j = 0; j < 8; j++) {
            int cj = (j >> 2) * 32 + tg * 4 + (j & 3);
            float bias = s_b1[cj];
            float l0, h0, l1, h1;
            UNPACK2(l0, h0, acc[0][j]);
            UNPACK2(l1, h1, acc[1][j]);
            s_x[(tp * 4 + 0) * C + cj] = fmaxf(l0 + bias, 0.f);
            s_x[(tp * 4 + 1) * C + cj] = fmaxf(h0 + bias, 0.f);
            s_x[(tp * 4 + 2) * C + cj] = fmaxf(l1 + bias, 0.f);
            s_x[(tp * 4 + 3) * C + cj] = fmaxf(h1 + bias, 0.f);
        }
    }
    __syncthreads();

    {
        int c = tid & 63;
        int q = tid >> 6;
        int p0 = q * 32;
        int p1 = p0 + 32; if (p1 > np) p1 = np;
        if (p0 < np) {
            int   cs = s_seg[p0];
            float rs = 0.f, rm = 0.f;
            for (int p = p0; p < p1; p++) {
                int   sg = s_seg[p];
                float v  = s_x[p * C + c];
                if (sg != cs) {
                    atomicAdd(&out[cs * 192 + c * 3], rs);
                    atomicMax((int*)&out[cs * 192 + c * 3 + 1], __float_as_int(rm));
                    rs = 0.f; rm = 0.f; cs = sg;
                }
                rs += v; rm = fmaxf(rm, v);
            }
            atomicAdd(&out[cs * 192 + c * 3], rs);
            atomicMax((int*)&out[cs * 192 + c * 3 + 1], __float_as_int(rm));
        }
    }
}

// ---------------- broadcast global max pool into shuffled output layout ----------------
__global__ void bcast_kernel(float* __restrict__ out)
{
    int i = blockIdx.x * blockDim.x + threadIdx.x;
    if (i < S_SEG * C) {
        int s = i / C, c = i % C;
        out[s * 192 + c * 3 + 2] = __int_as_float(g_maxpool[c]);
    }
}

// ---------------- launch: dependency-minimal fork/join ----------------
extern "C" void kernel_launch(void* const* d_in, const int* in_sizes, int n_in,
                              void* d_out, int out_size)
{
    const float* inputs = (const float*)d_in[0];
    const int*   unq    = (const int*)  d_in[1];
    const float* W1  = (const float*)d_in[3];
    const float* g1  = (const float*)d_in[4];
    const float* b1  = (const float*)d_in[5];
    const float* m1  = (const float*)d_in[6];
    const float* v1  = (const float*)d_in[7];
    const float* W2a = (const float*)d_in[8];
    const float* g2a = (const float*)d_in[9];
    const float* b2a = (const float*)d_in[10];
    const float* m2a = (const float*)d_in[11];
    const float* v2a = (const float*)d_in[12];
    const float* W2b = (const float*)d_in[13];
    const float* g2b = (const float*)d_in[14];
    const float* b2b = (const float*)d_in[15];
    const float* m2b = (const float*)d_in[16];
    const float* v2b = (const float*)d_in[17];
    float* out = (float*)d_out;

    int N = in_sizes[0] / CIN;
    int ntiles = (N + TILE - 1) / TILE;

    static cudaStream_t s2 = nullptr;
    static cudaEvent_t evCombo = nullptr, evJoin = nullptr;
    static bool attrSet = false;
    if (!s2) {
        cudaStreamCreateWithFlags(&s2, cudaStreamNonBlocking);
        cudaEventCreateWithFlags(&evCombo, cudaEventDisableTiming);
        cudaEventCreateWithFlags(&evJoin, cudaEventDisableTiming);
    }
    if (!attrSet) {
        cudaFuncSetAttribute(branch2_kernel,
                             cudaFuncAttributeMaxDynamicSharedMemorySize, B2_SMEM_FLOATS * 4);
        attrSet = true;
    }

    // ---- chain A (stream 0), recorded FIRST so branch2 grabs SMs early ----
    combo_kernel<<<(out_size + 255) / 256, 256>>>(out, out_size,
                             W1, g1, b1, m1, v1,
                             W2a, g2a, b2a, m2a, v2a,
                             W2b, g2b, b2b, m2b, v2b);
    cudaEventRecord(evCombo, 0);
    prep2_kernel<<<40, 256>>>();
    branch2_kernel<<<148, NTHR, B2_SMEM_FLOATS * 4>>>(inputs, N, ntiles);
    bcast_kernel<<<(S_SEG * C + 255) / 256, 256>>>(out);

    // ---- chain B (s2): hist/scan/scatter have NO dependencies (self-cleaning hist);
    //      only branch1 waits for combo (zeroed out + folded W1) ----
    hist_kernel<<<(N + 255) / 256, 256, 0, s2>>>(unq, N);
    scan_kernel<<<1, 1024, 0, s2>>>();
    scatter_kernel<<<(N + 255) / 256, 256, 0, s2>>>(unq, N);
    cudaStreamWaitEvent(s2, evCombo, 0);
    branch1_kernel<<<ntiles, NTHR, B1_SMEM_FLOATS * 4, s2>>>(inputs, out, N);
    cudaEventRecord(evJoin, s2);

    // ---- join ----
    cudaStreamWaitEvent(0, evJoin, 0);
}